// round 1
// baseline (speedup 1.0000x reference)
#include <cuda_runtime.h>
#include <cuda_bf16.h>

#define BATCH 8
#define CCH   128
#define NTOK  16384
#define HEADS 8
#define HD    16
#define LN_EPS 1e-5f

// ---------------- device scratch (no allocations allowed) ----------------
__device__ float          g_kv[BATCH * HEADS * HD * HD];      // accumulated k^T v (pre /N)
__device__ __nv_bfloat16  g_wkv[256 * 128];                   // reordered K/V proj rows
__device__ __nv_bfloat16  g_o1hi[128 * 128], g_o1lo[128 * 128];
__device__ __nv_bfloat16  g_o2hi[128 * 128], g_o2lo[128 * 128];
__device__ __nv_bfloat16  g_meff[BATCH * 128 * 128];          // per-batch effective q->av matrix
__device__ float          g_meffb[BATCH * 128];

// ---------------- helpers ----------------
__device__ __forceinline__ unsigned pk2f(float a, float b) {
    __nv_bfloat16 ha = __float2bfloat16_rn(a);
    __nv_bfloat16 hb = __float2bfloat16_rn(b);
    unsigned short ua = *reinterpret_cast<unsigned short*>(&ha);
    unsigned short ub = *reinterpret_cast<unsigned short*>(&hb);
    return (unsigned)ua | ((unsigned)ub << 16);
}

__device__ __forceinline__ void split2(float2 f, unsigned& hi, unsigned& lo) {
    __nv_bfloat16 h0 = __float2bfloat16_rn(f.x);
    __nv_bfloat16 h1 = __float2bfloat16_rn(f.y);
    unsigned short u0 = *reinterpret_cast<unsigned short*>(&h0);
    unsigned short u1 = *reinterpret_cast<unsigned short*>(&h1);
    hi = (unsigned)u0 | ((unsigned)u1 << 16);
    float r0 = f.x - __bfloat162float(h0);
    float r1 = f.y - __bfloat162float(h1);
    lo = pk2f(r0, r1);
}

__device__ __forceinline__ void mma16816(float* c, const unsigned* a, const unsigned* b) {
    asm volatile(
        "mma.sync.aligned.m16n8k16.row.col.f32.bf16.bf16.f32 "
        "{%0,%1,%2,%3}, {%4,%5,%6,%7}, {%8,%9}, {%0,%1,%2,%3};\n"
        : "+f"(c[0]), "+f"(c[1]), "+f"(c[2]), "+f"(c[3])
        : "r"(a[0]), "r"(a[1]), "r"(a[2]), "r"(a[3]), "r"(b[0]), "r"(b[1]));
}

// Generic 128-K GEMM tile: warp computes [rbase..rbase+32) x [cbase..cbase+64).
// A: fp32 smem [.][lda] (rows = tokens, cols = k). W: bf16 smem [.][ldw] (rows = c_out, cols = k).
template <bool SPLIT>
__device__ __forceinline__ void gemm128(const float* A, int lda,
                                        const __nv_bfloat16* Whi, const __nv_bfloat16* Wlo, int ldw,
                                        float acc[2][8][4], int rbase, int cbase, int lr, int lc) {
    for (int kc = 0; kc < 128; kc += 16) {
        unsigned ah[2][4], al[2][4];
#pragma unroll
        for (int mi = 0; mi < 2; mi++) {
            const float* p0 = &A[(rbase + mi * 16 + lr) * lda + kc + lc * 2];
            const float* p1 = p0 + 8 * lda;
            float2 f0 = *(const float2*)p0;
            float2 f1 = *(const float2*)p1;
            float2 f2 = *(const float2*)(p0 + 8);
            float2 f3 = *(const float2*)(p1 + 8);
            if (SPLIT) {
                split2(f0, ah[mi][0], al[mi][0]);
                split2(f1, ah[mi][1], al[mi][1]);
                split2(f2, ah[mi][2], al[mi][2]);
                split2(f3, ah[mi][3], al[mi][3]);
            } else {
                ah[mi][0] = pk2f(f0.x, f0.y);
                ah[mi][1] = pk2f(f1.x, f1.y);
                ah[mi][2] = pk2f(f2.x, f2.y);
                ah[mi][3] = pk2f(f3.x, f3.y);
            }
        }
#pragma unroll
        for (int ni = 0; ni < 8; ni++) {
            int cb = cbase + ni * 8 + lr;
            unsigned bh[2];
            bh[0] = *(const unsigned*)(Whi + cb * ldw + kc + lc * 2);
            bh[1] = *(const unsigned*)(Whi + cb * ldw + kc + 8 + lc * 2);
            mma16816(acc[0][ni], ah[0], bh);
            mma16816(acc[1][ni], ah[1], bh);
            if (SPLIT) {
                unsigned bl[2];
                bl[0] = *(const unsigned*)(Wlo + cb * ldw + kc + lc * 2);
                bl[1] = *(const unsigned*)(Wlo + cb * ldw + kc + 8 + lc * 2);
                mma16816(acc[0][ni], ah[0], bl);
                mma16816(acc[1][ni], ah[1], bl);
                mma16816(acc[0][ni], al[0], bh);
                mma16816(acc[1][ni], al[1], bh);
            }
        }
    }
}

// ---------------- kernel 0: weight prep (runs every launch; cheap) ----------------
__global__ void prep_kernel(const float* __restrict__ qkv_w,
                            const float* __restrict__ o1_w,
                            const float* __restrict__ o2_w) {
    int idx = blockIdx.x * blockDim.x + threadIdx.x;
    int nthr = gridDim.x * blockDim.x;
    for (int i = idx; i < BATCH * HEADS * HD * HD; i += nthr) g_kv[i] = 0.f;
    // reordered K/V weight rows: row r -> head h = r/32, j = r%32; j<16 => k_d, else v_e
    for (int i = idx; i < 256 * 128; i += nthr) {
        int r = i >> 7, c = i & 127;
        int h = r >> 5, j = r & 31;
        int src = (j < 16) ? (48 * h + 16 + j) : (48 * h + 32 + (j - 16));
        g_wkv[i] = __float2bfloat16_rn(qkv_w[src * 128 + c]);
    }
    for (int i = idx; i < 128 * 128; i += nthr) {
        float f1 = o1_w[i];
        __nv_bfloat16 h1 = __float2bfloat16_rn(f1);
        g_o1hi[i] = h1;
        g_o1lo[i] = __float2bfloat16_rn(f1 - __bfloat162float(h1));
        float f2 = o2_w[i];
        __nv_bfloat16 h2 = __float2bfloat16_rn(f2);
        g_o2hi[i] = h2;
        g_o2lo[i] = __float2bfloat16_rn(f2 - __bfloat162float(h2));
    }
}

// ---------------- kernel 1: k,v projection + LN + kv accumulation ----------------
// 64 tokens per block. smem: As[64][132] f32 | Wt[256][136] bf16 | KV[64][264] f32 | qb[256] f32
#define K2_AS   (64 * 132)
#define K2_WT_OFF (K2_AS * 4)
#define K2_KV_OFF (K2_WT_OFF + 256 * 136 * 2)
#define K2_QB_OFF (K2_KV_OFF + 64 * 264 * 4)
#define K2_SMEM   (K2_QB_OFF + 256 * 4)

__global__ void __launch_bounds__(256, 1) kv_kernel(const float* __restrict__ x,
                                                    const float* __restrict__ qkv_b,
                                                    const float* __restrict__ kln_w,
                                                    const float* __restrict__ kln_b,
                                                    const float* __restrict__ vln_w,
                                                    const float* __restrict__ vln_b) {
    extern __shared__ char smem[];
    float* As = (float*)smem;
    __nv_bfloat16* Wt = (__nv_bfloat16*)(smem + K2_WT_OFF);
    float* KV = (float*)(smem + K2_KV_OFF);
    float* qb = (float*)(smem + K2_QB_OFF);

    int tid = threadIdx.x;
    int b = blockIdx.y;
    int n0 = blockIdx.x * 64;
    const float* xb = x + (size_t)b * CCH * NTOK;

    // A tile (transpose load: global [c][n] -> smem [t][c])
    for (int i = tid; i < 64 * 128; i += 256) {
        int t = i & 63, c = i >> 6;
        As[t * 132 + c] = xb[(size_t)c * NTOK + n0 + t];
    }
    // weights
    {
        const unsigned* src = (const unsigned*)g_wkv;
        for (int i = tid; i < 256 * 64; i += 256) {
            int r = i >> 6, c32 = i & 63;
            ((unsigned*)(Wt + r * 136))[c32] = src[r * 64 + c32];
        }
    }
    // reordered qkv bias for k/v rows
    {
        int r = tid;
        int h = r >> 5, j = r & 31;
        int src = (j < 16) ? (48 * h + 16 + j) : (48 * h + 32 + (j - 16));
        qb[r] = qkv_b[src];
    }
    __syncthreads();

    int w = tid >> 5, l = tid & 31;
    int mw = w >> 2, nw = w & 3;   // 2 x 4 warp grid over 64 x 256
    int lr = l >> 2, lc = l & 3;

    float acc[2][8][4];
#pragma unroll
    for (int a = 0; a < 2; a++)
#pragma unroll
        for (int bb = 0; bb < 8; bb++)
#pragma unroll
            for (int cc = 0; cc < 4; cc++) acc[a][bb][cc] = 0.f;

    gemm128<false>(As, 132, Wt, nullptr, 136, acc, mw * 32, nw * 64, lr, lc);

    // epilogue: raw k/v (+bias) into KV
#pragma unroll
    for (int mi = 0; mi < 2; mi++) {
        int row = mw * 32 + mi * 16 + lr;
#pragma unroll
        for (int ni = 0; ni < 8; ni++) {
            int col = nw * 64 + ni * 8 + lc * 2;
            KV[row * 264 + col]       = acc[mi][ni][0] + qb[col];
            KV[row * 264 + col + 1]   = acc[mi][ni][1] + qb[col + 1];
            KV[(row + 8) * 264 + col]     = acc[mi][ni][2] + qb[col];
            KV[(row + 8) * 264 + col + 1] = acc[mi][ni][3] + qb[col + 1];
        }
    }
    __syncthreads();

    // LayerNorm over d=16 (ddof=1, eps on std), in place
    for (int task = tid; task < 1024; task += 256) {
        int t = task >> 4;
        int rem = task & 15;
        int h = rem >> 1;
        int isv = rem & 1;
        float* p = &KV[t * 264 + h * 32 + isv * 16];
        float s = 0.f, ss = 0.f;
#pragma unroll
        for (int d = 0; d < 16; d++) { float vv = p[d]; s += vv; ss += vv * vv; }
        float mean = s * (1.f / 16.f);
        float var = (ss - 16.f * mean * mean) * (1.f / 15.f);
        var = fmaxf(var, 0.f);
        float inv = 1.f / (sqrtf(var) + LN_EPS);
        const float* wp = (isv ? vln_w : kln_w) + h * 16;
        const float* bp = (isv ? vln_b : kln_b) + h * 16;
#pragma unroll
        for (int d = 0; d < 16; d++) p[d] = wp[d] * ((p[d] - mean) * inv) + bp[d];
    }
    __syncthreads();

    // kv accumulation: g_kv[b][h][d][e] += sum_t k[t,h,d]*v[t,h,e]
    for (int i = 0; i < 8; i++) {
        int eidx = tid + (i << 8);
        int h = eidx >> 8;
        int d = (eidx >> 4) & 15;
        int e = eidx & 15;
        float s = 0.f;
#pragma unroll 8
        for (int t = 0; t < 64; t++)
            s += KV[t * 264 + h * 32 + d] * KV[t * 264 + h * 32 + 16 + e];
        atomicAdd(&g_kv[((b * HEADS + h) * HD + d) * HD + e], s);
    }
}

// ---------------- kernel 2: compose Meff_b = Wq o kv / N ----------------
__global__ void compose_kernel(const float* __restrict__ qkv_w, const float* __restrict__ qkv_b) {
    __shared__ float kvs[HEADS * HD * HD];
    int b = blockIdx.x, tid = threadIdx.x;  // 128 threads
    for (int i = tid; i < HEADS * HD * HD; i += 128)
        kvs[i] = g_kv[b * HEADS * HD * HD + i] * (1.f / (float)NTOK);
    __syncthreads();
    {
        int h = tid >> 4, e = tid & 15;
        float s = 0.f;
#pragma unroll
        for (int d = 0; d < 16; d++) s += qkv_b[48 * h + d] * kvs[(h * 16 + d) * 16 + e];
        g_meffb[b * 128 + tid] = s;
    }
    for (int co = 0; co < 128; co++) {
        int h = co >> 4, e = co & 15;
        float s = 0.f;
#pragma unroll
        for (int d = 0; d < 16; d++)
            s += qkv_w[(48 * h + d) * 128 + tid] * kvs[(h * 16 + d) * 16 + e];
        g_meff[(b * 128 + co) * 128 + tid] = __float2bfloat16_rn(s);
    }
}

// ---------------- kernel 3: fused av + residual + o1 + gelu + o2 + residual ----------------
// 128 tokens/block. smem: xs[128][132] f32 | rt[128][132] f32 | w0/w1[128][136] bf16 | bias[384]
#define K4_XS_OFF 0
#define K4_RT_OFF (128 * 132 * 4)
#define K4_W_OFF  (K4_RT_OFF + 128 * 132 * 4)
#define K4_B_OFF  (K4_W_OFF + 2 * 128 * 136 * 2)
#define K4_SMEM   (K4_B_OFF + 3 * 128 * 4)

__global__ void __launch_bounds__(256, 1) main_kernel(const float* __restrict__ x,
                                                      const float* __restrict__ o1_b,
                                                      const float* __restrict__ o2_b,
                                                      float* __restrict__ out) {
    extern __shared__ char smem[];
    float* xs = (float*)(smem + K4_XS_OFF);
    float* rt = (float*)(smem + K4_RT_OFF);
    __nv_bfloat16* w0 = (__nv_bfloat16*)(smem + K4_W_OFF);
    __nv_bfloat16* w1 = w0 + 128 * 136;
    float* outs = (float*)w0;  // reused after final MMA, [128][129]
    float* bias = (float*)(smem + K4_B_OFF);

    int tid = threadIdx.x;
    int b = blockIdx.y;
    int n0 = blockIdx.x * 128;
    const float* xb = x + (size_t)b * CCH * NTOK;

    for (int i = tid; i < 128 * 128; i += 256) {
        int t = i & 127, c = i >> 7;
        xs[t * 132 + c] = xb[(size_t)c * NTOK + n0 + t];
    }
    {
        const unsigned* msrc = (const unsigned*)(g_meff + (size_t)b * 128 * 128);
        for (int i = tid; i < 128 * 64; i += 256) {
            int r = i >> 6, c = i & 63;
            ((unsigned*)(w0 + r * 136))[c] = msrc[r * 64 + c];
        }
    }
    if (tid < 128) {
        bias[tid] = g_meffb[b * 128 + tid];
        bias[128 + tid] = o1_b[tid];
        bias[256 + tid] = o2_b[tid];
    }
    __syncthreads();

    int w = tid >> 5, l = tid & 31;
    int mw = w >> 1, nw = w & 1;   // 4 x 2 warp grid over 128 x 128
    int lr = l >> 2, lc = l & 3;

    float acc[2][8][4];
#define ZACC() { _Pragma("unroll") for (int a_=0;a_<2;a_++) _Pragma("unroll") for (int b_=0;b_<8;b_++) _Pragma("unroll") for (int c_=0;c_<4;c_++) acc[a_][b_][c_]=0.f; }

    // phase 1: ret = Meff*x + meffb + x  (plain bf16 — av is tiny vs residual)
    ZACC();
    gemm128<false>(xs, 132, w0, nullptr, 136, acc, mw * 32, nw * 64, lr, lc);
#pragma unroll
    for (int mi = 0; mi < 2; mi++) {
        int row = mw * 32 + mi * 16 + lr;
#pragma unroll
        for (int ni = 0; ni < 8; ni++) {
            int col = nw * 64 + ni * 8 + lc * 2;
            rt[row * 132 + col]       = acc[mi][ni][0] + bias[col] + xs[row * 132 + col];
            rt[row * 132 + col + 1]   = acc[mi][ni][1] + bias[col + 1] + xs[row * 132 + col + 1];
            rt[(row + 8) * 132 + col]     = acc[mi][ni][2] + bias[col] + xs[(row + 8) * 132 + col];
            rt[(row + 8) * 132 + col + 1] = acc[mi][ni][3] + bias[col + 1] + xs[(row + 8) * 132 + col + 1];
        }
    }
    __syncthreads();

    // load o1 hi/lo
    for (int i = tid; i < 128 * 64; i += 256) {
        int r = i >> 6, c = i & 63;
        ((unsigned*)(w0 + r * 136))[c] = ((const unsigned*)g_o1hi)[r * 64 + c];
        ((unsigned*)(w1 + r * 136))[c] = ((const unsigned*)g_o1lo)[r * 64 + c];
    }
    __syncthreads();

    // phase 2: h1 = gelu(o1 * ret + b1)   (split bf16 for precision)
    ZACC();
    gemm128<true>(rt, 132, w0, w1, 136, acc, mw * 32, nw * 64, lr, lc);
#pragma unroll
    for (int mi = 0; mi < 2; mi++)
#pragma unroll
        for (int ni = 0; ni < 8; ni++) {
            int col = nw * 64 + ni * 8 + lc * 2;
#pragma unroll
            for (int q = 0; q < 4; q++) {
                float h = acc[mi][ni][q] + bias[128 + col + (q & 1)];
                acc[mi][ni][q] = 0.5f * h * (1.f + erff(h * 0.70710678118654752f));
            }
        }
    __syncthreads();  // all warps done reading rt/w0
#pragma unroll
    for (int mi = 0; mi < 2; mi++) {
        int row = mw * 32 + mi * 16 + lr;
#pragma unroll
        for (int ni = 0; ni < 8; ni++) {
            int col = nw * 64 + ni * 8 + lc * 2;
            rt[row * 132 + col]       = acc[mi][ni][0];
            rt[row * 132 + col + 1]   = acc[mi][ni][1];
            rt[(row + 8) * 132 + col]     = acc[mi][ni][2];
            rt[(row + 8) * 132 + col + 1] = acc[mi][ni][3];
        }
    }
    // load o2 hi/lo (w0 reads finished before the sync above)
    for (int i = tid; i < 128 * 64; i += 256) {
        int r = i >> 6, c = i & 63;
        ((unsigned*)(w0 + r * 136))[c] = ((const unsigned*)g_o2hi)[r * 64 + c];
        ((unsigned*)(w1 + r * 136))[c] = ((const unsigned*)g_o2lo)[r * 64 + c];
    }
    __syncthreads();

    // phase 3: out = o2 * h1 + b2 + x   (split bf16)
    ZACC();
    gemm128<true>(rt, 132, w0, w1, 136, acc, mw * 32, nw * 64, lr, lc);
#pragma unroll
    for (int mi = 0; mi < 2; mi++) {
        int row = mw * 32 + mi * 16 + lr;
#pragma unroll
        for (int ni = 0; ni < 8; ni++) {
            int col = nw * 64 + ni * 8 + lc * 2;
            acc[mi][ni][0] += bias[256 + col]     + xs[row * 132 + col];
            acc[mi][ni][1] += bias[256 + col + 1] + xs[row * 132 + col + 1];
            acc[mi][ni][2] += bias[256 + col]     + xs[(row + 8) * 132 + col];
            acc[mi][ni][3] += bias[256 + col + 1] + xs[(row + 8) * 132 + col + 1];
        }
    }
    __syncthreads();  // all MMA reads of w0 done; outs may now overlay it
#pragma unroll
    for (int mi = 0; mi < 2; mi++) {
        int row = mw * 32 + mi * 16 + lr;
#pragma unroll
        for (int ni = 0; ni < 8; ni++) {
            int col = nw * 64 + ni * 8 + lc * 2;
            outs[row * 129 + col]       = acc[mi][ni][0];
            outs[row * 129 + col + 1]   = acc[mi][ni][1];
            outs[(row + 8) * 129 + col]     = acc[mi][ni][2];
            outs[(row + 8) * 129 + col + 1] = acc[mi][ni][3];
        }
    }
    __syncthreads();

    // coalesced transposed store: out[b][c][n0+t]
    float* ob = out + (size_t)b * CCH * NTOK + n0;
    for (int i = tid; i < 128 * 128; i += 256) {
        int c = i >> 7, t = i & 127;
        ob[(size_t)c * NTOK + t] = outs[t * 129 + c];
    }
}

// ---------------- launch ----------------
extern "C" void kernel_launch(void* const* d_in, const int* in_sizes, int n_in,
                              void* d_out, int out_size) {
    const float* x     = (const float*)d_in[0];
    const float* qkv_w = (const float*)d_in[1];
    const float* qkv_b = (const float*)d_in[2];
    const float* o1_w  = (const float*)d_in[3];
    const float* o1_b  = (const float*)d_in[4];
    const float* o2_w  = (const float*)d_in[5];
    const float* o2_b  = (const float*)d_in[6];
    const float* kln_w = (const float*)d_in[7];
    const float* kln_b = (const float*)d_in[8];
    const float* vln_w = (const float*)d_in[9];
    const float* vln_b = (const float*)d_in[10];
    float* out = (float*)d_out;

    cudaFuncSetAttribute(kv_kernel, cudaFuncAttributeMaxDynamicSharedMemorySize, K2_SMEM);
    cudaFuncSetAttribute(main_kernel, cudaFuncAttributeMaxDynamicSharedMemorySize, K4_SMEM);

    prep_kernel<<<128, 256>>>(qkv_w, o1_w, o2_w);

    dim3 g2(NTOK / 64, BATCH);
    kv_kernel<<<g2, 256, K2_SMEM>>>(x, qkv_b, kln_w, kln_b, vln_w, vln_b);

    compose_kernel<<<BATCH, 128>>>(qkv_w, qkv_b);

    dim3 g4(NTOK / 128, BATCH);
    main_kernel<<<g4, 256, K4_SMEM>>>(x, o1_b, o2_b, out);
}

// round 2
// speedup vs baseline: 1.0032x; 1.0032x over previous
#include <cuda_runtime.h>
#include <cuda_bf16.h>

#define BATCH 8
#define CCH   128
#define NTOK  16384
#define HEADS 8
#define HD    16
#define LN_EPS 1e-5f

// ---------------- device scratch ----------------
__device__ float          g_kv[BATCH * HEADS * HD * HD];
__device__ __nv_bfloat16  g_wkv[256 * 128];
__device__ __nv_bfloat16  g_o1hi[128 * 128], g_o1lo[128 * 128];
__device__ __nv_bfloat16  g_o2hi[128 * 128], g_o2lo[128 * 128];
__device__ __nv_bfloat16  g_meff[BATCH * 128 * 128];
__device__ float          g_meffb[BATCH * 128];

// ---------------- helpers ----------------
__device__ __forceinline__ unsigned pk2f(float a, float b) {
    __nv_bfloat16 ha = __float2bfloat16_rn(a);
    __nv_bfloat16 hb = __float2bfloat16_rn(b);
    unsigned short ua = *reinterpret_cast<unsigned short*>(&ha);
    unsigned short ub = *reinterpret_cast<unsigned short*>(&hb);
    return (unsigned)ua | ((unsigned)ub << 16);
}

__device__ __forceinline__ void mma16816(float* c, const unsigned* a, const unsigned* b) {
    asm volatile(
        "mma.sync.aligned.m16n8k16.row.col.f32.bf16.bf16.f32 "
        "{%0,%1,%2,%3}, {%4,%5,%6,%7}, {%8,%9}, {%0,%1,%2,%3};\n"
        : "+f"(c[0]), "+f"(c[1]), "+f"(c[2]), "+f"(c[3])
        : "r"(a[0]), "r"(a[1]), "r"(a[2]), "r"(a[3]), "r"(b[0]), "r"(b[1]));
}

// write a float pair as bf16 hi + bf16 lo (residual) packed stores
__device__ __forceinline__ void store_split2(__nv_bfloat16* hi, __nv_bfloat16* lo, int idx,
                                             float a, float b) {
    __nv_bfloat16 ha = __float2bfloat16_rn(a);
    __nv_bfloat16 hb = __float2bfloat16_rn(b);
    unsigned short ua = *reinterpret_cast<unsigned short*>(&ha);
    unsigned short ub = *reinterpret_cast<unsigned short*>(&hb);
    *(unsigned*)(hi + idx) = (unsigned)ua | ((unsigned)ub << 16);
    *(unsigned*)(lo + idx) = pk2f(a - __bfloat162float(ha), b - __bfloat162float(hb));
}

// GEMM with bf16 A (optionally hi/lo split) and bf16 W (optionally hi/lo split).
// Warp computes rows [rbase, rbase+32) x cols [cbase, cbase+NI*8).
template <int NI, bool SPLIT>
__device__ __forceinline__ void gemm_bb(const __nv_bfloat16* __restrict__ Ahi,
                                        const __nv_bfloat16* __restrict__ Alo, int lda,
                                        const __nv_bfloat16* __restrict__ Whi,
                                        const __nv_bfloat16* __restrict__ Wlo, int ldw,
                                        float (&acc)[2][NI][4], int rbase, int cbase,
                                        int lr, int lc) {
#pragma unroll
    for (int kc = 0; kc < 128; kc += 16) {
        unsigned ah[2][4], al[2][4];
#pragma unroll
        for (int mi = 0; mi < 2; mi++) {
            const __nv_bfloat16* p = Ahi + (rbase + mi * 16 + lr) * lda + kc + lc * 2;
            ah[mi][0] = *(const unsigned*)p;
            ah[mi][1] = *(const unsigned*)(p + 8 * lda);
            ah[mi][2] = *(const unsigned*)(p + 8);
            ah[mi][3] = *(const unsigned*)(p + 8 * lda + 8);
            if (SPLIT) {
                const __nv_bfloat16* q = Alo + (rbase + mi * 16 + lr) * lda + kc + lc * 2;
                al[mi][0] = *(const unsigned*)q;
                al[mi][1] = *(const unsigned*)(q + 8 * lda);
                al[mi][2] = *(const unsigned*)(q + 8);
                al[mi][3] = *(const unsigned*)(q + 8 * lda + 8);
            }
        }
#pragma unroll
        for (int ni = 0; ni < NI; ni++) {
            int cb = cbase + ni * 8 + lr;
            const __nv_bfloat16* pb = Whi + cb * ldw + kc + lc * 2;
            unsigned bh[2] = {*(const unsigned*)pb, *(const unsigned*)(pb + 8)};
            mma16816(acc[0][ni], ah[0], bh);
            mma16816(acc[1][ni], ah[1], bh);
            if (SPLIT) {
                const __nv_bfloat16* pl = Wlo + cb * ldw + kc + lc * 2;
                unsigned bl[2] = {*(const unsigned*)pl, *(const unsigned*)(pl + 8)};
                mma16816(acc[0][ni], ah[0], bl);
                mma16816(acc[1][ni], ah[1], bl);
                mma16816(acc[0][ni], al[0], bh);
                mma16816(acc[1][ni], al[1], bh);
            }
        }
    }
}

// GEMM with fp32 A (convert on the fly), bf16 W. Used only for phase-1 (small share of work).
template <int NI>
__device__ __forceinline__ void gemm_fb(const float* __restrict__ A, int lda,
                                        const __nv_bfloat16* __restrict__ Whi, int ldw,
                                        float (&acc)[2][NI][4], int rbase, int cbase,
                                        int lr, int lc) {
#pragma unroll
    for (int kc = 0; kc < 128; kc += 16) {
        unsigned ah[2][4];
#pragma unroll
        for (int mi = 0; mi < 2; mi++) {
            const float* p0 = &A[(rbase + mi * 16 + lr) * lda + kc + lc * 2];
            const float* p1 = p0 + 8 * lda;
            float2 f0 = *(const float2*)p0;
            float2 f1 = *(const float2*)p1;
            float2 f2 = *(const float2*)(p0 + 8);
            float2 f3 = *(const float2*)(p1 + 8);
            ah[mi][0] = pk2f(f0.x, f0.y);
            ah[mi][1] = pk2f(f1.x, f1.y);
            ah[mi][2] = pk2f(f2.x, f2.y);
            ah[mi][3] = pk2f(f3.x, f3.y);
        }
#pragma unroll
        for (int ni = 0; ni < NI; ni++) {
            int cb = cbase + ni * 8 + lr;
            const __nv_bfloat16* pb = Whi + cb * ldw + kc + lc * 2;
            unsigned bh[2] = {*(const unsigned*)pb, *(const unsigned*)(pb + 8)};
            mma16816(acc[0][ni], ah[0], bh);
            mma16816(acc[1][ni], ah[1], bh);
        }
    }
}

// ---------------- kernel 0: weight prep ----------------
__global__ void prep_kernel(const float* __restrict__ qkv_w,
                            const float* __restrict__ o1_w,
                            const float* __restrict__ o2_w) {
    int idx = blockIdx.x * blockDim.x + threadIdx.x;
    int nthr = gridDim.x * blockDim.x;
    for (int i = idx; i < BATCH * HEADS * HD * HD; i += nthr) g_kv[i] = 0.f;
    for (int i = idx; i < 256 * 128; i += nthr) {
        int r = i >> 7, c = i & 127;
        int h = r >> 5, j = r & 31;
        int src = (j < 16) ? (48 * h + 16 + j) : (48 * h + 32 + (j - 16));
        g_wkv[i] = __float2bfloat16_rn(qkv_w[src * 128 + c]);
    }
    for (int i = idx; i < 128 * 128; i += nthr) {
        float f1 = o1_w[i];
        __nv_bfloat16 h1 = __float2bfloat16_rn(f1);
        g_o1hi[i] = h1;
        g_o1lo[i] = __float2bfloat16_rn(f1 - __bfloat162float(h1));
        float f2 = o2_w[i];
        __nv_bfloat16 h2 = __float2bfloat16_rn(f2);
        g_o2hi[i] = h2;
        g_o2lo[i] = __float2bfloat16_rn(f2 - __bfloat162float(h2));
    }
}

// ---------------- kernel 1: k,v projection + LN + kv via MMA ----------------
// grid (64, BATCH), 256 threads, 4 tiles of 64 tokens each.
#define KV_TILES 4
#define KV_AS_OFF 0
#define KV_AS_SZ  (64 * 136 * 2)
#define KV_WT_OFF (KV_AS_OFF + KV_AS_SZ)
#define KV_WT_SZ  (256 * 136 * 2)
#define KV_KV_OFF (KV_WT_OFF + KV_WT_SZ)
#define KV_KV_SZ  (64 * 264 * 4)
#define KV_KT_OFF (KV_KV_OFF + KV_KV_SZ)
#define KV_KT_SZ  (128 * 72 * 2)
#define KV_VT_OFF (KV_KT_OFF + KV_KT_SZ)
#define KV_VT_SZ  (128 * 72 * 2)
#define KV_QB_OFF (KV_VT_OFF + KV_VT_SZ)
#define KV_SMEM   (KV_QB_OFF + 256 * 4)

__global__ void __launch_bounds__(256, 1) kv_kernel(const float* __restrict__ x,
                                                    const float* __restrict__ qkv_b,
                                                    const float* __restrict__ kln_w,
                                                    const float* __restrict__ kln_b,
                                                    const float* __restrict__ vln_w,
                                                    const float* __restrict__ vln_b) {
    extern __shared__ char smem[];
    __nv_bfloat16* As = (__nv_bfloat16*)(smem + KV_AS_OFF);
    __nv_bfloat16* Wt = (__nv_bfloat16*)(smem + KV_WT_OFF);
    float* KV = (float*)(smem + KV_KV_OFF);
    __nv_bfloat16* kT = (__nv_bfloat16*)(smem + KV_KT_OFF);
    __nv_bfloat16* vT = (__nv_bfloat16*)(smem + KV_VT_OFF);
    float* qb = (float*)(smem + KV_QB_OFF);

    int tid = threadIdx.x;
    int b = blockIdx.y;
    const float* xb = x + (size_t)b * CCH * NTOK;

    // weights + bias (once per block)
    {
        const unsigned* src = (const unsigned*)g_wkv;
        for (int i = tid; i < 256 * 64; i += 256) {
            int r = i >> 6, c32 = i & 63;
            ((unsigned*)(Wt + r * 136))[c32] = src[r * 64 + c32];
        }
        int h = tid >> 5, j = tid & 31;
        int src_r = (j < 16) ? (48 * h + 16 + j) : (48 * h + 32 + (j - 16));
        qb[tid] = qkv_b[src_r];
    }

    int w = tid >> 5, l = tid & 31;
    int mw = w >> 2, nw = w & 3;   // 2 x 4 warps over 64 x 256
    int lr = l >> 2, lc = l & 3;

    // per-warp kv accumulators (head = w), persist across tiles
    float acc2[2][4];
#pragma unroll
    for (int e = 0; e < 2; e++)
#pragma unroll
        for (int q = 0; q < 4; q++) acc2[e][q] = 0.f;

    for (int tile = 0; tile < KV_TILES; tile++) {
        int n0 = (blockIdx.x * KV_TILES + tile) * 64;

        // load x tile -> bf16
        for (int i = tid; i < 64 * 128; i += 256) {
            int t = i & 63, c = i >> 6;
            As[t * 136 + c] = __float2bfloat16_rn(xb[(size_t)c * NTOK + n0 + t]);
        }
        __syncthreads();

        float acc[2][8][4];
#pragma unroll
        for (int a_ = 0; a_ < 2; a_++)
#pragma unroll
            for (int b_ = 0; b_ < 8; b_++)
#pragma unroll
                for (int c_ = 0; c_ < 4; c_++) acc[a_][b_][c_] = 0.f;

        gemm_bb<8, false>(As, nullptr, 136, Wt, nullptr, 136, acc, mw * 32, nw * 64, lr, lc);

        // epilogue: k/v (+bias) -> KV fp32
#pragma unroll
        for (int mi = 0; mi < 2; mi++) {
            int row = mw * 32 + mi * 16 + lr;
#pragma unroll
            for (int ni = 0; ni < 8; ni++) {
                int col = nw * 64 + ni * 8 + lc * 2;
                KV[row * 264 + col]           = acc[mi][ni][0] + qb[col];
                KV[row * 264 + col + 1]       = acc[mi][ni][1] + qb[col + 1];
                KV[(row + 8) * 264 + col]     = acc[mi][ni][2] + qb[col];
                KV[(row + 8) * 264 + col + 1] = acc[mi][ni][3] + qb[col + 1];
            }
        }
        __syncthreads();

        // LayerNorm over d=16 (ddof=1, eps on std); write transposed bf16 kT/vT
        for (int task = tid; task < 1024; task += 256) {
            int t = task >> 4;
            int rem = task & 15;
            int h = rem >> 1;
            int isv = rem & 1;
            const float* p = &KV[t * 264 + h * 32 + isv * 16];
            float s = 0.f, ss = 0.f;
#pragma unroll
            for (int d = 0; d < 16; d++) { float vv = p[d]; s += vv; ss += vv * vv; }
            float mean = s * (1.f / 16.f);
            float var = (ss - 16.f * mean * mean) * (1.f / 15.f);
            var = fmaxf(var, 0.f);
            float inv = 1.f / (sqrtf(var) + LN_EPS);
            const float* wp = (isv ? vln_w : kln_w) + h * 16;
            const float* bp = (isv ? vln_b : kln_b) + h * 16;
            __nv_bfloat16* dstT = isv ? vT : kT;
#pragma unroll
            for (int d = 0; d < 16; d++) {
                float val = wp[d] * ((p[d] - mean) * inv) + bp[d];
                dstT[(h * 16 + d) * 72 + t] = __float2bfloat16_rn(val);
            }
        }
        __syncthreads();

        // kv accumulation via MMA: warp w owns head w. C[d][e] += sum_t kT[d][t]*vT[e][t]
#pragma unroll
        for (int tcc = 0; tcc < 4; tcc++) {
            int tc = tcc * 16;
            unsigned a[4];
            const __nv_bfloat16* pa = kT + (w * 16 + lr) * 72 + tc + lc * 2;
            a[0] = *(const unsigned*)pa;
            a[1] = *(const unsigned*)(pa + 8 * 72);
            a[2] = *(const unsigned*)(pa + 8);
            a[3] = *(const unsigned*)(pa + 8 * 72 + 8);
#pragma unroll
            for (int eh = 0; eh < 2; eh++) {
                const __nv_bfloat16* pb = vT + (w * 16 + eh * 8 + lr) * 72 + tc + lc * 2;
                unsigned bb[2] = {*(const unsigned*)pb, *(const unsigned*)(pb + 8)};
                mma16816(acc2[eh], a, bb);
            }
        }
        __syncthreads();  // protect kT/vT against next tile's LN writes
    }

    // flush kv accumulators (one atomic round per block)
    float* base = g_kv + (size_t)(b * HEADS + w) * HD * HD;
#pragma unroll
    for (int eh = 0; eh < 2; eh++) {
        int e0 = eh * 8 + lc * 2;
        atomicAdd(base + lr * 16 + e0,           acc2[eh][0]);
        atomicAdd(base + lr * 16 + e0 + 1,       acc2[eh][1]);
        atomicAdd(base + (lr + 8) * 16 + e0,     acc2[eh][2]);
        atomicAdd(base + (lr + 8) * 16 + e0 + 1, acc2[eh][3]);
    }
}

// ---------------- kernel 2: compose Meff_b = Wq o kv / N ----------------
__global__ void compose_kernel(const float* __restrict__ qkv_w, const float* __restrict__ qkv_b) {
    __shared__ float kvs[HEADS * HD * HD];
    int b = blockIdx.x, tid = threadIdx.x;  // 128 threads
    for (int i = tid; i < HEADS * HD * HD; i += 128)
        kvs[i] = g_kv[b * HEADS * HD * HD + i] * (1.f / (float)NTOK);
    __syncthreads();
    {
        int h = tid >> 4, e = tid & 15;
        float s = 0.f;
#pragma unroll
        for (int d = 0; d < 16; d++) s += qkv_b[48 * h + d] * kvs[(h * 16 + d) * 16 + e];
        g_meffb[b * 128 + tid] = s;
    }
    for (int co = 0; co < 128; co++) {
        int h = co >> 4, e = co & 15;
        float s = 0.f;
#pragma unroll
        for (int d = 0; d < 16; d++)
            s += qkv_w[(48 * h + d) * 128 + tid] * kvs[(h * 16 + d) * 16 + e];
        g_meff[(b * 128 + co) * 128 + tid] = __float2bfloat16_rn(s);
    }
}

// ---------------- kernel 3: fused av + residual + o1 + gelu + o2 + residual ----------------
// 128 tokens/block, 512 threads (16 warps, 4x4 grid of 32x32 warp tiles).
#define K4_XS_OFF 0
#define K4_XS_SZ  (128 * 132 * 4)
#define K4_RH_OFF (K4_XS_OFF + K4_XS_SZ)
#define K4_RH_SZ  (128 * 136 * 2)
#define K4_RL_OFF (K4_RH_OFF + K4_RH_SZ)
#define K4_W0_OFF (K4_RL_OFF + K4_RH_SZ)
#define K4_W1_OFF (K4_W0_OFF + K4_RH_SZ)
#define K4_B_OFF  (K4_W1_OFF + K4_RH_SZ)
#define K4_SMEM   (K4_B_OFF + 3 * 128 * 4)

__global__ void __launch_bounds__(512, 1) main_kernel(const float* __restrict__ x,
                                                      const float* __restrict__ o1_b,
                                                      const float* __restrict__ o2_b,
                                                      float* __restrict__ out) {
    extern __shared__ char smem[];
    float* xs = (float*)(smem + K4_XS_OFF);
    __nv_bfloat16* rth = (__nv_bfloat16*)(smem + K4_RH_OFF);
    __nv_bfloat16* rtl = (__nv_bfloat16*)(smem + K4_RL_OFF);
    __nv_bfloat16* w0 = (__nv_bfloat16*)(smem + K4_W0_OFF);
    __nv_bfloat16* w1 = (__nv_bfloat16*)(smem + K4_W1_OFF);
    float* outs = (float*)(smem + K4_RH_OFF);  // overlay on rth/rtl after final GEMM, [128][129]
    float* bias = (float*)(smem + K4_B_OFF);

    int tid = threadIdx.x;
    int b = blockIdx.y;
    int n0 = blockIdx.x * 128;
    const float* xb = x + (size_t)b * CCH * NTOK;

    for (int i = tid; i < 128 * 128; i += 512) {
        int t = i & 127, c = i >> 7;
        xs[t * 132 + c] = xb[(size_t)c * NTOK + n0 + t];
    }
    {
        const unsigned* msrc = (const unsigned*)(g_meff + (size_t)b * 128 * 128);
        for (int i = tid; i < 128 * 64; i += 512) {
            int r = i >> 6, c = i & 63;
            ((unsigned*)(w0 + r * 136))[c] = msrc[r * 64 + c];
        }
    }
    if (tid < 128) {
        bias[tid] = g_meffb[b * 128 + tid];
        bias[128 + tid] = o1_b[tid];
        bias[256 + tid] = o2_b[tid];
    }
    __syncthreads();

    int w = tid >> 5, l = tid & 31;
    int mw = w >> 2, nw = w & 3;  // 4 x 4 warps over 128 x 128
    int lr = l >> 2, lc = l & 3;
    int rbase = mw * 32, cbase = nw * 32;

    float acc[2][4][4];
#define ZACC() { _Pragma("unroll") for (int a_=0;a_<2;a_++) _Pragma("unroll") for (int b_=0;b_<4;b_++) _Pragma("unroll") for (int c_=0;c_<4;c_++) acc[a_][b_][c_]=0.f; }

    // phase 1: ret = Meff*x + meffb + x   (plain bf16 — av tiny vs residual)
    ZACC();
    gemm_fb<4>(xs, 132, w0, 136, acc, rbase, cbase, lr, lc);
#pragma unroll
    for (int mi = 0; mi < 2; mi++) {
        int row = rbase + mi * 16 + lr;
#pragma unroll
        for (int ni = 0; ni < 4; ni++) {
            int col = cbase + ni * 8 + lc * 2;
            float r00 = acc[mi][ni][0] + bias[col]     + xs[row * 132 + col];
            float r01 = acc[mi][ni][1] + bias[col + 1] + xs[row * 132 + col + 1];
            float r10 = acc[mi][ni][2] + bias[col]     + xs[(row + 8) * 132 + col];
            float r11 = acc[mi][ni][3] + bias[col + 1] + xs[(row + 8) * 132 + col + 1];
            store_split2(rth, rtl, row * 136 + col, r00, r01);
            store_split2(rth, rtl, (row + 8) * 136 + col, r10, r11);
        }
    }
    __syncthreads();

    // load o1 hi/lo
    for (int i = tid; i < 128 * 64; i += 512) {
        int r = i >> 6, c = i & 63;
        ((unsigned*)(w0 + r * 136))[c] = ((const unsigned*)g_o1hi)[r * 64 + c];
        ((unsigned*)(w1 + r * 136))[c] = ((const unsigned*)g_o1lo)[r * 64 + c];
    }
    __syncthreads();

    // phase 2: h1 = gelu(o1 * ret + b1)
    ZACC();
    gemm_bb<4, true>(rth, rtl, 136, w0, w1, 136, acc, rbase, cbase, lr, lc);
#pragma unroll
    for (int mi = 0; mi < 2; mi++)
#pragma unroll
        for (int ni = 0; ni < 4; ni++) {
            int col = cbase + ni * 8 + lc * 2;
#pragma unroll
            for (int q = 0; q < 4; q++) {
                float h = acc[mi][ni][q] + bias[128 + col + (q & 1)];
                acc[mi][ni][q] = 0.5f * h * (1.f + erff(h * 0.70710678118654752f));
            }
        }
    __syncthreads();  // all reads of rt / w0 done
#pragma unroll
    for (int mi = 0; mi < 2; mi++) {
        int row = rbase + mi * 16 + lr;
#pragma unroll
        for (int ni = 0; ni < 4; ni++) {
            int col = cbase + ni * 8 + lc * 2;
            store_split2(rth, rtl, row * 136 + col, acc[mi][ni][0], acc[mi][ni][1]);
            store_split2(rth, rtl, (row + 8) * 136 + col, acc[mi][ni][2], acc[mi][ni][3]);
        }
    }
    // load o2 hi/lo
    for (int i = tid; i < 128 * 64; i += 512) {
        int r = i >> 6, c = i & 63;
        ((unsigned*)(w0 + r * 136))[c] = ((const unsigned*)g_o2hi)[r * 64 + c];
        ((unsigned*)(w1 + r * 136))[c] = ((const unsigned*)g_o2lo)[r * 64 + c];
    }
    __syncthreads();

    // phase 3: out = o2 * h1 + b2 + x
    ZACC();
    gemm_bb<4, true>(rth, rtl, 136, w0, w1, 136, acc, rbase, cbase, lr, lc);
#pragma unroll
    for (int mi = 0; mi < 2; mi++) {
        int row = rbase + mi * 16 + lr;
#pragma unroll
        for (int ni = 0; ni < 4; ni++) {
            int col = cbase + ni * 8 + lc * 2;
            acc[mi][ni][0] += bias[256 + col]     + xs[row * 132 + col];
            acc[mi][ni][1] += bias[256 + col + 1] + xs[row * 132 + col + 1];
            acc[mi][ni][2] += bias[256 + col]     + xs[(row + 8) * 132 + col];
            acc[mi][ni][3] += bias[256 + col + 1] + xs[(row + 8) * 132 + col + 1];
        }
    }
    __syncthreads();  // rt reads done; outs may overlay
#pragma unroll
    for (int mi = 0; mi < 2; mi++) {
        int row = rbase + mi * 16 + lr;
#pragma unroll
        for (int ni = 0; ni < 4; ni++) {
            int col = cbase + ni * 8 + lc * 2;
            outs[row * 129 + col]           = acc[mi][ni][0];
            outs[row * 129 + col + 1]       = acc[mi][ni][1];
            outs[(row + 8) * 129 + col]     = acc[mi][ni][2];
            outs[(row + 8) * 129 + col + 1] = acc[mi][ni][3];
        }
    }
    __syncthreads();

    // coalesced transposed store
    float* ob = out + (size_t)b * CCH * NTOK + n0;
    for (int i = tid; i < 128 * 128; i += 512) {
        int c = i >> 7, t = i & 127;
        ob[(size_t)c * NTOK + t] = outs[t * 129 + c];
    }
}

// ---------------- launch ----------------
extern "C" void kernel_launch(void* const* d_in, const int* in_sizes, int n_in,
                              void* d_out, int out_size) {
    const float* x     = (const float*)d_in[0];
    const float* qkv_w = (const float*)d_in[1];
    const float* qkv_b = (const float*)d_in[2];
    const float* o1_w  = (const float*)d_in[3];
    const float* o1_b  = (const float*)d_in[4];
    const float* o2_w  = (const float*)d_in[5];
    const float* o2_b  = (const float*)d_in[6];
    const float* kln_w = (const float*)d_in[7];
    const float* kln_b = (const float*)d_in[8];
    const float* vln_w = (const float*)d_in[9];
    const float* vln_b = (const float*)d_in[10];
    float* out = (float*)d_out;

    cudaFuncSetAttribute(kv_kernel, cudaFuncAttributeMaxDynamicSharedMemorySize, KV_SMEM);
    cudaFuncSetAttribute(main_kernel, cudaFuncAttributeMaxDynamicSharedMemorySize, K4_SMEM);

    prep_kernel<<<128, 256>>>(qkv_w, o1_w, o2_w);

    dim3 g2(NTOK / (64 * KV_TILES), BATCH);
    kv_kernel<<<g2, 256, KV_SMEM>>>(x, qkv_b, kln_w, kln_b, vln_w, vln_b);

    compose_kernel<<<BATCH, 128>>>(qkv_w, qkv_b);

    dim3 g4(NTOK / 128, BATCH);
    main_kernel<<<g4, 512, K4_SMEM>>>(x, o1_b, o2_b, out);
}

// round 3
// speedup vs baseline: 2.0744x; 2.0677x over previous
#include <cuda_runtime.h>
#include <cuda_fp16.h>

#define BATCH 8
#define CCH   128
#define NTOK  16384
#define HEADS 8
#define HD    16
#define LN_EPS 1e-5f

// ---------------- device scratch ----------------
__device__ float  g_kv[BATCH * HEADS * HD * HD];
__device__ __half g_wkv[256 * 128];
__device__ __half g_o1h[128 * 128];
__device__ __half g_o2h[128 * 128];
__device__ __half g_meff[BATCH * 128 * 128];
__device__ float  g_meffb[BATCH * 128];

// ---------------- helpers ----------------
__device__ __forceinline__ unsigned pk2h(float a, float b) {
    __half2 h = __floats2half2_rn(a, b);
    return *reinterpret_cast<unsigned*>(&h);
}

__device__ __forceinline__ void mma16816h(float* c, const unsigned* a, const unsigned* b) {
    asm volatile(
        "mma.sync.aligned.m16n8k16.row.col.f32.f16.f16.f32 "
        "{%0,%1,%2,%3}, {%4,%5,%6,%7}, {%8,%9}, {%0,%1,%2,%3};\n"
        : "+f"(c[0]), "+f"(c[1]), "+f"(c[2]), "+f"(c[3])
        : "r"(a[0]), "r"(a[1]), "r"(a[2]), "r"(a[3]), "r"(b[0]), "r"(b[1]));
}

__device__ __forceinline__ unsigned smem_u32(const void* p) {
    return (unsigned)__cvta_generic_to_shared(p);
}

__device__ __forceinline__ void cpasync16(unsigned s, const void* g) {
    asm volatile("cp.async.cg.shared.global [%0], [%1], 16;\n" :: "r"(s), "l"(g));
}
#define CP_COMMIT() asm volatile("cp.async.commit_group;\n")
#define CP_WAIT(n)  asm volatile("cp.async.wait_group %0;\n" :: "n"(n))

// fp16 GEMM: A [tokens][k] ld=lda halves, W [cout][k] ld=ldw halves, K=128.
// Warp computes rows [rbase, rbase+32) x cols [cbase, cbase+NI*8).
template <int NI>
__device__ __forceinline__ void gemm_h(const __half* __restrict__ A, int lda,
                                       const __half* __restrict__ W, int ldw,
                                       float (&acc)[2][NI][4], int rbase, int cbase,
                                       int lr, int lc) {
#pragma unroll
    for (int kc = 0; kc < 128; kc += 16) {
        unsigned ah[2][4];
#pragma unroll
        for (int mi = 0; mi < 2; mi++) {
            const __half* p = A + (rbase + mi * 16 + lr) * lda + kc + lc * 2;
            ah[mi][0] = *(const unsigned*)p;
            ah[mi][1] = *(const unsigned*)(p + 8 * lda);
            ah[mi][2] = *(const unsigned*)(p + 8);
            ah[mi][3] = *(const unsigned*)(p + 8 * lda + 8);
        }
#pragma unroll
        for (int ni = 0; ni < NI; ni++) {
            int cb = cbase + ni * 8 + lr;
            const __half* pb = W + cb * ldw + kc + lc * 2;
            unsigned bh[2] = {*(const unsigned*)pb, *(const unsigned*)(pb + 8)};
            mma16816h(acc[0][ni], ah[0], bh);
            mma16816h(acc[1][ni], ah[1], bh);
        }
    }
}

// ---------------- kernel 0: weight prep ----------------
__global__ void prep_kernel(const float* __restrict__ qkv_w,
                            const float* __restrict__ o1_w,
                            const float* __restrict__ o2_w) {
    int idx = blockIdx.x * blockDim.x + threadIdx.x;
    int nthr = gridDim.x * blockDim.x;
    for (int i = idx; i < BATCH * HEADS * HD * HD; i += nthr) g_kv[i] = 0.f;
    for (int i = idx; i < 256 * 128; i += nthr) {
        int r = i >> 7, c = i & 127;
        int h = r >> 5, j = r & 31;
        int src = (j < 16) ? (48 * h + 16 + j) : (48 * h + 32 + (j - 16));
        g_wkv[i] = __float2half_rn(qkv_w[src * 128 + c]);
    }
    for (int i = idx; i < 128 * 128; i += nthr) {
        g_o1h[i] = __float2half_rn(o1_w[i]);
        g_o2h[i] = __float2half_rn(o2_w[i]);
    }
}

// ---------------- kernel 1: k,v projection + register-LN + kv via MMA ----------------
// 512 threads, 2 tiles of 128 tokens per block. grid (NTOK/256, BATCH).
#define KV_TILES 2
#define KV_AS_OFF 0
#define KV_AS_SZ  (128 * 136 * 2)
#define KV_WT_OFF (KV_AS_OFF + KV_AS_SZ)
#define KV_WT_SZ  (256 * 136 * 2)
#define KV_KT_OFF (KV_WT_OFF + KV_WT_SZ)
#define KV_KT_SZ  (128 * 136 * 2)
#define KV_VT_OFF (KV_KT_OFF + KV_KT_SZ)
#define KV_VT_SZ  (128 * 136 * 2)
#define KV_LNW_OFF (KV_VT_OFF + KV_VT_SZ)
#define KV_LNB_OFF (KV_LNW_OFF + 256 * 4)
#define KV_QB_OFF  (KV_LNB_OFF + 256 * 4)
#define KV_SMEM    (KV_QB_OFF + 256 * 4)

__global__ void __launch_bounds__(512, 1) kv_kernel(const float* __restrict__ x,
                                                    const float* __restrict__ qkv_b,
                                                    const float* __restrict__ kln_w,
                                                    const float* __restrict__ kln_b,
                                                    const float* __restrict__ vln_w,
                                                    const float* __restrict__ vln_b) {
    extern __shared__ char smem[];
    __half* As = (__half*)(smem + KV_AS_OFF);
    __half* Wt = (__half*)(smem + KV_WT_OFF);
    __half* kT = (__half*)(smem + KV_KT_OFF);
    __half* vT = (__half*)(smem + KV_VT_OFF);
    float* lnw = (float*)(smem + KV_LNW_OFF);
    float* lnb = (float*)(smem + KV_LNB_OFF);
    float* qb  = (float*)(smem + KV_QB_OFF);

    int tid = threadIdx.x;
    int b = blockIdx.y;
    const float* xb = x + (size_t)b * CCH * NTOK;

    // per-block constants
    {
        const unsigned* src = (const unsigned*)g_wkv;
        for (int i = tid; i < 256 * 64; i += 512) {
            int r = i >> 6, c = i & 63;
            ((unsigned*)(Wt + r * 136))[c] = src[r * 64 + c];
        }
        if (tid < 256) {
            int h = tid >> 5, j = tid & 31;
            int isv = (j >= 16), d = j & 15;
            int src_r = (j < 16) ? (48 * h + 16 + j) : (48 * h + 32 + (j - 16));
            qb[tid] = qkv_b[src_r];
            lnw[tid] = (isv ? vln_w : kln_w)[h * 16 + d];
            lnb[tid] = (isv ? vln_b : kln_b)[h * 16 + d];
        }
    }

    int w = tid >> 5, l = tid & 31;
    int mw = w >> 2, nw = w & 3;   // 4 x 4 warps over 128 tok x 256 out
    int lr = l >> 2, lc = l & 3;

    // per-warp kv accumulators: head = w>>1, token-half = w&1
    int hh = w >> 1, th = w & 1;
    float acc2[2][4];
#pragma unroll
    for (int e = 0; e < 2; e++)
#pragma unroll
        for (int q = 0; q < 4; q++) acc2[e][q] = 0.f;

    for (int tile = 0; tile < KV_TILES; tile++) {
        int n0 = (blockIdx.x * KV_TILES + tile) * 128;

        // x tile -> fp16 (coalesced global read)
        for (int i = tid; i < 128 * 128; i += 512) {
            int t = i & 127, c = i >> 7;
            As[t * 136 + c] = __float2half_rn(xb[(size_t)c * NTOK + n0 + t]);
        }
        __syncthreads();

        float acc[2][8][4];
#pragma unroll
        for (int a_ = 0; a_ < 2; a_++)
#pragma unroll
            for (int b_ = 0; b_ < 8; b_++)
#pragma unroll
                for (int c_ = 0; c_ < 4; c_++) acc[a_][b_][c_] = 0.f;

        gemm_h<8>(As, 136, Wt, 136, acc, mw * 32, nw * 64, lr, lc);

        // bias add
#pragma unroll
        for (int mi = 0; mi < 2; mi++)
#pragma unroll
            for (int ni = 0; ni < 8; ni++) {
                int col = nw * 64 + ni * 8 + lc * 2;
                acc[mi][ni][0] += qb[col];
                acc[mi][ni][1] += qb[col + 1];
                acc[mi][ni][2] += qb[col];
                acc[mi][ni][3] += qb[col + 1];
            }

        // register LayerNorm per 16-wide group (ddof=1, eps on std) + transposed fp16 write
#pragma unroll
        for (int g = 0; g < 4; g++) {
            int hg = 2 * nw + (g >> 1);
            int isv = g & 1;
            __half* dstT = isv ? vT : kT;
#pragma unroll
            for (int mi = 0; mi < 2; mi++)
#pragma unroll
                for (int rh = 0; rh < 2; rh++) {
                    float v0 = acc[mi][2 * g][rh * 2];
                    float v1 = acc[mi][2 * g][rh * 2 + 1];
                    float v2 = acc[mi][2 * g + 1][rh * 2];
                    float v3 = acc[mi][2 * g + 1][rh * 2 + 1];
                    float s = v0 + v1 + v2 + v3;
                    float ss = v0 * v0 + v1 * v1 + v2 * v2 + v3 * v3;
                    s  += __shfl_xor_sync(0xffffffffu, s, 1);
                    ss += __shfl_xor_sync(0xffffffffu, ss, 1);
                    s  += __shfl_xor_sync(0xffffffffu, s, 2);
                    ss += __shfl_xor_sync(0xffffffffu, ss, 2);
                    float mean = s * (1.f / 16.f);
                    float var = (ss - 16.f * mean * mean) * (1.f / 15.f);
                    var = fmaxf(var, 0.f);
                    float inv = 1.f / (sqrtf(var) + LN_EPS);
                    int t = mw * 32 + mi * 16 + rh * 8 + lr;
                    int c0 = nw * 64 + g * 16 + lc * 2;       // group d = lc*2
                    int c1 = c0 + 8;                           // group d = 8 + lc*2
                    int d0 = lc * 2, d1 = 8 + lc * 2;
                    float n0v = lnw[c0] * ((v0 - mean) * inv) + lnb[c0];
                    float n1v = lnw[c0 + 1] * ((v1 - mean) * inv) + lnb[c0 + 1];
                    float n2v = lnw[c1] * ((v2 - mean) * inv) + lnb[c1];
                    float n3v = lnw[c1 + 1] * ((v3 - mean) * inv) + lnb[c1 + 1];
                    dstT[(hg * 16 + d0) * 136 + t]     = __float2half_rn(n0v);
                    dstT[(hg * 16 + d0 + 1) * 136 + t] = __float2half_rn(n1v);
                    dstT[(hg * 16 + d1) * 136 + t]     = __float2half_rn(n2v);
                    dstT[(hg * 16 + d1 + 1) * 136 + t] = __float2half_rn(n3v);
                }
        }
        __syncthreads();

        // per-head kv outer product: warp (hh, th) does C[d][e] += sum_t kT[d][t]*vT[e][t]
#pragma unroll
        for (int tcc = 0; tcc < 4; tcc++) {
            int tc = th * 64 + tcc * 16;
            unsigned a[4];
            const __half* pa = kT + (hh * 16 + lr) * 136 + tc + lc * 2;
            a[0] = *(const unsigned*)pa;
            a[1] = *(const unsigned*)(pa + 8 * 136);
            a[2] = *(const unsigned*)(pa + 8);
            a[3] = *(const unsigned*)(pa + 8 * 136 + 8);
#pragma unroll
            for (int eh = 0; eh < 2; eh++) {
                const __half* pb = vT + (hh * 16 + eh * 8 + lr) * 136 + tc + lc * 2;
                unsigned bb[2] = {*(const unsigned*)pb, *(const unsigned*)(pb + 8)};
                mma16816h(acc2[eh], a, bb);
            }
        }
        __syncthreads();  // kT/vT reads done before next tile rewrites
    }

    // flush
    float* base = g_kv + (size_t)(b * HEADS + hh) * HD * HD;
#pragma unroll
    for (int eh = 0; eh < 2; eh++) {
        int e0 = eh * 8 + lc * 2;
        atomicAdd(base + lr * 16 + e0,           acc2[eh][0]);
        atomicAdd(base + lr * 16 + e0 + 1,       acc2[eh][1]);
        atomicAdd(base + (lr + 8) * 16 + e0,     acc2[eh][2]);
        atomicAdd(base + (lr + 8) * 16 + e0 + 1, acc2[eh][3]);
    }
}

// ---------------- kernel 2: compose Meff_b = Wq o kv / N ----------------
__global__ void compose_kernel(const float* __restrict__ qkv_w, const float* __restrict__ qkv_b) {
    __shared__ float kvs[HEADS * HD * HD];
    int b = blockIdx.x, tid = threadIdx.x;  // 128 threads
    for (int i = tid; i < HEADS * HD * HD; i += 128)
        kvs[i] = g_kv[b * HEADS * HD * HD + i] * (1.f / (float)NTOK);
    __syncthreads();
    {
        int h = tid >> 4, e = tid & 15;
        float s = 0.f;
#pragma unroll
        for (int d = 0; d < 16; d++) s += qkv_b[48 * h + d] * kvs[(h * 16 + d) * 16 + e];
        g_meffb[b * 128 + tid] = s;
    }
    for (int co = 0; co < 128; co++) {
        int h = co >> 4, e = co & 15;
        float s = 0.f;
#pragma unroll
        for (int d = 0; d < 16; d++)
            s += qkv_w[(48 * h + d) * 128 + tid] * kvs[(h * 16 + d) * 16 + e];
        g_meff[(b * 128 + co) * 128 + tid] = __float2half_rn(s);
    }
}

// ---------------- kernel 3: fused av + residual + o1 + gelu + o2 + residual ----------------
// 512 threads, 128 tokens/block. All GEMMs plain fp16.
#define K4_XS_OFF 0
#define K4_XS_SZ  (128 * 132 * 4)
#define K4_XH_OFF (K4_XS_OFF + K4_XS_SZ)
#define K4_H_SZ   (128 * 136 * 2)
#define K4_RT_OFF (K4_XH_OFF + K4_H_SZ)
#define K4_WA_OFF (K4_RT_OFF + K4_H_SZ)
#define K4_WB_OFF (K4_WA_OFF + K4_H_SZ)
#define K4_B_OFF  (K4_WB_OFF + K4_H_SZ)
#define K4_SMEM   (K4_B_OFF + 3 * 128 * 4)

__global__ void __launch_bounds__(512, 1) main_kernel(const float* __restrict__ x,
                                                      const float* __restrict__ o1_b,
                                                      const float* __restrict__ o2_b,
                                                      float* __restrict__ out) {
    extern __shared__ char smem[];
    float* xs = (float*)(smem + K4_XS_OFF);
    __half* xh = (__half*)(smem + K4_XH_OFF);
    __half* rt = (__half*)(smem + K4_RT_OFF);
    __half* wA = (__half*)(smem + K4_WA_OFF);
    __half* wB = (__half*)(smem + K4_WB_OFF);
    float* outs = (float*)(smem + K4_RT_OFF);  // overlay rt+wA after phase3
    float* bias = (float*)(smem + K4_B_OFF);

    int tid = threadIdx.x;
    int b = blockIdx.y;
    int n0 = blockIdx.x * 128;
    const float* xb = x + (size_t)b * CCH * NTOK;

    // cp.async: group 0 = Meff -> wA
    {
        unsigned wa = smem_u32(wA);
        const __half* msrc = g_meff + (size_t)b * 128 * 128;
        for (int i = tid; i < 128 * 16; i += 512) {
            int r = i >> 4, c = i & 15;
            cpasync16(wa + r * 272 + c * 16, msrc + r * 128 + c * 8);
        }
    }
    CP_COMMIT();
    // group 1 = o1 -> wB (overlaps phase 1)
    {
        unsigned wb = smem_u32(wB);
        for (int i = tid; i < 128 * 16; i += 512) {
            int r = i >> 4, c = i & 15;
            cpasync16(wb + r * 272 + c * 16, g_o1h + r * 128 + c * 8);
        }
    }
    CP_COMMIT();

    // x tile: fp32 + fp16 copies
    for (int i = tid; i < 128 * 128; i += 512) {
        int t = i & 127, c = i >> 7;
        float v = xb[(size_t)c * NTOK + n0 + t];
        xs[t * 132 + c] = v;
        xh[t * 136 + c] = __float2half_rn(v);
    }
    if (tid < 128) {
        bias[tid] = g_meffb[b * 128 + tid];
        bias[128 + tid] = o1_b[tid];
        bias[256 + tid] = o2_b[tid];
    }
    CP_WAIT(1);  // Meff done (o1 may still be in flight)
    __syncthreads();

    int w = tid >> 5, l = tid & 31;
    int mw = w >> 2, nw = w & 3;  // 4x4 warps over 128x128
    int lr = l >> 2, lc = l & 3;
    int rbase = mw * 32, cbase = nw * 32;

    float acc[2][4][4];
#define ZACC() { _Pragma("unroll") for (int a_=0;a_<2;a_++) _Pragma("unroll") for (int b_=0;b_<4;b_++) _Pragma("unroll") for (int c_=0;c_<4;c_++) acc[a_][b_][c_]=0.f; }

    // phase 1: ret = Meff*x + meffb + x
    ZACC();
    gemm_h<4>(xh, 136, wA, 136, acc, rbase, cbase, lr, lc);
#pragma unroll
    for (int mi = 0; mi < 2; mi++) {
        int row = rbase + mi * 16 + lr;
#pragma unroll
        for (int ni = 0; ni < 4; ni++) {
            int col = cbase + ni * 8 + lc * 2;
            float r00 = acc[mi][ni][0] + bias[col]     + xs[row * 132 + col];
            float r01 = acc[mi][ni][1] + bias[col + 1] + xs[row * 132 + col + 1];
            float r10 = acc[mi][ni][2] + bias[col]     + xs[(row + 8) * 132 + col];
            float r11 = acc[mi][ni][3] + bias[col + 1] + xs[(row + 8) * 132 + col + 1];
            *(unsigned*)(rt + row * 136 + col) = pk2h(r00, r01);
            *(unsigned*)(rt + (row + 8) * 136 + col) = pk2h(r10, r11);
        }
    }
    CP_WAIT(0);      // o1 in wB
    __syncthreads(); // rt written; wA reads done

    // group: o2 -> wA (overlaps phase 2)
    {
        unsigned wa = smem_u32(wA);
        for (int i = tid; i < 128 * 16; i += 512) {
            int r = i >> 4, c = i & 15;
            cpasync16(wa + r * 272 + c * 16, g_o2h + r * 128 + c * 8);
        }
    }
    CP_COMMIT();

    // phase 2: h1 = gelu(o1 * ret + b1)
    ZACC();
    gemm_h<4>(rt, 136, wB, 136, acc, rbase, cbase, lr, lc);
#pragma unroll
    for (int mi = 0; mi < 2; mi++)
#pragma unroll
        for (int ni = 0; ni < 4; ni++) {
            int col = cbase + ni * 8 + lc * 2;
#pragma unroll
            for (int q = 0; q < 4; q++) {
                float h = acc[mi][ni][q] + bias[128 + col + (q & 1)];
                acc[mi][ni][q] = 0.5f * h * (1.f + erff(h * 0.70710678118654752f));
            }
        }
    __syncthreads();  // all rt reads done
#pragma unroll
    for (int mi = 0; mi < 2; mi++) {
        int row = rbase + mi * 16 + lr;
#pragma unroll
        for (int ni = 0; ni < 4; ni++) {
            int col = cbase + ni * 8 + lc * 2;
            *(unsigned*)(rt + row * 136 + col) = pk2h(acc[mi][ni][0], acc[mi][ni][1]);
            *(unsigned*)(rt + (row + 8) * 136 + col) = pk2h(acc[mi][ni][2], acc[mi][ni][3]);
        }
    }
    CP_WAIT(0);      // o2 in wA
    __syncthreads();

    // phase 3: out = o2 * h1 + b2 + x
    ZACC();
    gemm_h<4>(rt, 136, wA, 136, acc, rbase, cbase, lr, lc);
#pragma unroll
    for (int mi = 0; mi < 2; mi++) {
        int row = rbase + mi * 16 + lr;
#pragma unroll
        for (int ni = 0; ni < 4; ni++) {
            int col = cbase + ni * 8 + lc * 2;
            acc[mi][ni][0] += bias[256 + col]     + xs[row * 132 + col];
            acc[mi][ni][1] += bias[256 + col + 1] + xs[row * 132 + col + 1];
            acc[mi][ni][2] += bias[256 + col]     + xs[(row + 8) * 132 + col];
            acc[mi][ni][3] += bias[256 + col + 1] + xs[(row + 8) * 132 + col + 1];
        }
    }
    __syncthreads();  // rt/wA reads done; outs may overlay
#pragma unroll
    for (int mi = 0; mi < 2; mi++) {
        int row = rbase + mi * 16 + lr;
#pragma unroll
        for (int ni = 0; ni < 4; ni++) {
            int col = cbase + ni * 8 + lc * 2;
            outs[row * 129 + col]           = acc[mi][ni][0];
            outs[row * 129 + col + 1]       = acc[mi][ni][1];
            outs[(row + 8) * 129 + col]     = acc[mi][ni][2];
            outs[(row + 8) * 129 + col + 1] = acc[mi][ni][3];
        }
    }
    __syncthreads();

    // coalesced transposed store
    float* ob = out + (size_t)b * CCH * NTOK + n0;
    for (int i = tid; i < 128 * 128; i += 512) {
        int c = i >> 7, t = i & 127;
        ob[(size_t)c * NTOK + t] = outs[t * 129 + c];
    }
}

// ---------------- launch ----------------
extern "C" void kernel_launch(void* const* d_in, const int* in_sizes, int n_in,
                              void* d_out, int out_size) {
    const float* x     = (const float*)d_in[0];
    const float* qkv_w = (const float*)d_in[1];
    const float* qkv_b = (const float*)d_in[2];
    const float* o1_w  = (const float*)d_in[3];
    const float* o1_b  = (const float*)d_in[4];
    const float* o2_w  = (const float*)d_in[5];
    const float* o2_b  = (const float*)d_in[6];
    const float* kln_w = (const float*)d_in[7];
    const float* kln_b = (const float*)d_in[8];
    const float* vln_w = (const float*)d_in[9];
    const float* vln_b = (const float*)d_in[10];
    float* out = (float*)d_out;

    cudaFuncSetAttribute(kv_kernel, cudaFuncAttributeMaxDynamicSharedMemorySize, KV_SMEM);
    cudaFuncSetAttribute(main_kernel, cudaFuncAttributeMaxDynamicSharedMemorySize, K4_SMEM);

    prep_kernel<<<128, 256>>>(qkv_w, o1_w, o2_w);

    dim3 g2(NTOK / (128 * KV_TILES), BATCH);
    kv_kernel<<<g2, 512, KV_SMEM>>>(x, qkv_b, kln_w, kln_b, vln_w, vln_b);

    compose_kernel<<<BATCH, 128>>>(qkv_w, qkv_b);

    dim3 g4(NTOK / 128, BATCH);
    main_kernel<<<g4, 512, K4_SMEM>>>(x, o1_b, o2_b, out);
}

// round 4
// speedup vs baseline: 2.1282x; 1.0259x over previous
#include <cuda_runtime.h>
#include <cuda_fp16.h>

#define BATCH 8
#define CCH   128
#define NTOK  16384
#define HEADS 8
#define HD    16
#define LN_EPS 1e-5f

// ---------------- device scratch ----------------
__device__ float  g_kv[BATCH * HEADS * HD * HD];
__device__ __half g_wkv[256 * 128];
__device__ __half g_o1h[128 * 128];
__device__ __half g_o2h[128 * 128];
__device__ __half g_meff[BATCH * 128 * 128];
__device__ float  g_meffb[BATCH * 128];

// ---------------- helpers ----------------
__device__ __forceinline__ unsigned pk2h(float a, float b) {
    __half2 h = __floats2half2_rn(a, b);
    return *reinterpret_cast<unsigned*>(&h);
}

__device__ __forceinline__ void mma16816h(float* c, const unsigned* a, const unsigned* b) {
    asm volatile(
        "mma.sync.aligned.m16n8k16.row.col.f32.f16.f16.f32 "
        "{%0,%1,%2,%3}, {%4,%5,%6,%7}, {%8,%9}, {%0,%1,%2,%3};\n"
        : "+f"(c[0]), "+f"(c[1]), "+f"(c[2]), "+f"(c[3])
        : "r"(a[0]), "r"(a[1]), "r"(a[2]), "r"(a[3]), "r"(b[0]), "r"(b[1]));
}

__device__ __forceinline__ unsigned smem_u32(const void* p) {
    return (unsigned)__cvta_generic_to_shared(p);
}

__device__ __forceinline__ void ldsm4(unsigned& r0, unsigned& r1, unsigned& r2, unsigned& r3,
                                      unsigned addr) {
    asm volatile("ldmatrix.sync.aligned.m8n8.x4.shared.b16 {%0,%1,%2,%3}, [%4];\n"
                 : "=r"(r0), "=r"(r1), "=r"(r2), "=r"(r3) : "r"(addr));
}

__device__ __forceinline__ void cpasync16(unsigned s, const void* g) {
    asm volatile("cp.async.cg.shared.global [%0], [%1], 16;\n" :: "r"(s), "l"(g));
}
#define CP_COMMIT() asm volatile("cp.async.commit_group;\n")
#define CP_WAIT(n)  asm volatile("cp.async.wait_group %0;\n" :: "n"(n))

// fp16 GEMM via ldmatrix: A [tokens][k] ld=lda halves, W [cout][k] ld=ldw halves, K=128.
// Warp computes rows [rbase, rbase+32) x cols [cbase, cbase+NI*8).
template <int NI>
__device__ __forceinline__ void gemm_h(const __half* __restrict__ A, int lda,
                                       const __half* __restrict__ W, int ldw,
                                       float (&acc)[2][NI][4], int rbase, int cbase,
                                       int lane) {
    // A tiles: lanes 0-7 rows 0-7 (k+0), 8-15 rows 8-15 (k+0), 16-23 rows 0-7 (k+8), 24-31 rows 8-15 (k+8)
    unsigned a_addr = smem_u32(A + (rbase + (lane & 15)) * lda + ((lane >> 4) << 3));
    // B tiles: lanes 0-7 n rows 0-7 (k+0), 8-15 n 0-7 (k+8), 16-23 n 8-15 (k+0), 24-31 n 8-15 (k+8)
    unsigned b_addr = smem_u32(W + (cbase + (lane & 7) + ((lane >> 4) << 3)) * ldw
                               + (((lane >> 3) & 1) << 3));
#pragma unroll
    for (int kc = 0; kc < 128; kc += 16) {
        unsigned a[2][4];
        ldsm4(a[0][0], a[0][1], a[0][2], a[0][3], a_addr);
        ldsm4(a[1][0], a[1][1], a[1][2], a[1][3], a_addr + 16 * lda * 2);
#pragma unroll
        for (int nj = 0; nj < NI / 2; nj++) {
            unsigned b0, b1, b2, b3;
            ldsm4(b0, b1, b2, b3, b_addr + nj * 16 * ldw * 2);
            unsigned bh0[2] = {b0, b1}, bh1[2] = {b2, b3};
            mma16816h(acc[0][2 * nj],     a[0], bh0);
            mma16816h(acc[1][2 * nj],     a[1], bh0);
            mma16816h(acc[0][2 * nj + 1], a[0], bh1);
            mma16816h(acc[1][2 * nj + 1], a[1], bh1);
        }
        a_addr += 32;  // 16 halves
        b_addr += 32;
    }
}

// ---------------- kernel 0: weight prep ----------------
__global__ void prep_kernel(const float* __restrict__ qkv_w,
                            const float* __restrict__ o1_w,
                            const float* __restrict__ o2_w) {
    int idx = blockIdx.x * blockDim.x + threadIdx.x;
    int nthr = gridDim.x * blockDim.x;
    for (int i = idx; i < BATCH * HEADS * HD * HD; i += nthr) g_kv[i] = 0.f;
    for (int i = idx; i < 256 * 128; i += nthr) {
        int r = i >> 7, c = i & 127;
        int h = r >> 5, j = r & 31;
        int src = (j < 16) ? (48 * h + 16 + j) : (48 * h + 32 + (j - 16));
        g_wkv[i] = __float2half_rn(qkv_w[src * 128 + c]);
    }
    for (int i = idx; i < 128 * 128; i += nthr) {
        g_o1h[i] = __float2half_rn(o1_w[i]);
        g_o2h[i] = __float2half_rn(o2_w[i]);
    }
}

// ---------------- kernel 1: k,v projection + register-LN + kv via MMA ----------------
// 512 threads, 2 tiles of 128 tokens per block. grid (NTOK/256, BATCH).
#define KV_TILES 2
#define KV_AS_OFF 0
#define KV_AS_SZ  (128 * 136 * 2)
#define KV_WT_OFF (KV_AS_OFF + KV_AS_SZ)
#define KV_WT_SZ  (256 * 136 * 2)
#define KV_KT_OFF (KV_WT_OFF + KV_WT_SZ)
#define KV_KT_SZ  (128 * 136 * 2)
#define KV_VT_OFF (KV_KT_OFF + KV_KT_SZ)
#define KV_VT_SZ  (128 * 136 * 2)
#define KV_LNW_OFF (KV_VT_OFF + KV_VT_SZ)
#define KV_LNB_OFF (KV_LNW_OFF + 256 * 4)
#define KV_QB_OFF  (KV_LNB_OFF + 256 * 4)
#define KV_SMEM    (KV_QB_OFF + 256 * 4)

__global__ void __launch_bounds__(512, 1) kv_kernel(const float* __restrict__ x,
                                                    const float* __restrict__ qkv_b,
                                                    const float* __restrict__ kln_w,
                                                    const float* __restrict__ kln_b,
                                                    const float* __restrict__ vln_w,
                                                    const float* __restrict__ vln_b) {
    extern __shared__ char smem[];
    __half* As = (__half*)(smem + KV_AS_OFF);
    __half* Wt = (__half*)(smem + KV_WT_OFF);
    __half* kT = (__half*)(smem + KV_KT_OFF);
    __half* vT = (__half*)(smem + KV_VT_OFF);
    float* lnw = (float*)(smem + KV_LNW_OFF);
    float* lnb = (float*)(smem + KV_LNB_OFF);
    float* qb  = (float*)(smem + KV_QB_OFF);

    int tid = threadIdx.x;
    int b = blockIdx.y;
    const float* xb = x + (size_t)b * CCH * NTOK;

    // per-block constants: Wt via cp.async
    {
        unsigned wt = smem_u32(Wt);
        for (int i = tid; i < 256 * 16; i += 512) {
            int r = i >> 4, c = i & 15;
            cpasync16(wt + r * 272 + c * 16, g_wkv + r * 128 + c * 8);
        }
        CP_COMMIT();
        if (tid < 256) {
            int h = tid >> 5, j = tid & 31;
            int isv = (j >= 16), d = j & 15;
            int src_r = (j < 16) ? (48 * h + 16 + j) : (48 * h + 32 + (j - 16));
            qb[tid] = qkv_b[src_r];
            lnw[tid] = (isv ? vln_w : kln_w)[h * 16 + d];
            lnb[tid] = (isv ? vln_b : kln_b)[h * 16 + d];
        }
    }

    int w = tid >> 5, l = tid & 31;
    int mw = w >> 2, nw = w & 3;   // 4 x 4 warps over 128 tok x 256 out
    int lr = l >> 2, lc = l & 3;

    // per-warp kv accumulators: head = w>>1, token-half = w&1
    int hh = w >> 1, th = w & 1;
    float acc2[2][4];
#pragma unroll
    for (int e = 0; e < 2; e++)
#pragma unroll
        for (int q = 0; q < 4; q++) acc2[e][q] = 0.f;

    for (int tile = 0; tile < KV_TILES; tile++) {
        int n0 = (blockIdx.x * KV_TILES + tile) * 128;

        // x tile -> fp16 (coalesced global read)
        for (int i = tid; i < 128 * 128; i += 512) {
            int t = i & 127, c = i >> 7;
            As[t * 136 + c] = __float2half_rn(xb[(size_t)c * NTOK + n0 + t]);
        }
        if (tile == 0) CP_WAIT(0);
        __syncthreads();

        float acc[2][8][4];
#pragma unroll
        for (int a_ = 0; a_ < 2; a_++)
#pragma unroll
            for (int b_ = 0; b_ < 8; b_++)
#pragma unroll
                for (int c_ = 0; c_ < 4; c_++) acc[a_][b_][c_] = 0.f;

        gemm_h<8>(As, 136, Wt, 136, acc, mw * 32, nw * 64, l);

        // bias add
#pragma unroll
        for (int mi = 0; mi < 2; mi++)
#pragma unroll
            for (int ni = 0; ni < 8; ni++) {
                int col = nw * 64 + ni * 8 + lc * 2;
                acc[mi][ni][0] += qb[col];
                acc[mi][ni][1] += qb[col + 1];
                acc[mi][ni][2] += qb[col];
                acc[mi][ni][3] += qb[col + 1];
            }

        // register LayerNorm per 16-wide group (ddof=1, eps on std) + transposed fp16 write
#pragma unroll
        for (int g = 0; g < 4; g++) {
            int hg = 2 * nw + (g >> 1);
            int isv = g & 1;
            __half* dstT = isv ? vT : kT;
#pragma unroll
            for (int mi = 0; mi < 2; mi++)
#pragma unroll
                for (int rh = 0; rh < 2; rh++) {
                    float v0 = acc[mi][2 * g][rh * 2];
                    float v1 = acc[mi][2 * g][rh * 2 + 1];
                    float v2 = acc[mi][2 * g + 1][rh * 2];
                    float v3 = acc[mi][2 * g + 1][rh * 2 + 1];
                    float s = v0 + v1 + v2 + v3;
                    float ss = v0 * v0 + v1 * v1 + v2 * v2 + v3 * v3;
                    s  += __shfl_xor_sync(0xffffffffu, s, 1);
                    ss += __shfl_xor_sync(0xffffffffu, ss, 1);
                    s  += __shfl_xor_sync(0xffffffffu, s, 2);
                    ss += __shfl_xor_sync(0xffffffffu, ss, 2);
                    float mean = s * (1.f / 16.f);
                    float var = (ss - 16.f * mean * mean) * (1.f / 15.f);
                    var = fmaxf(var, 0.f);
                    float inv = 1.f / (sqrtf(var) + LN_EPS);
                    int t = mw * 32 + mi * 16 + rh * 8 + lr;
                    int c0 = nw * 64 + g * 16 + lc * 2;
                    int c1 = c0 + 8;
                    int d0 = lc * 2, d1 = 8 + lc * 2;
                    float n0v = lnw[c0] * ((v0 - mean) * inv) + lnb[c0];
                    float n1v = lnw[c0 + 1] * ((v1 - mean) * inv) + lnb[c0 + 1];
                    float n2v = lnw[c1] * ((v2 - mean) * inv) + lnb[c1];
                    float n3v = lnw[c1 + 1] * ((v3 - mean) * inv) + lnb[c1 + 1];
                    dstT[(hg * 16 + d0) * 136 + t]     = __float2half_rn(n0v);
                    dstT[(hg * 16 + d0 + 1) * 136 + t] = __float2half_rn(n1v);
                    dstT[(hg * 16 + d1) * 136 + t]     = __float2half_rn(n2v);
                    dstT[(hg * 16 + d1 + 1) * 136 + t] = __float2half_rn(n3v);
                }
        }
        __syncthreads();

        // per-head kv outer product: warp (hh, th) does C[d][e] += sum_t kT[d][t]*vT[e][t]
#pragma unroll
        for (int tcc = 0; tcc < 4; tcc++) {
            int tc = th * 64 + tcc * 16;
            unsigned a[4];
            const __half* pa = kT + (hh * 16 + lr) * 136 + tc + lc * 2;
            a[0] = *(const unsigned*)pa;
            a[1] = *(const unsigned*)(pa + 8 * 136);
            a[2] = *(const unsigned*)(pa + 8);
            a[3] = *(const unsigned*)(pa + 8 * 136 + 8);
#pragma unroll
            for (int eh = 0; eh < 2; eh++) {
                const __half* pb = vT + (hh * 16 + eh * 8 + lr) * 136 + tc + lc * 2;
                unsigned bb[2] = {*(const unsigned*)pb, *(const unsigned*)(pb + 8)};
                mma16816h(acc2[eh], a, bb);
            }
        }
        __syncthreads();  // kT/vT reads done before next tile rewrites
    }

    // flush
    float* base = g_kv + (size_t)(b * HEADS + hh) * HD * HD;
#pragma unroll
    for (int eh = 0; eh < 2; eh++) {
        int e0 = eh * 8 + lc * 2;
        atomicAdd(base + lr * 16 + e0,           acc2[eh][0]);
        atomicAdd(base + lr * 16 + e0 + 1,       acc2[eh][1]);
        atomicAdd(base + (lr + 8) * 16 + e0,     acc2[eh][2]);
        atomicAdd(base + (lr + 8) * 16 + e0 + 1, acc2[eh][3]);
    }
}

// ---------------- kernel 2: compose Meff_b = Wq o kv / N ----------------
__global__ void compose_kernel(const float* __restrict__ qkv_w, const float* __restrict__ qkv_b) {
    __shared__ float kvs[HEADS * HD * HD];
    int b = blockIdx.x, tid = threadIdx.x;  // 128 threads
    for (int i = tid; i < HEADS * HD * HD; i += 128)
        kvs[i] = g_kv[b * HEADS * HD * HD + i] * (1.f / (float)NTOK);
    __syncthreads();
    {
        int h = tid >> 4, e = tid & 15;
        float s = 0.f;
#pragma unroll
        for (int d = 0; d < 16; d++) s += qkv_b[48 * h + d] * kvs[(h * 16 + d) * 16 + e];
        g_meffb[b * 128 + tid] = s;
    }
    for (int co = 0; co < 128; co++) {
        int h = co >> 4, e = co & 15;
        float s = 0.f;
#pragma unroll
        for (int d = 0; d < 16; d++)
            s += qkv_w[(48 * h + d) * 128 + tid] * kvs[(h * 16 + d) * 16 + e];
        g_meff[(b * 128 + co) * 128 + tid] = __float2half_rn(s);
    }
}

// ---------------- kernel 3: fused av + residual + o1 + gelu + o2 + residual ----------------
// 512 threads, 128 tokens/block. All GEMMs plain fp16 via ldmatrix.
#define K4_XS_OFF 0
#define K4_XS_SZ  (128 * 132 * 4)
#define K4_XH_OFF (K4_XS_OFF + K4_XS_SZ)
#define K4_H_SZ   (128 * 136 * 2)
#define K4_RT_OFF (K4_XH_OFF + K4_H_SZ)
#define K4_WA_OFF (K4_RT_OFF + K4_H_SZ)
#define K4_WB_OFF (K4_WA_OFF + K4_H_SZ)
#define K4_B_OFF  (K4_WB_OFF + K4_H_SZ)
#define K4_SMEM   (K4_B_OFF + 3 * 128 * 4)

__global__ void __launch_bounds__(512, 1) main_kernel(const float* __restrict__ x,
                                                      const float* __restrict__ o1_b,
                                                      const float* __restrict__ o2_b,
                                                      float* __restrict__ out) {
    extern __shared__ char smem[];
    float* xs = (float*)(smem + K4_XS_OFF);
    __half* xh = (__half*)(smem + K4_XH_OFF);
    __half* rt = (__half*)(smem + K4_RT_OFF);
    __half* wA = (__half*)(smem + K4_WA_OFF);
    __half* wB = (__half*)(smem + K4_WB_OFF);
    float* outs = (float*)(smem + K4_RT_OFF);  // overlay rt+wA after phase3
    float* bias = (float*)(smem + K4_B_OFF);

    int tid = threadIdx.x;
    int b = blockIdx.y;
    int n0 = blockIdx.x * 128;
    const float* xb = x + (size_t)b * CCH * NTOK;

    // cp.async: group 0 = Meff -> wA
    {
        unsigned wa = smem_u32(wA);
        const __half* msrc = g_meff + (size_t)b * 128 * 128;
        for (int i = tid; i < 128 * 16; i += 512) {
            int r = i >> 4, c = i & 15;
            cpasync16(wa + r * 272 + c * 16, msrc + r * 128 + c * 8);
        }
    }
    CP_COMMIT();
    // group 1 = o1 -> wB (overlaps phase 1)
    {
        unsigned wb = smem_u32(wB);
        for (int i = tid; i < 128 * 16; i += 512) {
            int r = i >> 4, c = i & 15;
            cpasync16(wb + r * 272 + c * 16, g_o1h + r * 128 + c * 8);
        }
    }
    CP_COMMIT();

    // x tile: fp32 + fp16 copies
    for (int i = tid; i < 128 * 128; i += 512) {
        int t = i & 127, c = i >> 7;
        float v = xb[(size_t)c * NTOK + n0 + t];
        xs[t * 132 + c] = v;
        xh[t * 136 + c] = __float2half_rn(v);
    }
    if (tid < 128) {
        bias[tid] = g_meffb[b * 128 + tid];
        bias[128 + tid] = o1_b[tid];
        bias[256 + tid] = o2_b[tid];
    }
    CP_WAIT(1);  // Meff done (o1 may still be in flight)
    __syncthreads();

    int w = tid >> 5, l = tid & 31;
    int mw = w >> 2, nw = w & 3;  // 4x4 warps over 128x128
    int lr = l >> 2, lc = l & 3;
    int rbase = mw * 32, cbase = nw * 32;

    float acc[2][4][4];
#define ZACC() { _Pragma("unroll") for (int a_=0;a_<2;a_++) _Pragma("unroll") for (int b_=0;b_<4;b_++) _Pragma("unroll") for (int c_=0;c_<4;c_++) acc[a_][b_][c_]=0.f; }

    // phase 1: ret = Meff*x + meffb + x
    ZACC();
    gemm_h<4>(xh, 136, wA, 136, acc, rbase, cbase, l);
#pragma unroll
    for (int mi = 0; mi < 2; mi++) {
        int row = rbase + mi * 16 + lr;
#pragma unroll
        for (int ni = 0; ni < 4; ni++) {
            int col = cbase + ni * 8 + lc * 2;
            float r00 = acc[mi][ni][0] + bias[col]     + xs[row * 132 + col];
            float r01 = acc[mi][ni][1] + bias[col + 1] + xs[row * 132 + col + 1];
            float r10 = acc[mi][ni][2] + bias[col]     + xs[(row + 8) * 132 + col];
            float r11 = acc[mi][ni][3] + bias[col + 1] + xs[(row + 8) * 132 + col + 1];
            *(unsigned*)(rt + row * 136 + col) = pk2h(r00, r01);
            *(unsigned*)(rt + (row + 8) * 136 + col) = pk2h(r10, r11);
        }
    }
    CP_WAIT(0);      // o1 in wB
    __syncthreads(); // rt written; wA reads done

    // group: o2 -> wA (overlaps phase 2)
    {
        unsigned wa = smem_u32(wA);
        for (int i = tid; i < 128 * 16; i += 512) {
            int r = i >> 4, c = i & 15;
            cpasync16(wa + r * 272 + c * 16, g_o2h + r * 128 + c * 8);
        }
    }
    CP_COMMIT();

    // phase 2: h1 = gelu(o1 * ret + b1)
    ZACC();
    gemm_h<4>(rt, 136, wB, 136, acc, rbase, cbase, l);
#pragma unroll
    for (int mi = 0; mi < 2; mi++)
#pragma unroll
        for (int ni = 0; ni < 4; ni++) {
            int col = cbase + ni * 8 + lc * 2;
#pragma unroll
            for (int q = 0; q < 4; q++) {
                float h = acc[mi][ni][q] + bias[128 + col + (q & 1)];
                acc[mi][ni][q] = 0.5f * h * (1.f + erff(h * 0.70710678118654752f));
            }
        }
    __syncthreads();  // all rt reads done
#pragma unroll
    for (int mi = 0; mi < 2; mi++) {
        int row = rbase + mi * 16 + lr;
#pragma unroll
        for (int ni = 0; ni < 4; ni++) {
            int col = cbase + ni * 8 + lc * 2;
            *(unsigned*)(rt + row * 136 + col) = pk2h(acc[mi][ni][0], acc[mi][ni][1]);
            *(unsigned*)(rt + (row + 8) * 136 + col) = pk2h(acc[mi][ni][2], acc[mi][ni][3]);
        }
    }
    CP_WAIT(0);      // o2 in wA
    __syncthreads();

    // phase 3: out = o2 * h1 + b2 + x
    ZACC();
    gemm_h<4>(rt, 136, wA, 136, acc, rbase, cbase, l);
#pragma unroll
    for (int mi = 0; mi < 2; mi++) {
        int row = rbase + mi * 16 + lr;
#pragma unroll
        for (int ni = 0; ni < 4; ni++) {
            int col = cbase + ni * 8 + lc * 2;
            acc[mi][ni][0] += bias[256 + col]     + xs[row * 132 + col];
            acc[mi][ni][1] += bias[256 + col + 1] + xs[row * 132 + col + 1];
            acc[mi][ni][2] += bias[256 + col]     + xs[(row + 8) * 132 + col];
            acc[mi][ni][3] += bias[256 + col + 1] + xs[(row + 8) * 132 + col + 1];
        }
    }
    __syncthreads();  // rt/wA reads done; outs may overlay
#pragma unroll
    for (int mi = 0; mi < 2; mi++) {
        int row = rbase + mi * 16 + lr;
#pragma unroll
        for (int ni = 0; ni < 4; ni++) {
            int col = cbase + ni * 8 + lc * 2;
            outs[row * 129 + col]           = acc[mi][ni][0];
            outs[row * 129 + col + 1]       = acc[mi][ni][1];
            outs[(row + 8) * 129 + col]     = acc[mi][ni][2];
            outs[(row + 8) * 129 + col + 1] = acc[mi][ni][3];
        }
    }
    __syncthreads();

    // coalesced transposed store
    float* ob = out + (size_t)b * CCH * NTOK + n0;
    for (int i = tid; i < 128 * 128; i += 512) {
        int c = i >> 7, t = i & 127;
        ob[(size_t)c * NTOK + t] = outs[t * 129 + c];
    }
}

// ---------------- launch ----------------
extern "C" void kernel_launch(void* const* d_in, const int* in_sizes, int n_in,
                              void* d_out, int out_size) {
    const float* x     = (const float*)d_in[0];
    const float* qkv_w = (const float*)d_in[1];
    const float* qkv_b = (const float*)d_in[2];
    const float* o1_w  = (const float*)d_in[3];
    const float* o1_b  = (const float*)d_in[4];
    const float* o2_w  = (const float*)d_in[5];
    const float* o2_b  = (const float*)d_in[6];
    const float* kln_w = (const float*)d_in[7];
    const float* kln_b = (const float*)d_in[8];
    const float* vln_w = (const float*)d_in[9];
    const float* vln_b = (const float*)d_in[10];
    float* out = (float*)d_out;

    cudaFuncSetAttribute(kv_kernel, cudaFuncAttributeMaxDynamicSharedMemorySize, KV_SMEM);
    cudaFuncSetAttribute(main_kernel, cudaFuncAttributeMaxDynamicSharedMemorySize, K4_SMEM);

    prep_kernel<<<128, 256>>>(qkv_w, o1_w, o2_w);

    dim3 g2(NTOK / (128 * KV_TILES), BATCH);
    kv_kernel<<<g2, 512, KV_SMEM>>>(x, qkv_b, kln_w, kln_b, vln_w, vln_b);

    compose_kernel<<<BATCH, 128>>>(qkv_w, qkv_b);

    dim3 g4(NTOK / 128, BATCH);
    main_kernel<<<g4, 512, K4_SMEM>>>(x, o1_b, o2_b, out);
}

// round 5
// speedup vs baseline: 2.4826x; 1.1665x over previous
#include <cuda_runtime.h>
#include <cuda_fp16.h>

#define BATCH 8
#define CCH   128
#define NTOK  16384
#define HEADS 8
#define LN_EPS 1e-5f

// ---------------- device scratch ----------------
__device__ float  g_kv[BATCH * HEADS * 16 * 16];
__device__ __half g_wkv[256 * 128];
__device__ __half g_o1h[128 * 128];
__device__ __half g_o2h[128 * 128];
__device__ __half g_meff[BATCH * 128 * 128];
__device__ float  g_meffb[BATCH * 128];
__device__ __half g_x16[(size_t)BATCH * CCH * NTOK];

// ---------------- helpers ----------------
__device__ __forceinline__ unsigned pk2h(float a, float b) {
    __half2 h = __floats2half2_rn(a, b);
    return *reinterpret_cast<unsigned*>(&h);
}

__device__ __forceinline__ void mma16816h(float* c, const unsigned* a, const unsigned* b) {
    asm volatile(
        "mma.sync.aligned.m16n8k16.row.col.f32.f16.f16.f32 "
        "{%0,%1,%2,%3}, {%4,%5,%6,%7}, {%8,%9}, {%0,%1,%2,%3};\n"
        : "+f"(c[0]), "+f"(c[1]), "+f"(c[2]), "+f"(c[3])
        : "r"(a[0]), "r"(a[1]), "r"(a[2]), "r"(a[3]), "r"(b[0]), "r"(b[1]));
}

__device__ __forceinline__ unsigned smem_u32(const void* p) {
    return (unsigned)__cvta_generic_to_shared(p);
}

__device__ __forceinline__ void ldsm4(unsigned& r0, unsigned& r1, unsigned& r2, unsigned& r3,
                                      unsigned addr) {
    asm volatile("ldmatrix.sync.aligned.m8n8.x4.shared.b16 {%0,%1,%2,%3}, [%4];\n"
                 : "=r"(r0), "=r"(r1), "=r"(r2), "=r"(r3) : "r"(addr));
}

__device__ __forceinline__ void ldsm4t(unsigned& r0, unsigned& r1, unsigned& r2, unsigned& r3,
                                       unsigned addr) {
    asm volatile("ldmatrix.sync.aligned.m8n8.x4.trans.shared.b16 {%0,%1,%2,%3}, [%4];\n"
                 : "=r"(r0), "=r"(r1), "=r"(r2), "=r"(r3) : "r"(addr));
}

__device__ __forceinline__ void cpasync16(unsigned s, const void* g) {
    asm volatile("cp.async.cg.shared.global [%0], [%1], 16;\n" :: "r"(s), "l"(g));
}
#define CP_COMMIT() asm volatile("cp.async.commit_group;\n")
#define CP_WAIT(n)  asm volatile("cp.async.wait_group %0;\n" :: "n"(n))

// Output-layout GEMM: C[c_out rows][token cols] = A[c_out][k] * B[k][t].
// A: smem [rows][136], non-trans ldmatrix. B: smem [k=128][136], trans ldmatrix.
// Warp tile: 32 rows x (NI8*8) token cols. acc[mi 2][ni NI8][4]:
//   elements (row = rbase+mi*16+lr (+8), col = cbase+ni*8+2lc (+1))
template <int NI8>
__device__ __forceinline__ void gemm_t(const __half* __restrict__ A,
                                       const __half* __restrict__ B,
                                       float (&acc)[2][NI8][4], int rbase, int cbase, int lane) {
    unsigned a_addr = smem_u32(A + (rbase + (lane & 15)) * 136 + ((lane >> 4) << 3));
    unsigned b_addr = smem_u32(B + (lane & 15) * 136 + cbase + ((lane >> 4) << 3));
#pragma unroll
    for (int kc = 0; kc < 128; kc += 16) {
        unsigned a[2][4];
        ldsm4(a[0][0], a[0][1], a[0][2], a[0][3], a_addr);
        ldsm4(a[1][0], a[1][1], a[1][2], a[1][3], a_addr + 16 * 136 * 2);
#pragma unroll
        for (int g = 0; g < NI8 / 2; g++) {
            unsigned b0, b1, b2, b3;
            ldsm4t(b0, b1, b2, b3, b_addr + g * 32);
            unsigned bl[2] = {b0, b1}, bh[2] = {b2, b3};
            mma16816h(acc[0][2 * g],     a[0], bl);
            mma16816h(acc[1][2 * g],     a[1], bl);
            mma16816h(acc[0][2 * g + 1], a[0], bh);
            mma16816h(acc[1][2 * g + 1], a[1], bh);
        }
        a_addr += 32;             // k += 16 halves
        b_addr += 16 * 136 * 2;   // 16 k-rows down
    }
}

// ---------------- kernel 0: weight prep ----------------
__global__ void prep_kernel(const float* __restrict__ qkv_w,
                            const float* __restrict__ o1_w,
                            const float* __restrict__ o2_w) {
    int idx = blockIdx.x * blockDim.x + threadIdx.x;
    int nthr = gridDim.x * blockDim.x;
    for (int i = idx; i < BATCH * HEADS * 16 * 16; i += nthr) g_kv[i] = 0.f;
    for (int i = idx; i < 256 * 128; i += nthr) {
        int r = i >> 7, c = i & 127;
        int h = r >> 5, j = r & 31;
        int src = (j < 16) ? (48 * h + 16 + j) : (48 * h + 32 + (j - 16));
        g_wkv[i] = __float2half_rn(qkv_w[src * 128 + c]);
    }
    for (int i = idx; i < 128 * 128; i += nthr) {
        g_o1h[i] = __float2half_rn(o1_w[i]);
        g_o2h[i] = __float2half_rn(o2_w[i]);
    }
}

// ---------------- kernel 0b: x -> fp16 ----------------
__global__ void x16_kernel(const float* __restrict__ x) {
    size_t i = ((size_t)blockIdx.x * 256 + threadIdx.x) * 4;
    float4 v = *(const float4*)(x + i);
    __half2 h0 = __floats2half2_rn(v.x, v.y);
    __half2 h1 = __floats2half2_rn(v.z, v.w);
    uint2 u;
    u.x = *reinterpret_cast<unsigned*>(&h0);
    u.y = *reinterpret_cast<unsigned*>(&h1);
    *(uint2*)(g_x16 + i) = u;
}

// ---------------- kernel 1: k,v projection + register-LN + kv via MMA ----------------
// 512 threads, 2 token tiles of 128/block, double-buffered x tiles.
#define KVS_WT   0
#define KVS_XT0  (256 * 136 * 2)
#define KVS_XT1  (KVS_XT0 + 128 * 136 * 2)
#define KVS_KT   (KVS_XT1 + 128 * 136 * 2)
#define KVS_VT   (KVS_KT + 128 * 136 * 2)
#define KVS_QB   (KVS_VT + 128 * 136 * 2)
#define KVS_SMEM (KVS_QB + 256 * 4)

__global__ void __launch_bounds__(512, 1) kv_kernel(const float* __restrict__ qkv_b,
                                                    const float* __restrict__ kln_w,
                                                    const float* __restrict__ kln_b,
                                                    const float* __restrict__ vln_w,
                                                    const float* __restrict__ vln_b) {
    extern __shared__ char smem[];
    __half* Wt = (__half*)(smem + KVS_WT);
    __half* xt0 = (__half*)(smem + KVS_XT0);
    __half* xt1 = (__half*)(smem + KVS_XT1);
    __half* kT = (__half*)(smem + KVS_KT);
    __half* vT = (__half*)(smem + KVS_VT);
    float* qb = (float*)(smem + KVS_QB);

    int tid = threadIdx.x;
    int b = blockIdx.y;

    // prefetch weights (group 0)
    {
        unsigned wt = smem_u32(Wt);
        for (int i = tid; i < 256 * 16; i += 512) {
            int r = i >> 4, c = i & 15;
            cpasync16(wt + r * 272 + c * 16, g_wkv + r * 128 + c * 8);
        }
        CP_COMMIT();
    }
    // prefetch x tiles (groups 1, 2)
    const __half* xsrc = g_x16 + (size_t)b * CCH * NTOK;
    {
        unsigned xa = smem_u32(xt0);
        int n0 = blockIdx.x * 256;
        for (int i = tid; i < 128 * 16; i += 512) {
            int r = i >> 4, c = i & 15;
            cpasync16(xa + r * 272 + c * 16, xsrc + (size_t)r * NTOK + n0 + c * 8);
        }
        CP_COMMIT();
        unsigned xb2 = smem_u32(xt1);
        for (int i = tid; i < 128 * 16; i += 512) {
            int r = i >> 4, c = i & 15;
            cpasync16(xb2 + r * 272 + c * 16, xsrc + (size_t)r * NTOK + n0 + 128 + c * 8);
        }
        CP_COMMIT();
    }
    if (tid < 256) {
        int h = tid >> 5, j = tid & 31;
        int src_r = (j < 16) ? (48 * h + 16 + j) : (48 * h + 32 + (j - 16));
        qb[tid] = qkv_b[src_r];
    }

    int w = tid >> 5, l = tid & 31;
    int lr = l >> 2, lc = l & 3;
    int mw = w >> 1;      // cout group (head), 0..7
    int nw = w & 1;       // token half
    int rbase = mw * 32, cbase = nw * 64;

    // LN params in registers: [mi(k/v)][row lr / lr+8]
    float lw[2][2], lb[2][2];
    lw[0][0] = kln_w[mw * 16 + lr];     lw[0][1] = kln_w[mw * 16 + lr + 8];
    lb[0][0] = kln_b[mw * 16 + lr];     lb[0][1] = kln_b[mw * 16 + lr + 8];
    lw[1][0] = vln_w[mw * 16 + lr];     lw[1][1] = vln_w[mw * 16 + lr + 8];
    lb[1][0] = vln_b[mw * 16 + lr];     lb[1][1] = vln_b[mw * 16 + lr + 8];

    float acc2[2][4];
#pragma unroll
    for (int e = 0; e < 2; e++)
#pragma unroll
        for (int q = 0; q < 4; q++) acc2[e][q] = 0.f;

#pragma unroll
    for (int tile = 0; tile < 2; tile++) {
        if (tile == 0) { CP_WAIT(1); } else { CP_WAIT(0); }
        __syncthreads();
        const __half* xt = tile ? xt1 : xt0;

        float acc[2][8][4];
#pragma unroll
        for (int a_ = 0; a_ < 2; a_++)
#pragma unroll
            for (int b_ = 0; b_ < 8; b_++)
#pragma unroll
                for (int c_ = 0; c_ < 4; c_++) acc[a_][b_][c_] = 0.f;

        gemm_t<8>(Wt, xt, acc, rbase, cbase, l);

        // bias (per output row)
        float q0 = qb[rbase + lr],      q1 = qb[rbase + lr + 8];
        float q2 = qb[rbase + 16 + lr], q3 = qb[rbase + 16 + lr + 8];
#pragma unroll
        for (int ni = 0; ni < 8; ni++) {
            acc[0][ni][0] += q0; acc[0][ni][1] += q0;
            acc[0][ni][2] += q1; acc[0][ni][3] += q1;
            acc[1][ni][0] += q2; acc[1][ni][1] += q2;
            acc[1][ni][2] += q3; acc[1][ni][3] += q3;
        }

        // register LayerNorm over d=16 (rows lr/lr+8 across 8 lanes), ddof=1, eps on std
#pragma unroll
        for (int mi = 0; mi < 2; mi++) {
            __half* dst = mi ? vT : kT;
#pragma unroll
            for (int ni = 0; ni < 8; ni++) {
                float* c = acc[mi][ni];
                float sa = c[0] + c[2], sb = c[1] + c[3];
                float ssa = c[0] * c[0] + c[2] * c[2];
                float ssb = c[1] * c[1] + c[3] * c[3];
#pragma unroll
                for (int m = 4; m <= 16; m <<= 1) {
                    sa += __shfl_xor_sync(0xffffffffu, sa, m);
                    sb += __shfl_xor_sync(0xffffffffu, sb, m);
                    ssa += __shfl_xor_sync(0xffffffffu, ssa, m);
                    ssb += __shfl_xor_sync(0xffffffffu, ssb, m);
                }
                float ma = sa * (1.f / 16.f);
                float va = fmaxf((ssa - 16.f * ma * ma) * (1.f / 15.f), 0.f);
                float ia = 1.f / (sqrtf(va) + LN_EPS);
                float mb = sb * (1.f / 16.f);
                float vb = fmaxf((ssb - 16.f * mb * mb) * (1.f / 15.f), 0.f);
                float ib = 1.f / (sqrtf(vb) + LN_EPS);
                float n0 = lw[mi][0] * ((c[0] - ma) * ia) + lb[mi][0];
                float n1 = lw[mi][0] * ((c[1] - mb) * ib) + lb[mi][0];
                float n2 = lw[mi][1] * ((c[2] - ma) * ia) + lb[mi][1];
                float n3 = lw[mi][1] * ((c[3] - mb) * ib) + lb[mi][1];
                int row = mw * 16 + lr;
                int col = cbase + ni * 8 + lc * 2;
                *(unsigned*)(dst + row * 136 + col)       = pk2h(n0, n1);
                *(unsigned*)(dst + (row + 8) * 136 + col) = pk2h(n2, n3);
            }
        }
        __syncthreads();

        // per-head kv outer product: warp (head mw, half nw): C[d][e] += sum_t kT[d][t]*vT[e][t]
#pragma unroll
        for (int tcc = 0; tcc < 4; tcc++) {
            int tc = nw * 64 + tcc * 16;
            unsigned a[4];
            const __half* pa = kT + (mw * 16 + lr) * 136 + tc + lc * 2;
            a[0] = *(const unsigned*)pa;
            a[1] = *(const unsigned*)(pa + 8 * 136);
            a[2] = *(const unsigned*)(pa + 8);
            a[3] = *(const unsigned*)(pa + 8 * 136 + 8);
#pragma unroll
            for (int eh = 0; eh < 2; eh++) {
                const __half* pb = vT + (mw * 16 + eh * 8 + lr) * 136 + tc + lc * 2;
                unsigned bb[2] = {*(const unsigned*)pb, *(const unsigned*)(pb + 8)};
                mma16816h(acc2[eh], a, bb);
            }
        }
        __syncthreads();
    }

    // flush
    float* base = g_kv + (size_t)(b * HEADS + mw) * 256;
#pragma unroll
    for (int eh = 0; eh < 2; eh++) {
        int e0 = eh * 8 + lc * 2;
        atomicAdd(base + lr * 16 + e0,           acc2[eh][0]);
        atomicAdd(base + lr * 16 + e0 + 1,       acc2[eh][1]);
        atomicAdd(base + (lr + 8) * 16 + e0,     acc2[eh][2]);
        atomicAdd(base + (lr + 8) * 16 + e0 + 1, acc2[eh][3]);
    }
}

// ---------------- kernel 2: compose Meff_b = Wq o kv / N ----------------
__global__ void compose_kernel(const float* __restrict__ qkv_w, const float* __restrict__ qkv_b) {
    __shared__ float kvs[HEADS * 256];
    int b = blockIdx.x, tid = threadIdx.x;  // 128 threads
    for (int i = tid; i < HEADS * 256; i += 128)
        kvs[i] = g_kv[b * HEADS * 256 + i] * (1.f / (float)NTOK);
    __syncthreads();
    {
        int h = tid >> 4, e = tid & 15;
        float s = 0.f;
#pragma unroll
        for (int d = 0; d < 16; d++) s += qkv_b[48 * h + d] * kvs[(h * 16 + d) * 16 + e];
        g_meffb[b * 128 + tid] = s;
    }
    for (int co = 0; co < 128; co++) {
        int h = co >> 4, e = co & 15;
        float s = 0.f;
#pragma unroll
        for (int d = 0; d < 16; d++)
            s += qkv_w[(48 * h + d) * 128 + tid] * kvs[(h * 16 + d) * 16 + e];
        g_meff[(b * 128 + co) * 128 + tid] = __float2half_rn(s);
    }
}

// ---------------- kernel 3: fused av + residual + o1 + gelu + o2 + residual ----------------
// 256 threads, 2 CTAs/SM, 128 tokens/block. Output layout (c_out rows x token cols).
#define M4_BUFA 0                         // x16 tile, then o2
#define M4_BUFB (128 * 136 * 2)           // Meff, then o1
#define M4_RT   (2 * 128 * 136 * 2)
#define M4_BIAS (3 * 128 * 136 * 2)
#define M4_SMEM (M4_BIAS + 3 * 128 * 4)

__global__ void __launch_bounds__(256, 2) main_kernel(const float* __restrict__ x,
                                                      const float* __restrict__ o1_b,
                                                      const float* __restrict__ o2_b,
                                                      float* __restrict__ out) {
    extern __shared__ char smem[];
    __half* bufA = (__half*)(smem + M4_BUFA);
    __half* bufB = (__half*)(smem + M4_BUFB);
    __half* rt = (__half*)(smem + M4_RT);
    float* bias = (float*)(smem + M4_BIAS);

    int tid = threadIdx.x;
    int b = blockIdx.y;
    int n0 = blockIdx.x * 128;

    // prefetch Meff -> bufB, x16 tile -> bufA (one group)
    {
        unsigned ba = smem_u32(bufA), bb = smem_u32(bufB);
        const __half* msrc = g_meff + (size_t)b * 128 * 128;
        const __half* xsrc = g_x16 + (size_t)b * CCH * NTOK + n0;
        for (int i = tid; i < 128 * 16; i += 256) {
            int r = i >> 4, c = i & 15;
            cpasync16(bb + r * 272 + c * 16, msrc + r * 128 + c * 8);
            cpasync16(ba + r * 272 + c * 16, xsrc + (size_t)r * NTOK + c * 8);
        }
        CP_COMMIT();
    }
    if (tid < 128) {
        bias[tid] = g_meffb[b * 128 + tid];
        bias[128 + tid] = o1_b[tid];
        bias[256 + tid] = o2_b[tid];
    }
    CP_WAIT(0);
    __syncthreads();

    int w = tid >> 5, l = tid & 31;
    int lr = l >> 2, lc = l & 3;
    int mw = w >> 1, nw = w & 1;  // 4 cout groups x 2 token halves
    int rbase = mw * 32, cbase = nw * 64;

    float acc[2][8][4];
#define ZACC() { _Pragma("unroll") for (int a_=0;a_<2;a_++) _Pragma("unroll") for (int b_=0;b_<8;b_++) _Pragma("unroll") for (int c_=0;c_<4;c_++) acc[a_][b_][c_]=0.f; }

    // ---- phase 1: rt = Meff*x + meffb + x ----
    ZACC();
    gemm_t<8>(bufB, bufA, acc, rbase, cbase, l);
    {
        float bm0 = bias[rbase + lr],      bm1 = bias[rbase + lr + 8];
        float bm2 = bias[rbase + 16 + lr], bm3 = bias[rbase + 16 + lr + 8];
#pragma unroll
        for (int mi = 0; mi < 2; mi++) {
            int row = rbase + mi * 16 + lr;
            float ba0 = mi ? bm2 : bm0, ba1 = mi ? bm3 : bm1;
#pragma unroll
            for (int ni = 0; ni < 8; ni++) {
                int col = cbase + ni * 8 + lc * 2;
                __half2 xv0 = *(const __half2*)(bufA + row * 136 + col);
                __half2 xv1 = *(const __half2*)(bufA + (row + 8) * 136 + col);
                float2 f0 = __half22float2(xv0), f1 = __half22float2(xv1);
                float r00 = acc[mi][ni][0] + ba0 + f0.x;
                float r01 = acc[mi][ni][1] + ba0 + f0.y;
                float r10 = acc[mi][ni][2] + ba1 + f1.x;
                float r11 = acc[mi][ni][3] + ba1 + f1.y;
                *(unsigned*)(rt + row * 136 + col)       = pk2h(r00, r01);
                *(unsigned*)(rt + (row + 8) * 136 + col) = pk2h(r10, r11);
            }
        }
    }
    __syncthreads();  // rt written; bufA/bufB reads done

    // prefetch o1 -> bufB (group), o2 -> bufA (group)
    {
        unsigned bb = smem_u32(bufB);
        for (int i = tid; i < 128 * 16; i += 256) {
            int r = i >> 4, c = i & 15;
            cpasync16(bb + r * 272 + c * 16, g_o1h + r * 128 + c * 8);
        }
        CP_COMMIT();
        unsigned ba = smem_u32(bufA);
        for (int i = tid; i < 128 * 16; i += 256) {
            int r = i >> 4, c = i & 15;
            cpasync16(ba + r * 272 + c * 16, g_o2h + r * 128 + c * 8);
        }
        CP_COMMIT();
    }
    CP_WAIT(1);  // o1 ready
    __syncthreads();

    // ---- phase 2: h1 = gelu(o1 * rt + b1) ----
    ZACC();
    gemm_t<8>(bufB, rt, acc, rbase, cbase, l);
    {
        float b10 = bias[128 + rbase + lr],      b11 = bias[128 + rbase + lr + 8];
        float b12 = bias[128 + rbase + 16 + lr], b13 = bias[128 + rbase + 16 + lr + 8];
#pragma unroll
        for (int mi = 0; mi < 2; mi++) {
            float ba0 = mi ? b12 : b10, ba1 = mi ? b13 : b11;
#pragma unroll
            for (int ni = 0; ni < 8; ni++) {
#pragma unroll
                for (int q = 0; q < 4; q++) {
                    float h = acc[mi][ni][q] + ((q < 2) ? ba0 : ba1);
                    acc[mi][ni][q] = 0.5f * h * (1.f + erff(h * 0.70710678118654752f));
                }
            }
        }
    }
    __syncthreads();  // all rt reads done before overwrite
#pragma unroll
    for (int mi = 0; mi < 2; mi++) {
        int row = rbase + mi * 16 + lr;
#pragma unroll
        for (int ni = 0; ni < 8; ni++) {
            int col = cbase + ni * 8 + lc * 2;
            *(unsigned*)(rt + row * 136 + col)       = pk2h(acc[mi][ni][0], acc[mi][ni][1]);
            *(unsigned*)(rt + (row + 8) * 136 + col) = pk2h(acc[mi][ni][2], acc[mi][ni][3]);
        }
    }
    CP_WAIT(0);  // o2 ready
    __syncthreads();

    // ---- phase 3: out = o2 * h1 + b2 + x ----
    ZACC();
    gemm_t<8>(bufA, rt, acc, rbase, cbase, l);
    {
        float b20 = bias[256 + rbase + lr],      b21 = bias[256 + rbase + lr + 8];
        float b22 = bias[256 + rbase + 16 + lr], b23 = bias[256 + rbase + 16 + lr + 8];
        const float* xb = x + (size_t)b * CCH * NTOK + n0;
        float* ob = out + (size_t)b * CCH * NTOK + n0;
#pragma unroll
        for (int mi = 0; mi < 2; mi++) {
            int row = rbase + mi * 16 + lr;
            float ba0 = mi ? b22 : b20, ba1 = mi ? b23 : b21;
#pragma unroll
            for (int ni = 0; ni < 8; ni++) {
                int col = cbase + ni * 8 + lc * 2;
                float2 xv0 = *(const float2*)(xb + (size_t)row * NTOK + col);
                float2 xv1 = *(const float2*)(xb + (size_t)(row + 8) * NTOK + col);
                float2 o0, o1v;
                o0.x = acc[mi][ni][0] + ba0 + xv0.x;
                o0.y = acc[mi][ni][1] + ba0 + xv0.y;
                o1v.x = acc[mi][ni][2] + ba1 + xv1.x;
                o1v.y = acc[mi][ni][3] + ba1 + xv1.y;
                *(float2*)(ob + (size_t)row * NTOK + col) = o0;
                *(float2*)(ob + (size_t)(row + 8) * NTOK + col) = o1v;
            }
        }
    }
}

// ---------------- launch ----------------
extern "C" void kernel_launch(void* const* d_in, const int* in_sizes, int n_in,
                              void* d_out, int out_size) {
    const float* x     = (const float*)d_in[0];
    const float* qkv_w = (const float*)d_in[1];
    const float* qkv_b = (const float*)d_in[2];
    const float* o1_w  = (const float*)d_in[3];
    const float* o1_b  = (const float*)d_in[4];
    const float* o2_w  = (const float*)d_in[5];
    const float* o2_b  = (const float*)d_in[6];
    const float* kln_w = (const float*)d_in[7];
    const float* kln_b = (const float*)d_in[8];
    const float* vln_w = (const float*)d_in[9];
    const float* vln_b = (const float*)d_in[10];
    float* out = (float*)d_out;

    cudaFuncSetAttribute(kv_kernel, cudaFuncAttributeMaxDynamicSharedMemorySize, KVS_SMEM);
    cudaFuncSetAttribute(main_kernel, cudaFuncAttributeMaxDynamicSharedMemorySize, M4_SMEM);

    prep_kernel<<<128, 256>>>(qkv_w, o1_w, o2_w);
    x16_kernel<<<(BATCH * CCH * NTOK) / 1024, 256>>>(x);

    dim3 g2(NTOK / 256, BATCH);
    kv_kernel<<<g2, 512, KVS_SMEM>>>(qkv_b, kln_w, kln_b, vln_w, vln_b);

    compose_kernel<<<BATCH, 128>>>(qkv_w, qkv_b);

    dim3 g4(NTOK / 128, BATCH);
    main_kernel<<<g4, 256, M4_SMEM>>>(x, o1_b, o2_b, out);
}

// round 6
// speedup vs baseline: 2.8543x; 1.1498x over previous
#include <cuda_runtime.h>
#include <cuda_fp16.h>

#define BATCH 8
#define CCH   128
#define NTOK  16384
#define HEADS 8
#define LN_EPS 1e-5f

// ---------------- device scratch ----------------
__device__ float  g_kv[BATCH * HEADS * 16 * 16];
__device__ __half g_wkv[256 * 128];
__device__ __half g_o1h[128 * 128];
__device__ __half g_o2h[128 * 128];
__device__ __half g_meff[BATCH * 128 * 128];
__device__ float  g_meffb[BATCH * 128];
__device__ __half g_x16[(size_t)BATCH * CCH * NTOK];

// ---------------- helpers ----------------
__device__ __forceinline__ unsigned pk2h(float a, float b) {
    __half2 h = __floats2half2_rn(a, b);
    return *reinterpret_cast<unsigned*>(&h);
}

__device__ __forceinline__ void mma16816h(float* c, const unsigned* a, const unsigned* b) {
    asm volatile(
        "mma.sync.aligned.m16n8k16.row.col.f32.f16.f16.f32 "
        "{%0,%1,%2,%3}, {%4,%5,%6,%7}, {%8,%9}, {%0,%1,%2,%3};\n"
        : "+f"(c[0]), "+f"(c[1]), "+f"(c[2]), "+f"(c[3])
        : "r"(a[0]), "r"(a[1]), "r"(a[2]), "r"(a[3]), "r"(b[0]), "r"(b[1]));
}

__device__ __forceinline__ unsigned smem_u32(const void* p) {
    return (unsigned)__cvta_generic_to_shared(p);
}

__device__ __forceinline__ void ldsm4(unsigned& r0, unsigned& r1, unsigned& r2, unsigned& r3,
                                      unsigned addr) {
    asm volatile("ldmatrix.sync.aligned.m8n8.x4.shared.b16 {%0,%1,%2,%3}, [%4];\n"
                 : "=r"(r0), "=r"(r1), "=r"(r2), "=r"(r3) : "r"(addr));
}

__device__ __forceinline__ void ldsm4t(unsigned& r0, unsigned& r1, unsigned& r2, unsigned& r3,
                                       unsigned addr) {
    asm volatile("ldmatrix.sync.aligned.m8n8.x4.trans.shared.b16 {%0,%1,%2,%3}, [%4];\n"
                 : "=r"(r0), "=r"(r1), "=r"(r2), "=r"(r3) : "r"(addr));
}

__device__ __forceinline__ void cpasync16(unsigned s, const void* g) {
    asm volatile("cp.async.cg.shared.global [%0], [%1], 16;\n" :: "r"(s), "l"(g));
}
#define CP_COMMIT() asm volatile("cp.async.commit_group;\n")
#define CP_WAIT(n)  asm volatile("cp.async.wait_group %0;\n" :: "n"(n))

// Output-layout GEMM: C[c_out rows][token cols] = A[c_out][k] * B[k][t].
template <int NI8>
__device__ __forceinline__ void gemm_t(const __half* __restrict__ A,
                                       const __half* __restrict__ B,
                                       float (&acc)[2][NI8][4], int rbase, int cbase, int lane) {
    unsigned a_addr = smem_u32(A + (rbase + (lane & 15)) * 136 + ((lane >> 4) << 3));
    unsigned b_addr = smem_u32(B + (lane & 15) * 136 + cbase + ((lane >> 4) << 3));
#pragma unroll
    for (int kc = 0; kc < 128; kc += 16) {
        unsigned a[2][4];
        ldsm4(a[0][0], a[0][1], a[0][2], a[0][3], a_addr);
        ldsm4(a[1][0], a[1][1], a[1][2], a[1][3], a_addr + 16 * 136 * 2);
#pragma unroll
        for (int g = 0; g < NI8 / 2; g++) {
            unsigned b0, b1, b2, b3;
            ldsm4t(b0, b1, b2, b3, b_addr + g * 32);
            unsigned bl[2] = {b0, b1}, bh[2] = {b2, b3};
            mma16816h(acc[0][2 * g],     a[0], bl);
            mma16816h(acc[1][2 * g],     a[1], bl);
            mma16816h(acc[0][2 * g + 1], a[0], bh);
            mma16816h(acc[1][2 * g + 1], a[1], bh);
        }
        a_addr += 32;
        b_addr += 16 * 136 * 2;
    }
}

// ---------------- kernel 0: weight prep ----------------
__global__ void prep_kernel(const float* __restrict__ qkv_w,
                            const float* __restrict__ o1_w,
                            const float* __restrict__ o2_w) {
    int idx = blockIdx.x * blockDim.x + threadIdx.x;
    int nthr = gridDim.x * blockDim.x;
    for (int i = idx; i < BATCH * HEADS * 16 * 16; i += nthr) g_kv[i] = 0.f;
    for (int i = idx; i < 256 * 128; i += nthr) {
        int r = i >> 7, c = i & 127;
        int h = r >> 5, j = r & 31;
        int src = (j < 16) ? (48 * h + 16 + j) : (48 * h + 32 + (j - 16));
        g_wkv[i] = __float2half_rn(qkv_w[src * 128 + c]);
    }
    for (int i = idx; i < 128 * 128; i += nthr) {
        g_o1h[i] = __float2half_rn(o1_w[i]);
        g_o2h[i] = __float2half_rn(o2_w[i]);
    }
}

// ---------------- kernel 0b: x -> fp16 ----------------
__global__ void x16_kernel(const float* __restrict__ x) {
    size_t i = ((size_t)blockIdx.x * 256 + threadIdx.x) * 4;
    float4 v = *(const float4*)(x + i);
    __half2 h0 = __floats2half2_rn(v.x, v.y);
    __half2 h1 = __floats2half2_rn(v.z, v.w);
    uint2 u;
    u.x = *reinterpret_cast<unsigned*>(&h0);
    u.y = *reinterpret_cast<unsigned*>(&h1);
    *(uint2*)(g_x16 + i) = u;
}

// ---------------- kernel 1: k,v projection + register-LN + kv via MMA ----------------
#define KVS_WT   0
#define KVS_XT0  (256 * 136 * 2)
#define KVS_XT1  (KVS_XT0 + 128 * 136 * 2)
#define KVS_KT   (KVS_XT1 + 128 * 136 * 2)
#define KVS_VT   (KVS_KT + 128 * 136 * 2)
#define KVS_QB   (KVS_VT + 128 * 136 * 2)
#define KVS_SMEM (KVS_QB + 256 * 4)

__global__ void __launch_bounds__(512, 1) kv_kernel(const float* __restrict__ qkv_b,
                                                    const float* __restrict__ kln_w,
                                                    const float* __restrict__ kln_b,
                                                    const float* __restrict__ vln_w,
                                                    const float* __restrict__ vln_b) {
    extern __shared__ char smem[];
    __half* Wt = (__half*)(smem + KVS_WT);
    __half* xt0 = (__half*)(smem + KVS_XT0);
    __half* xt1 = (__half*)(smem + KVS_XT1);
    __half* kT = (__half*)(smem + KVS_KT);
    __half* vT = (__half*)(smem + KVS_VT);
    float* qb = (float*)(smem + KVS_QB);

    int tid = threadIdx.x;
    int b = blockIdx.y;

    {
        unsigned wt = smem_u32(Wt);
        for (int i = tid; i < 256 * 16; i += 512) {
            int r = i >> 4, c = i & 15;
            cpasync16(wt + r * 272 + c * 16, g_wkv + r * 128 + c * 8);
        }
        CP_COMMIT();
    }
    const __half* xsrc = g_x16 + (size_t)b * CCH * NTOK;
    {
        unsigned xa = smem_u32(xt0);
        int n0 = blockIdx.x * 256;
        for (int i = tid; i < 128 * 16; i += 512) {
            int r = i >> 4, c = i & 15;
            cpasync16(xa + r * 272 + c * 16, xsrc + (size_t)r * NTOK + n0 + c * 8);
        }
        CP_COMMIT();
        unsigned xb2 = smem_u32(xt1);
        for (int i = tid; i < 128 * 16; i += 512) {
            int r = i >> 4, c = i & 15;
            cpasync16(xb2 + r * 272 + c * 16, xsrc + (size_t)r * NTOK + n0 + 128 + c * 8);
        }
        CP_COMMIT();
    }
    if (tid < 256) {
        int h = tid >> 5, j = tid & 31;
        int src_r = (j < 16) ? (48 * h + 16 + j) : (48 * h + 32 + (j - 16));
        qb[tid] = qkv_b[src_r];
    }

    int w = tid >> 5, l = tid & 31;
    int lr = l >> 2, lc = l & 3;
    int mw = w >> 1;
    int nw = w & 1;
    int rbase = mw * 32, cbase = nw * 64;

    float lw[2][2], lb[2][2];
    lw[0][0] = kln_w[mw * 16 + lr];     lw[0][1] = kln_w[mw * 16 + lr + 8];
    lb[0][0] = kln_b[mw * 16 + lr];     lb[0][1] = kln_b[mw * 16 + lr + 8];
    lw[1][0] = vln_w[mw * 16 + lr];     lw[1][1] = vln_w[mw * 16 + lr + 8];
    lb[1][0] = vln_b[mw * 16 + lr];     lb[1][1] = vln_b[mw * 16 + lr + 8];

    float acc2[2][4];
#pragma unroll
    for (int e = 0; e < 2; e++)
#pragma unroll
        for (int q = 0; q < 4; q++) acc2[e][q] = 0.f;

#pragma unroll
    for (int tile = 0; tile < 2; tile++) {
        if (tile == 0) { CP_WAIT(1); } else { CP_WAIT(0); }
        __syncthreads();
        const __half* xt = tile ? xt1 : xt0;

        float acc[2][8][4];
#pragma unroll
        for (int a_ = 0; a_ < 2; a_++)
#pragma unroll
            for (int b_ = 0; b_ < 8; b_++)
#pragma unroll
                for (int c_ = 0; c_ < 4; c_++) acc[a_][b_][c_] = 0.f;

        gemm_t<8>(Wt, xt, acc, rbase, cbase, l);

        float q0 = qb[rbase + lr],      q1 = qb[rbase + lr + 8];
        float q2 = qb[rbase + 16 + lr], q3 = qb[rbase + 16 + lr + 8];
#pragma unroll
        for (int ni = 0; ni < 8; ni++) {
            acc[0][ni][0] += q0; acc[0][ni][1] += q0;
            acc[0][ni][2] += q1; acc[0][ni][3] += q1;
            acc[1][ni][0] += q2; acc[1][ni][1] += q2;
            acc[1][ni][2] += q3; acc[1][ni][3] += q3;
        }

#pragma unroll
        for (int mi = 0; mi < 2; mi++) {
            __half* dst = mi ? vT : kT;
#pragma unroll
            for (int ni = 0; ni < 8; ni++) {
                float* c = acc[mi][ni];
                float sa = c[0] + c[2], sb = c[1] + c[3];
                float ssa = c[0] * c[0] + c[2] * c[2];
                float ssb = c[1] * c[1] + c[3] * c[3];
#pragma unroll
                for (int m = 4; m <= 16; m <<= 1) {
                    sa += __shfl_xor_sync(0xffffffffu, sa, m);
                    sb += __shfl_xor_sync(0xffffffffu, sb, m);
                    ssa += __shfl_xor_sync(0xffffffffu, ssa, m);
                    ssb += __shfl_xor_sync(0xffffffffu, ssb, m);
                }
                float ma = sa * (1.f / 16.f);
                float va = fmaxf((ssa - 16.f * ma * ma) * (1.f / 15.f), 0.f);
                float ia = 1.f / (sqrtf(va) + LN_EPS);
                float mb = sb * (1.f / 16.f);
                float vb = fmaxf((ssb - 16.f * mb * mb) * (1.f / 15.f), 0.f);
                float ib = 1.f / (sqrtf(vb) + LN_EPS);
                float n0 = lw[mi][0] * ((c[0] - ma) * ia) + lb[mi][0];
                float n1 = lw[mi][0] * ((c[1] - mb) * ib) + lb[mi][0];
                float n2 = lw[mi][1] * ((c[2] - ma) * ia) + lb[mi][1];
                float n3 = lw[mi][1] * ((c[3] - mb) * ib) + lb[mi][1];
                int row = mw * 16 + lr;
                int col = cbase + ni * 8 + lc * 2;
                *(unsigned*)(dst + row * 136 + col)       = pk2h(n0, n1);
                *(unsigned*)(dst + (row + 8) * 136 + col) = pk2h(n2, n3);
            }
        }
        __syncthreads();

#pragma unroll
        for (int tcc = 0; tcc < 4; tcc++) {
            int tc = nw * 64 + tcc * 16;
            unsigned a[4];
            const __half* pa = kT + (mw * 16 + lr) * 136 + tc + lc * 2;
            a[0] = *(const unsigned*)pa;
            a[1] = *(const unsigned*)(pa + 8 * 136);
            a[2] = *(const unsigned*)(pa + 8);
            a[3] = *(const unsigned*)(pa + 8 * 136 + 8);
#pragma unroll
            for (int eh = 0; eh < 2; eh++) {
                const __half* pb = vT + (mw * 16 + eh * 8 + lr) * 136 + tc + lc * 2;
                unsigned bb[2] = {*(const unsigned*)pb, *(const unsigned*)(pb + 8)};
                mma16816h(acc2[eh], a, bb);
            }
        }
        __syncthreads();
    }

    float* base = g_kv + (size_t)(b * HEADS + mw) * 256;
#pragma unroll
    for (int eh = 0; eh < 2; eh++) {
        int e0 = eh * 8 + lc * 2;
        atomicAdd(base + lr * 16 + e0,           acc2[eh][0]);
        atomicAdd(base + lr * 16 + e0 + 1,       acc2[eh][1]);
        atomicAdd(base + (lr + 8) * 16 + e0,     acc2[eh][2]);
        atomicAdd(base + (lr + 8) * 16 + e0 + 1, acc2[eh][3]);
    }
}

// ---------------- kernel 2: compose Meff_b = Wq o kv / N (parallel) ----------------
// grid (8 co-groups, BATCH), 128 threads. co group g == head g.
// thread ci computes Meff[b][g*16+e][ci] for e in 0..15.
__global__ void compose_kernel(const float* __restrict__ qkv_w, const float* __restrict__ qkv_b) {
    __shared__ float kvs[256];     // kv block of head g, scaled
    __shared__ float bsum[16];
    int g = blockIdx.x, b = blockIdx.y;
    int ci = threadIdx.x;          // 128 threads

    for (int i = ci; i < 256; i += 128)
        kvs[i] = g_kv[(b * HEADS + g) * 256 + i] * (1.f / (float)NTOK);
    if (ci < 16) {
        // meffb for co = g*16 + ci : sum_d qkv_b[48g+d] * kvs[d][ci]
        float s = 0.f;
#pragma unroll
        for (int d = 0; d < 16; d++) s += qkv_b[48 * g + d] * kvs[d * 16 + ci];
        bsum[ci] = s;
    }
    __syncthreads();

    // weights for this head, column ci
    float wq[16];
#pragma unroll
    for (int d = 0; d < 16; d++) wq[d] = qkv_w[(48 * g + d) * 128 + ci];

    __half* mdst = g_meff + ((size_t)b * 128 + g * 16) * 128 + ci;
#pragma unroll
    for (int e = 0; e < 16; e++) {
        float s = 0.f;
#pragma unroll
        for (int d = 0; d < 16; d++) s += wq[d] * kvs[d * 16 + e];
        mdst[e * 128] = __float2half_rn(s);
    }
    if (ci < 16) g_meffb[b * 128 + g * 16 + ci] = bsum[ci];
}

// ---------------- kernel 3: fused av + residual + o1 + gelu + o2 + residual ----------------
#define M4_BUFA 0                         // x16 tile, then o2
#define M4_BUFB (128 * 136 * 2)           // Meff, then o1
#define M4_RT   (2 * 128 * 136 * 2)
#define M4_BIAS (3 * 128 * 136 * 2)
#define M4_SMEM (M4_BIAS + 3 * 128 * 4)

__global__ void __launch_bounds__(256, 2) main_kernel(const float* __restrict__ o1_b,
                                                      const float* __restrict__ o2_b,
                                                      float* __restrict__ out) {
    extern __shared__ char smem[];
    __half* bufA = (__half*)(smem + M4_BUFA);
    __half* bufB = (__half*)(smem + M4_BUFB);
    __half* rt = (__half*)(smem + M4_RT);
    float* bias = (float*)(smem + M4_BIAS);

    int tid = threadIdx.x;
    int b = blockIdx.y;
    int n0 = blockIdx.x * 128;

    {
        unsigned ba = smem_u32(bufA), bb = smem_u32(bufB);
        const __half* msrc = g_meff + (size_t)b * 128 * 128;
        const __half* xsrc = g_x16 + (size_t)b * CCH * NTOK + n0;
        for (int i = tid; i < 128 * 16; i += 256) {
            int r = i >> 4, c = i & 15;
            cpasync16(bb + r * 272 + c * 16, msrc + r * 128 + c * 8);
            cpasync16(ba + r * 272 + c * 16, xsrc + (size_t)r * NTOK + c * 8);
        }
        CP_COMMIT();
    }
    if (tid < 128) {
        bias[tid] = g_meffb[b * 128 + tid];
        bias[128 + tid] = o1_b[tid];
        bias[256 + tid] = o2_b[tid];
    }
    CP_WAIT(0);
    __syncthreads();

    int w = tid >> 5, l = tid & 31;
    int lr = l >> 2, lc = l & 3;
    int mw = w >> 1, nw = w & 1;
    int rbase = mw * 32, cbase = nw * 64;

    float acc[2][8][4];
#define ZACC() { _Pragma("unroll") for (int a_=0;a_<2;a_++) _Pragma("unroll") for (int b_=0;b_<8;b_++) _Pragma("unroll") for (int c_=0;c_<4;c_++) acc[a_][b_][c_]=0.f; }

    // ---- phase 1: rt = Meff*x + meffb + x ----
    ZACC();
    gemm_t<8>(bufB, bufA, acc, rbase, cbase, l);
    {
        float bm0 = bias[rbase + lr],      bm1 = bias[rbase + lr + 8];
        float bm2 = bias[rbase + 16 + lr], bm3 = bias[rbase + 16 + lr + 8];
#pragma unroll
        for (int mi = 0; mi < 2; mi++) {
            int row = rbase + mi * 16 + lr;
            float ba0 = mi ? bm2 : bm0, ba1 = mi ? bm3 : bm1;
#pragma unroll
            for (int ni = 0; ni < 8; ni++) {
                int col = cbase + ni * 8 + lc * 2;
                __half2 xv0 = *(const __half2*)(bufA + row * 136 + col);
                __half2 xv1 = *(const __half2*)(bufA + (row + 8) * 136 + col);
                float2 f0 = __half22float2(xv0), f1 = __half22float2(xv1);
                float r00 = acc[mi][ni][0] + ba0 + f0.x;
                float r01 = acc[mi][ni][1] + ba0 + f0.y;
                float r10 = acc[mi][ni][2] + ba1 + f1.x;
                float r11 = acc[mi][ni][3] + ba1 + f1.y;
                *(unsigned*)(rt + row * 136 + col)       = pk2h(r00, r01);
                *(unsigned*)(rt + (row + 8) * 136 + col) = pk2h(r10, r11);
            }
        }
    }
    __syncthreads();

    {
        unsigned bb = smem_u32(bufB);
        for (int i = tid; i < 128 * 16; i += 256) {
            int r = i >> 4, c = i & 15;
            cpasync16(bb + r * 272 + c * 16, g_o1h + r * 128 + c * 8);
        }
        CP_COMMIT();
        unsigned ba = smem_u32(bufA);
        for (int i = tid; i < 128 * 16; i += 256) {
            int r = i >> 4, c = i & 15;
            cpasync16(ba + r * 272 + c * 16, g_o2h + r * 128 + c * 8);
        }
        CP_COMMIT();
    }
    CP_WAIT(1);
    __syncthreads();

    // ---- phase 2: h1 = gelu(o1 * rt + b1) ----
    ZACC();
    gemm_t<8>(bufB, rt, acc, rbase, cbase, l);
    {
        float b10 = bias[128 + rbase + lr],      b11 = bias[128 + rbase + lr + 8];
        float b12 = bias[128 + rbase + 16 + lr], b13 = bias[128 + rbase + 16 + lr + 8];
#pragma unroll
        for (int mi = 0; mi < 2; mi++) {
            float ba0 = mi ? b12 : b10, ba1 = mi ? b13 : b11;
#pragma unroll
            for (int ni = 0; ni < 8; ni++) {
#pragma unroll
                for (int q = 0; q < 4; q++) {
                    float h = acc[mi][ni][q] + ((q < 2) ? ba0 : ba1);
                    acc[mi][ni][q] = 0.5f * h * (1.f + erff(h * 0.70710678118654752f));
                }
            }
        }
    }
    __syncthreads();
#pragma unroll
    for (int mi = 0; mi < 2; mi++) {
        int row = rbase + mi * 16 + lr;
#pragma unroll
        for (int ni = 0; ni < 8; ni++) {
            int col = cbase + ni * 8 + lc * 2;
            *(unsigned*)(rt + row * 136 + col)       = pk2h(acc[mi][ni][0], acc[mi][ni][1]);
            *(unsigned*)(rt + (row + 8) * 136 + col) = pk2h(acc[mi][ni][2], acc[mi][ni][3]);
        }
    }
    CP_WAIT(0);
    __syncthreads();

    // ---- phase 3: out = o2 * h1 + b2 + x ----
    ZACC();
    gemm_t<8>(bufA, rt, acc, rbase, cbase, l);
    {
        float b20 = bias[256 + rbase + lr],      b21 = bias[256 + rbase + lr + 8];
        float b22 = bias[256 + rbase + 16 + lr], b23 = bias[256 + rbase + 16 + lr + 8];
        const __half* xh = g_x16 + (size_t)b * CCH * NTOK + n0;
        float* ob = out + (size_t)b * CCH * NTOK + n0;
#pragma unroll
        for (int mi = 0; mi < 2; mi++) {
            int row = rbase + mi * 16 + lr;
            float ba0 = mi ? b22 : b20, ba1 = mi ? b23 : b21;
#pragma unroll
            for (int ni = 0; ni < 8; ni++) {
                int col = cbase + ni * 8 + lc * 2;
                __half2 xv0 = *(const __half2*)(xh + (size_t)row * NTOK + col);
                __half2 xv1 = *(const __half2*)(xh + (size_t)(row + 8) * NTOK + col);
                float2 f0 = __half22float2(xv0), f1 = __half22float2(xv1);
                float2 o0, o1v;
                o0.x = acc[mi][ni][0] + ba0 + f0.x;
                o0.y = acc[mi][ni][1] + ba0 + f0.y;
                o1v.x = acc[mi][ni][2] + ba1 + f1.x;
                o1v.y = acc[mi][ni][3] + ba1 + f1.y;
                *(float2*)(ob + (size_t)row * NTOK + col) = o0;
                *(float2*)(ob + (size_t)(row + 8) * NTOK + col) = o1v;
            }
        }
    }
}

// ---------------- launch ----------------
extern "C" void kernel_launch(void* const* d_in, const int* in_sizes, int n_in,
                              void* d_out, int out_size) {
    const float* x     = (const float*)d_in[0];
    const float* qkv_w = (const float*)d_in[1];
    const float* qkv_b = (const float*)d_in[2];
    const float* o1_w  = (const float*)d_in[3];
    const float* o1_b  = (const float*)d_in[4];
    const float* o2_w  = (const float*)d_in[5];
    const float* o2_b  = (const float*)d_in[6];
    const float* kln_w = (const float*)d_in[7];
    const float* kln_b = (const float*)d_in[8];
    const float* vln_w = (const float*)d_in[9];
    const float* vln_b = (const float*)d_in[10];
    float* out = (float*)d_out;

    cudaFuncSetAttribute(kv_kernel, cudaFuncAttributeMaxDynamicSharedMemorySize, KVS_SMEM);
    cudaFuncSetAttribute(main_kernel, cudaFuncAttributeMaxDynamicSharedMemorySize, M4_SMEM);

    prep_kernel<<<128, 256>>>(qkv_w, o1_w, o2_w);
    x16_kernel<<<(BATCH * CCH * NTOK) / 1024, 256>>>(x);

    dim3 g2(NTOK / 256, BATCH);
    kv_kernel<<<g2, 512, KVS_SMEM>>>(qkv_b, kln_w, kln_b, vln_w, vln_b);

    dim3 gc(HEADS, BATCH);
    compose_kernel<<<gc, 128>>>(qkv_w, qkv_b);

    dim3 g4(NTOK / 128, BATCH);
    main_kernel<<<g4, 256, M4_SMEM>>>(o1_b, o2_b, out);
}

// round 7
// speedup vs baseline: 2.9485x; 1.0330x over previous
#include <cuda_runtime.h>
#include <cuda_fp16.h>

#define BATCH 8
#define CCH   128
#define NTOK  16384
#define HEADS 8
#define LN_EPS 1e-5f

// ---------------- device scratch ----------------
__device__ float  g_kv[BATCH * HEADS * 16 * 16];
__device__ __half g_wkv[256 * 128];
__device__ __half g_o1h[128 * 128];
__device__ __half g_o2h[128 * 128];
__device__ __half g_meff[BATCH * 128 * 128];
__device__ float  g_meffb[BATCH * 128];
__device__ __half g_x16[(size_t)BATCH * CCH * NTOK];

// ---------------- helpers ----------------
__device__ __forceinline__ unsigned pk2h(float a, float b) {
    __half2 h = __floats2half2_rn(a, b);
    return *reinterpret_cast<unsigned*>(&h);
}

__device__ __forceinline__ void mma16816h(float* c, const unsigned* a, const unsigned* b) {
    asm volatile(
        "mma.sync.aligned.m16n8k16.row.col.f32.f16.f16.f32 "
        "{%0,%1,%2,%3}, {%4,%5,%6,%7}, {%8,%9}, {%0,%1,%2,%3};\n"
        : "+f"(c[0]), "+f"(c[1]), "+f"(c[2]), "+f"(c[3])
        : "r"(a[0]), "r"(a[1]), "r"(a[2]), "r"(a[3]), "r"(b[0]), "r"(b[1]));
}

__device__ __forceinline__ unsigned smem_u32(const void* p) {
    return (unsigned)__cvta_generic_to_shared(p);
}

__device__ __forceinline__ void ldsm4(unsigned& r0, unsigned& r1, unsigned& r2, unsigned& r3,
                                      unsigned addr) {
    asm volatile("ldmatrix.sync.aligned.m8n8.x4.shared.b16 {%0,%1,%2,%3}, [%4];\n"
                 : "=r"(r0), "=r"(r1), "=r"(r2), "=r"(r3) : "r"(addr));
}

__device__ __forceinline__ void ldsm4t(unsigned& r0, unsigned& r1, unsigned& r2, unsigned& r3,
                                       unsigned addr) {
    asm volatile("ldmatrix.sync.aligned.m8n8.x4.trans.shared.b16 {%0,%1,%2,%3}, [%4];\n"
                 : "=r"(r0), "=r"(r1), "=r"(r2), "=r"(r3) : "r"(addr));
}

__device__ __forceinline__ void cpasync16(unsigned s, const void* g) {
    asm volatile("cp.async.cg.shared.global [%0], [%1], 16;\n" :: "r"(s), "l"(g));
}
#define CP_COMMIT() asm volatile("cp.async.commit_group;\n")
#define CP_WAIT(n)  asm volatile("cp.async.wait_group %0;\n" :: "n"(n))

// fast erf: Abramowitz-Stegun 7.1.26, max abs err 1.5e-7
__device__ __forceinline__ float fast_erf(float x) {
    float ax = fabsf(x);
    float t = 1.f / fmaf(0.3275911f, ax, 1.f);
    float p = fmaf(1.061405429f, t, -1.453152027f);
    p = fmaf(p, t, 1.421413741f);
    p = fmaf(p, t, -0.284496736f);
    p = fmaf(p, t, 0.254829592f);
    p *= t;
    float r = 1.f - p * __expf(-ax * ax);
    return copysignf(r, x);
}

// Output-layout GEMM: C[c_out rows][token cols] = A[c_out][k=128] * B[k=128][t].
// A: smem [rows][136], non-trans ldmatrix. B: smem [128][LDB], trans ldmatrix.
template <int NI8, int LDB>
__device__ __forceinline__ void gemm_t(const __half* __restrict__ A,
                                       const __half* __restrict__ B,
                                       float (&acc)[2][NI8][4], int rbase, int cbase, int lane) {
    unsigned a_addr = smem_u32(A + (rbase + (lane & 15)) * 136 + ((lane >> 4) << 3));
    unsigned b_addr = smem_u32(B + (lane & 15) * LDB + cbase + ((lane >> 4) << 3));
#pragma unroll
    for (int kc = 0; kc < 128; kc += 16) {
        unsigned a[2][4];
        ldsm4(a[0][0], a[0][1], a[0][2], a[0][3], a_addr);
        ldsm4(a[1][0], a[1][1], a[1][2], a[1][3], a_addr + 16 * 136 * 2);
#pragma unroll
        for (int g = 0; g < NI8 / 2; g++) {
            unsigned b0, b1, b2, b3;
            ldsm4t(b0, b1, b2, b3, b_addr + g * 32);
            unsigned bl[2] = {b0, b1}, bh[2] = {b2, b3};
            mma16816h(acc[0][2 * g],     a[0], bl);
            mma16816h(acc[1][2 * g],     a[1], bl);
            mma16816h(acc[0][2 * g + 1], a[0], bh);
            mma16816h(acc[1][2 * g + 1], a[1], bh);
        }
        a_addr += 32;
        b_addr += 16 * LDB * 2;
    }
}

// ---------------- kernel 0: weight prep ----------------
__global__ void prep_kernel(const float* __restrict__ qkv_w,
                            const float* __restrict__ o1_w,
                            const float* __restrict__ o2_w) {
    int idx = blockIdx.x * blockDim.x + threadIdx.x;
    int nthr = gridDim.x * blockDim.x;
    for (int i = idx; i < BATCH * HEADS * 16 * 16; i += nthr) g_kv[i] = 0.f;
    for (int i = idx; i < 256 * 128; i += nthr) {
        int r = i >> 7, c = i & 127;
        int h = r >> 5, j = r & 31;
        int src = (j < 16) ? (48 * h + 16 + j) : (48 * h + 32 + (j - 16));
        g_wkv[i] = __float2half_rn(qkv_w[src * 128 + c]);
    }
    for (int i = idx; i < 128 * 128; i += nthr) {
        g_o1h[i] = __float2half_rn(o1_w[i]);
        g_o2h[i] = __float2half_rn(o2_w[i]);
    }
}

// ---------------- kernel 1: x->fp16 + k,v projection + register-LN + kv via MMA ----------------
#define KVS_WT   0
#define KVS_XT0  (256 * 136 * 2)
#define KVS_XT1  (KVS_XT0 + 128 * 136 * 2)
#define KVS_KT   (KVS_XT1 + 128 * 136 * 2)
#define KVS_VT   (KVS_KT + 128 * 136 * 2)
#define KVS_QB   (KVS_VT + 128 * 136 * 2)
#define KVS_SMEM (KVS_QB + 256 * 4)

__global__ void __launch_bounds__(512, 1) kv_kernel(const float* __restrict__ x,
                                                    const float* __restrict__ qkv_b,
                                                    const float* __restrict__ kln_w,
                                                    const float* __restrict__ kln_b,
                                                    const float* __restrict__ vln_w,
                                                    const float* __restrict__ vln_b) {
    extern __shared__ char smem[];
    __half* Wt = (__half*)(smem + KVS_WT);
    __half* xt0 = (__half*)(smem + KVS_XT0);
    __half* xt1 = (__half*)(smem + KVS_XT1);
    __half* kT = (__half*)(smem + KVS_KT);
    __half* vT = (__half*)(smem + KVS_VT);
    float* qb = (float*)(smem + KVS_QB);

    int tid = threadIdx.x;
    int b = blockIdx.y;
    const float* xb = x + (size_t)b * CCH * NTOK;
    __half* x16b = g_x16 + (size_t)b * CCH * NTOK;

    // weights via cp.async (group 0)
    {
        unsigned wt = smem_u32(Wt);
        for (int i = tid; i < 256 * 16; i += 512) {
            int r = i >> 4, c = i & 15;
            cpasync16(wt + r * 272 + c * 16, g_wkv + r * 128 + c * 8);
        }
        CP_COMMIT();
    }
    if (tid < 256) {
        int h = tid >> 5, j = tid & 31;
        int src_r = (j < 16) ? (48 * h + 16 + j) : (48 * h + 32 + (j - 16));
        qb[tid] = qkv_b[src_r];
    }

    int w = tid >> 5, l = tid & 31;
    int lr = l >> 2, lc = l & 3;
    int mw = w >> 1;
    int nw = w & 1;
    int rbase = mw * 32, cbase = nw * 64;

    float lw[2][2], lb[2][2];
    lw[0][0] = kln_w[mw * 16 + lr];     lw[0][1] = kln_w[mw * 16 + lr + 8];
    lb[0][0] = kln_b[mw * 16 + lr];     lb[0][1] = kln_b[mw * 16 + lr + 8];
    lw[1][0] = vln_w[mw * 16 + lr];     lw[1][1] = vln_w[mw * 16 + lr + 8];
    lb[1][0] = vln_b[mw * 16 + lr];     lb[1][1] = vln_b[mw * 16 + lr + 8];

    float acc2[2][4];
#pragma unroll
    for (int e = 0; e < 2; e++)
#pragma unroll
        for (int q = 0; q < 4; q++) acc2[e][q] = 0.f;

#pragma unroll
    for (int tile = 0; tile < 2; tile++) {
        int n0 = blockIdx.x * 256 + tile * 128;
        __half* xt = tile ? xt1 : xt0;

        // load fp32 x tile, convert, store to smem + g_x16
#pragma unroll
        for (int k = 0; k < 8; k++) {
            int i = tid + k * 512;
            int r = i >> 5, c4 = i & 31;
            float4 v = *(const float4*)(xb + (size_t)r * NTOK + n0 + c4 * 4);
            __half2 h0 = __floats2half2_rn(v.x, v.y);
            __half2 h1 = __floats2half2_rn(v.z, v.w);
            uint2 u;
            u.x = *reinterpret_cast<unsigned*>(&h0);
            u.y = *reinterpret_cast<unsigned*>(&h1);
            *(uint2*)(xt + r * 136 + c4 * 4) = u;
            *(uint2*)(x16b + (size_t)r * NTOK + n0 + c4 * 4) = u;
        }
        if (tile == 0) CP_WAIT(0);
        __syncthreads();

        float acc[2][8][4];
#pragma unroll
        for (int a_ = 0; a_ < 2; a_++)
#pragma unroll
            for (int b_ = 0; b_ < 8; b_++)
#pragma unroll
                for (int c_ = 0; c_ < 4; c_++) acc[a_][b_][c_] = 0.f;

        gemm_t<8, 136>(Wt, xt, acc, rbase, cbase, l);

        float q0 = qb[rbase + lr],      q1 = qb[rbase + lr + 8];
        float q2 = qb[rbase + 16 + lr], q3 = qb[rbase + 16 + lr + 8];
#pragma unroll
        for (int ni = 0; ni < 8; ni++) {
            acc[0][ni][0] += q0; acc[0][ni][1] += q0;
            acc[0][ni][2] += q1; acc[0][ni][3] += q1;
            acc[1][ni][0] += q2; acc[1][ni][1] += q2;
            acc[1][ni][2] += q3; acc[1][ni][3] += q3;
        }

        // register LayerNorm over d=16, ddof=1, eps on std
#pragma unroll
        for (int mi = 0; mi < 2; mi++) {
            __half* dst = mi ? vT : kT;
#pragma unroll
            for (int ni = 0; ni < 8; ni++) {
                float* c = acc[mi][ni];
                float sa = c[0] + c[2], sb = c[1] + c[3];
                float ssa = c[0] * c[0] + c[2] * c[2];
                float ssb = c[1] * c[1] + c[3] * c[3];
#pragma unroll
                for (int m = 4; m <= 16; m <<= 1) {
                    sa += __shfl_xor_sync(0xffffffffu, sa, m);
                    sb += __shfl_xor_sync(0xffffffffu, sb, m);
                    ssa += __shfl_xor_sync(0xffffffffu, ssa, m);
                    ssb += __shfl_xor_sync(0xffffffffu, ssb, m);
                }
                float ma = sa * (1.f / 16.f);
                float va = fmaxf((ssa - 16.f * ma * ma) * (1.f / 15.f), 0.f);
                float ia = 1.f / (sqrtf(va) + LN_EPS);
                float mb = sb * (1.f / 16.f);
                float vb = fmaxf((ssb - 16.f * mb * mb) * (1.f / 15.f), 0.f);
                float ib = 1.f / (sqrtf(vb) + LN_EPS);
                float n0 = lw[mi][0] * ((c[0] - ma) * ia) + lb[mi][0];
                float n1 = lw[mi][0] * ((c[1] - mb) * ib) + lb[mi][0];
                float n2 = lw[mi][1] * ((c[2] - ma) * ia) + lb[mi][1];
                float n3 = lw[mi][1] * ((c[3] - mb) * ib) + lb[mi][1];
                int row = mw * 16 + lr;
                int col = cbase + ni * 8 + lc * 2;
                *(unsigned*)(dst + row * 136 + col)       = pk2h(n0, n1);
                *(unsigned*)(dst + (row + 8) * 136 + col) = pk2h(n2, n3);
            }
        }
        __syncthreads();

        // per-head kv outer product
#pragma unroll
        for (int tcc = 0; tcc < 4; tcc++) {
            int tc = nw * 64 + tcc * 16;
            unsigned a[4];
            const __half* pa = kT + (mw * 16 + lr) * 136 + tc + lc * 2;
            a[0] = *(const unsigned*)pa;
            a[1] = *(const unsigned*)(pa + 8 * 136);
            a[2] = *(const unsigned*)(pa + 8);
            a[3] = *(const unsigned*)(pa + 8 * 136 + 8);
#pragma unroll
            for (int eh = 0; eh < 2; eh++) {
                const __half* pb = vT + (mw * 16 + eh * 8 + lr) * 136 + tc + lc * 2;
                unsigned bb[2] = {*(const unsigned*)pb, *(const unsigned*)(pb + 8)};
                mma16816h(acc2[eh], a, bb);
            }
        }
        __syncthreads();
    }

    float* base = g_kv + (size_t)(b * HEADS + mw) * 256;
#pragma unroll
    for (int eh = 0; eh < 2; eh++) {
        int e0 = eh * 8 + lc * 2;
        atomicAdd(base + lr * 16 + e0,           acc2[eh][0]);
        atomicAdd(base + lr * 16 + e0 + 1,       acc2[eh][1]);
        atomicAdd(base + (lr + 8) * 16 + e0,     acc2[eh][2]);
        atomicAdd(base + (lr + 8) * 16 + e0 + 1, acc2[eh][3]);
    }
}

// ---------------- kernel 2: compose Meff_b = Wq o kv / N ----------------
__global__ void compose_kernel(const float* __restrict__ qkv_w, const float* __restrict__ qkv_b) {
    __shared__ float kvs[256];
    __shared__ float bsum[16];
    int g = blockIdx.x, b = blockIdx.y;
    int ci = threadIdx.x;

    for (int i = ci; i < 256; i += 128)
        kvs[i] = g_kv[(b * HEADS + g) * 256 + i] * (1.f / (float)NTOK);
    if (ci < 16) {
        float s = 0.f;
#pragma unroll
        for (int d = 0; d < 16; d++) s += qkv_b[48 * g + d] * kvs[d * 16 + ci];
        bsum[ci] = s;
    }
    __syncthreads();

    float wq[16];
#pragma unroll
    for (int d = 0; d < 16; d++) wq[d] = qkv_w[(48 * g + d) * 128 + ci];

    __half* mdst = g_meff + ((size_t)b * 128 + g * 16) * 128 + ci;
#pragma unroll
    for (int e = 0; e < 16; e++) {
        float s = 0.f;
#pragma unroll
        for (int d = 0; d < 16; d++) s += wq[d] * kvs[d * 16 + e];
        mdst[e * 128] = __float2half_rn(s);
    }
    if (ci < 16) g_meffb[b * 128 + g * 16 + ci] = bsum[ci];
}

// ---------------- kernel 3: fused av + residual + o1 + gelu + o2 + residual ----------------
// 512 threads, 256 tokens/block, x tile persists for both residuals.
#define M4_LDB  264
#define M4_XT   0                             // x16 tile [128][264]
#define M4_RT   (128 * M4_LDB * 2)            // rt [128][264]
#define M4_WA   (2 * 128 * M4_LDB * 2)        // Meff -> o2
#define M4_WB   (M4_WA + 128 * 136 * 2)       // o1
#define M4_BIAS (M4_WB + 128 * 136 * 2)
#define M4_SMEM (M4_BIAS + 3 * 128 * 4)

__global__ void __launch_bounds__(512, 1) main_kernel(const float* __restrict__ o1_b,
                                                      const float* __restrict__ o2_b,
                                                      float* __restrict__ out) {
    extern __shared__ char smem[];
    __half* xt = (__half*)(smem + M4_XT);
    __half* rt = (__half*)(smem + M4_RT);
    __half* wA = (__half*)(smem + M4_WA);
    __half* wB = (__half*)(smem + M4_WB);
    float* bias = (float*)(smem + M4_BIAS);

    int tid = threadIdx.x;
    int b = blockIdx.y;
    int n0 = blockIdx.x * 256;

    // group 0: Meff -> wA, x tile -> xt ; group 1: o1 -> wB
    {
        unsigned wa = smem_u32(wA), xa = smem_u32(xt);
        const __half* msrc = g_meff + (size_t)b * 128 * 128;
        const __half* xsrc = g_x16 + (size_t)b * CCH * NTOK + n0;
        for (int i = tid; i < 128 * 16; i += 512) {
            int r = i >> 4, c = i & 15;
            cpasync16(wa + r * 272 + c * 16, msrc + r * 128 + c * 8);
        }
        for (int i = tid; i < 128 * 32; i += 512) {
            int r = i >> 5, c = i & 31;
            cpasync16(xa + r * (M4_LDB * 2) + c * 16, xsrc + (size_t)r * NTOK + c * 8);
        }
        CP_COMMIT();
        unsigned wb = smem_u32(wB);
        for (int i = tid; i < 128 * 16; i += 512) {
            int r = i >> 4, c = i & 15;
            cpasync16(wb + r * 272 + c * 16, g_o1h + r * 128 + c * 8);
        }
        CP_COMMIT();
    }
    if (tid < 128) {
        bias[tid] = g_meffb[b * 128 + tid];
        bias[128 + tid] = o1_b[tid];
        bias[256 + tid] = o2_b[tid];
    }
    CP_WAIT(1);
    __syncthreads();

    int w = tid >> 5, l = tid & 31;
    int lr = l >> 2, lc = l & 3;
    int mw = w >> 2, nw = w & 3;   // 4 row groups x 4 col groups
    int rbase = mw * 32, cbase = nw * 64;

    float acc[2][8][4];
#define ZACC() { _Pragma("unroll") for (int a_=0;a_<2;a_++) _Pragma("unroll") for (int b_=0;b_<8;b_++) _Pragma("unroll") for (int c_=0;c_<4;c_++) acc[a_][b_][c_]=0.f; }

    // ---- phase 1: rt = Meff*x + meffb + x ----
    ZACC();
    gemm_t<8, M4_LDB>(wA, xt, acc, rbase, cbase, l);
    {
        float bm0 = bias[rbase + lr],      bm1 = bias[rbase + lr + 8];
        float bm2 = bias[rbase + 16 + lr], bm3 = bias[rbase + 16 + lr + 8];
#pragma unroll
        for (int mi = 0; mi < 2; mi++) {
            int row = rbase + mi * 16 + lr;
            float ba0 = mi ? bm2 : bm0, ba1 = mi ? bm3 : bm1;
#pragma unroll
            for (int ni = 0; ni < 8; ni++) {
                int col = cbase + ni * 8 + lc * 2;
                __half2 xv0 = *(const __half2*)(xt + row * M4_LDB + col);
                __half2 xv1 = *(const __half2*)(xt + (row + 8) * M4_LDB + col);
                float2 f0 = __half22float2(xv0), f1 = __half22float2(xv1);
                float r00 = acc[mi][ni][0] + ba0 + f0.x;
                float r01 = acc[mi][ni][1] + ba0 + f0.y;
                float r10 = acc[mi][ni][2] + ba1 + f1.x;
                float r11 = acc[mi][ni][3] + ba1 + f1.y;
                *(unsigned*)(rt + row * M4_LDB + col)       = pk2h(r00, r01);
                *(unsigned*)(rt + (row + 8) * M4_LDB + col) = pk2h(r10, r11);
            }
        }
    }
    __syncthreads();  // rt written; wA reads done

    // o2 -> wA (overlaps phase 2)
    {
        unsigned wa = smem_u32(wA);
        for (int i = tid; i < 128 * 16; i += 512) {
            int r = i >> 4, c = i & 15;
            cpasync16(wa + r * 272 + c * 16, g_o2h + r * 128 + c * 8);
        }
        CP_COMMIT();
    }

    // ---- phase 2: h1 = gelu(o1 * rt + b1) ----
    ZACC();
    gemm_t<8, M4_LDB>(wB, rt, acc, rbase, cbase, l);
    {
        float b10 = bias[128 + rbase + lr],      b11 = bias[128 + rbase + lr + 8];
        float b12 = bias[128 + rbase + 16 + lr], b13 = bias[128 + rbase + 16 + lr + 8];
#pragma unroll
        for (int mi = 0; mi < 2; mi++) {
            float ba0 = mi ? b12 : b10, ba1 = mi ? b13 : b11;
#pragma unroll
            for (int ni = 0; ni < 8; ni++) {
#pragma unroll
                for (int q = 0; q < 4; q++) {
                    float h = acc[mi][ni][q] + ((q < 2) ? ba0 : ba1);
                    acc[mi][ni][q] = 0.5f * h * (1.f + fast_erf(h * 0.70710678118654752f));
                }
            }
        }
    }
    __syncthreads();  // all rt reads done
#pragma unroll
    for (int mi = 0; mi < 2; mi++) {
        int row = rbase + mi * 16 + lr;
#pragma unroll
        for (int ni = 0; ni < 8; ni++) {
            int col = cbase + ni * 8 + lc * 2;
            *(unsigned*)(rt + row * M4_LDB + col)       = pk2h(acc[mi][ni][0], acc[mi][ni][1]);
            *(unsigned*)(rt + (row + 8) * M4_LDB + col) = pk2h(acc[mi][ni][2], acc[mi][ni][3]);
        }
    }
    CP_WAIT(0);
    __syncthreads();

    // ---- phase 3: out = o2 * h1 + b2 + x (x from resident tile) ----
    ZACC();
    gemm_t<8, M4_LDB>(wA, rt, acc, rbase, cbase, l);
    {
        float b20 = bias[256 + rbase + lr],      b21 = bias[256 + rbase + lr + 8];
        float b22 = bias[256 + rbase + 16 + lr], b23 = bias[256 + rbase + 16 + lr + 8];
        float* ob = out + (size_t)b * CCH * NTOK + n0;
#pragma unroll
        for (int mi = 0; mi < 2; mi++) {
            int row = rbase + mi * 16 + lr;
            float ba0 = mi ? b22 : b20, ba1 = mi ? b23 : b21;
#pragma unroll
            for (int ni = 0; ni < 8; ni++) {
                int col = cbase + ni * 8 + lc * 2;
                __half2 xv0 = *(const __half2*)(xt + row * M4_LDB + col);
                __half2 xv1 = *(const __half2*)(xt + (row + 8) * M4_LDB + col);
                float2 f0 = __half22float2(xv0), f1 = __half22float2(xv1);
                float2 o0, o1v;
                o0.x = acc[mi][ni][0] + ba0 + f0.x;
                o0.y = acc[mi][ni][1] + ba0 + f0.y;
                o1v.x = acc[mi][ni][2] + ba1 + f1.x;
                o1v.y = acc[mi][ni][3] + ba1 + f1.y;
                *(float2*)(ob + (size_t)row * NTOK + col) = o0;
                *(float2*)(ob + (size_t)(row + 8) * NTOK + col) = o1v;
            }
        }
    }
}

// ---------------- launch ----------------
extern "C" void kernel_launch(void* const* d_in, const int* in_sizes, int n_in,
                              void* d_out, int out_size) {
    const float* x     = (const float*)d_in[0];
    const float* qkv_w = (const float*)d_in[1];
    const float* qkv_b = (const float*)d_in[2];
    const float* o1_w  = (const float*)d_in[3];
    const float* o1_b  = (const float*)d_in[4];
    const float* o2_w  = (const float*)d_in[5];
    const float* o2_b  = (const float*)d_in[6];
    const float* kln_w = (const float*)d_in[7];
    const float* kln_b = (const float*)d_in[8];
    const float* vln_w = (const float*)d_in[9];
    const float* vln_b = (const float*)d_in[10];
    float* out = (float*)d_out;

    cudaFuncSetAttribute(kv_kernel, cudaFuncAttributeMaxDynamicSharedMemorySize, KVS_SMEM);
    cudaFuncSetAttribute(main_kernel, cudaFuncAttributeMaxDynamicSharedMemorySize, M4_SMEM);

    prep_kernel<<<128, 256>>>(qkv_w, o1_w, o2_w);

    dim3 g2(NTOK / 256, BATCH);
    kv_kernel<<<g2, 512, KVS_SMEM>>>(x, qkv_b, kln_w, kln_b, vln_w, vln_b);

    dim3 gc(HEADS, BATCH);
    compose_kernel<<<gc, 128>>>(qkv_w, qkv_b);

    dim3 g4(NTOK / 256, BATCH);
    main_kernel<<<g4, 512, M4_SMEM>>>(o1_b, o2_b, out);
}

// round 8
// speedup vs baseline: 3.1080x; 1.0541x over previous
#include <cuda_runtime.h>
#include <cuda_fp16.h>

#define BATCH 8
#define CCH   128
#define NTOK  16384
#define HEADS 8
#define LN_EPS 1e-5f

// ---------------- device scratch ----------------
__device__ float  g_kv[BATCH * HEADS * 16 * 16];
__device__ __half g_wkv[256 * 128];
__device__ __half g_o1h[128 * 128];
__device__ __half g_o2h[128 * 128];
__device__ __half g_meff[BATCH * 128 * 128];
__device__ float  g_meffb[BATCH * 128];
__device__ __half g_x16[(size_t)BATCH * CCH * NTOK];

// ---------------- helpers ----------------
__device__ __forceinline__ unsigned pk2h(float a, float b) {
    __half2 h = __floats2half2_rn(a, b);
    return *reinterpret_cast<unsigned*>(&h);
}

__device__ __forceinline__ void mma16816h(float* c, const unsigned* a, const unsigned* b) {
    asm volatile(
        "mma.sync.aligned.m16n8k16.row.col.f32.f16.f16.f32 "
        "{%0,%1,%2,%3}, {%4,%5,%6,%7}, {%8,%9}, {%0,%1,%2,%3};\n"
        : "+f"(c[0]), "+f"(c[1]), "+f"(c[2]), "+f"(c[3])
        : "r"(a[0]), "r"(a[1]), "r"(a[2]), "r"(a[3]), "r"(b[0]), "r"(b[1]));
}

__device__ __forceinline__ unsigned smem_u32(const void* p) {
    return (unsigned)__cvta_generic_to_shared(p);
}

__device__ __forceinline__ void ldsm4(unsigned& r0, unsigned& r1, unsigned& r2, unsigned& r3,
                                      unsigned addr) {
    asm volatile("ldmatrix.sync.aligned.m8n8.x4.shared.b16 {%0,%1,%2,%3}, [%4];\n"
                 : "=r"(r0), "=r"(r1), "=r"(r2), "=r"(r3) : "r"(addr));
}

__device__ __forceinline__ void ldsm4t(unsigned& r0, unsigned& r1, unsigned& r2, unsigned& r3,
                                       unsigned addr) {
    asm volatile("ldmatrix.sync.aligned.m8n8.x4.trans.shared.b16 {%0,%1,%2,%3}, [%4];\n"
                 : "=r"(r0), "=r"(r1), "=r"(r2), "=r"(r3) : "r"(addr));
}

__device__ __forceinline__ void cpasync16(unsigned s, const void* g) {
    asm volatile("cp.async.cg.shared.global [%0], [%1], 16;\n" :: "r"(s), "l"(g));
}
#define CP_COMMIT() asm volatile("cp.async.commit_group;\n")
#define CP_WAIT(n)  asm volatile("cp.async.wait_group %0;\n" :: "n"(n))

// fast erf: Abramowitz-Stegun 7.1.26, max abs err 1.5e-7
__device__ __forceinline__ float fast_erf(float x) {
    float ax = fabsf(x);
    float t = 1.f / fmaf(0.3275911f, ax, 1.f);
    float p = fmaf(1.061405429f, t, -1.453152027f);
    p = fmaf(p, t, 1.421413741f);
    p = fmaf(p, t, -0.284496736f);
    p = fmaf(p, t, 0.254829592f);
    p *= t;
    float r = 1.f - p * __expf(-ax * ax);
    return copysignf(r, x);
}

// Output-layout GEMM: C[c_out rows][token cols] = A[c_out][k=128] * B[k=128][t].
template <int NI8, int LDB>
__device__ __forceinline__ void gemm_t(const __half* __restrict__ A,
                                       const __half* __restrict__ B,
                                       float (&acc)[2][NI8][4], int rbase, int cbase, int lane) {
    unsigned a_addr = smem_u32(A + (rbase + (lane & 15)) * 136 + ((lane >> 4) << 3));
    unsigned b_addr = smem_u32(B + (lane & 15) * LDB + cbase + ((lane >> 4) << 3));
#pragma unroll
    for (int kc = 0; kc < 128; kc += 16) {
        unsigned a[2][4];
        ldsm4(a[0][0], a[0][1], a[0][2], a[0][3], a_addr);
        ldsm4(a[1][0], a[1][1], a[1][2], a[1][3], a_addr + 16 * 136 * 2);
#pragma unroll
        for (int g = 0; g < NI8 / 2; g++) {
            unsigned b0, b1, b2, b3;
            ldsm4t(b0, b1, b2, b3, b_addr + g * 32);
            unsigned bl[2] = {b0, b1}, bh[2] = {b2, b3};
            mma16816h(acc[0][2 * g],     a[0], bl);
            mma16816h(acc[1][2 * g],     a[1], bl);
            mma16816h(acc[0][2 * g + 1], a[0], bh);
            mma16816h(acc[1][2 * g + 1], a[1], bh);
        }
        a_addr += 32;
        b_addr += 16 * LDB * 2;
    }
}

// ---------------- kernel 0: weight prep ----------------
__global__ void prep_kernel(const float* __restrict__ qkv_w,
                            const float* __restrict__ o1_w,
                            const float* __restrict__ o2_w) {
    int idx = blockIdx.x * blockDim.x + threadIdx.x;
    int nthr = gridDim.x * blockDim.x;
    for (int i = idx; i < BATCH * HEADS * 16 * 16; i += nthr) g_kv[i] = 0.f;
    for (int i = idx; i < 256 * 128; i += nthr) {
        int r = i >> 7, c = i & 127;
        int h = r >> 5, j = r & 31;
        int src = (j < 16) ? (48 * h + 16 + j) : (48 * h + 32 + (j - 16));
        g_wkv[i] = __float2half_rn(qkv_w[src * 128 + c]);
    }
    for (int i = idx; i < 128 * 128; i += nthr) {
        g_o1h[i] = __float2half_rn(o1_w[i]);
        g_o2h[i] = __float2half_rn(o2_w[i]);
    }
}

// ---------------- kernel 1: x->fp16 + k,v projection + register-LN + register-kv MMA ----------------
// 512 threads, 2 tiles of 128 tokens. kv outer product entirely in registers
// (C fragments of the projection GEMM map 1:1 onto A/B fragments of the kv MMA).
#define KVS_WT   0
#define KVS_XT0  (256 * 136 * 2)
#define KVS_XT1  (KVS_XT0 + 128 * 136 * 2)
#define KVS_QB   (KVS_XT1 + 128 * 136 * 2)
#define KVS_SMEM (KVS_QB + 256 * 4)

__global__ void __launch_bounds__(512, 1) kv_kernel(const float* __restrict__ x,
                                                    const float* __restrict__ qkv_b,
                                                    const float* __restrict__ kln_w,
                                                    const float* __restrict__ kln_b,
                                                    const float* __restrict__ vln_w,
                                                    const float* __restrict__ vln_b) {
    extern __shared__ char smem[];
    __half* Wt = (__half*)(smem + KVS_WT);
    __half* xt0 = (__half*)(smem + KVS_XT0);
    __half* xt1 = (__half*)(smem + KVS_XT1);
    float* qb = (float*)(smem + KVS_QB);

    int tid = threadIdx.x;
    int b = blockIdx.y;
    const float* xb = x + (size_t)b * CCH * NTOK;
    __half* x16b = g_x16 + (size_t)b * CCH * NTOK;

    // weights via cp.async (group 0)
    {
        unsigned wt = smem_u32(Wt);
        for (int i = tid; i < 256 * 16; i += 512) {
            int r = i >> 4, c = i & 15;
            cpasync16(wt + r * 272 + c * 16, g_wkv + r * 128 + c * 8);
        }
        CP_COMMIT();
    }
    if (tid < 256) {
        int h = tid >> 5, j = tid & 31;
        int src_r = (j < 16) ? (48 * h + 16 + j) : (48 * h + 32 + (j - 16));
        qb[tid] = qkv_b[src_r];
    }

    int w = tid >> 5, l = tid & 31;
    int lr = l >> 2, lc = l & 3;
    int mw = w >> 1;      // head (c_out group of 32 rows = 16 k dims + 16 v dims)
    int nw = w & 1;       // token half
    int rbase = mw * 32, cbase = nw * 64;

    float lw[2][2], lb[2][2];
    lw[0][0] = kln_w[mw * 16 + lr];     lw[0][1] = kln_w[mw * 16 + lr + 8];
    lb[0][0] = kln_b[mw * 16 + lr];     lb[0][1] = kln_b[mw * 16 + lr + 8];
    lw[1][0] = vln_w[mw * 16 + lr];     lw[1][1] = vln_w[mw * 16 + lr + 8];
    lb[1][0] = vln_b[mw * 16 + lr];     lb[1][1] = vln_b[mw * 16 + lr + 8];

    float acc2[2][4];
#pragma unroll
    for (int e = 0; e < 2; e++)
#pragma unroll
        for (int q = 0; q < 4; q++) acc2[e][q] = 0.f;

#pragma unroll
    for (int tile = 0; tile < 2; tile++) {
        int n0 = blockIdx.x * 256 + tile * 128;
        __half* xt = tile ? xt1 : xt0;

        // load fp32 x tile, convert, store to smem + g_x16
#pragma unroll
        for (int k = 0; k < 8; k++) {
            int i = tid + k * 512;
            int r = i >> 5, c4 = i & 31;
            float4 v = *(const float4*)(xb + (size_t)r * NTOK + n0 + c4 * 4);
            __half2 h0 = __floats2half2_rn(v.x, v.y);
            __half2 h1 = __floats2half2_rn(v.z, v.w);
            uint2 u;
            u.x = *reinterpret_cast<unsigned*>(&h0);
            u.y = *reinterpret_cast<unsigned*>(&h1);
            *(uint2*)(xt + r * 136 + c4 * 4) = u;
            *(uint2*)(x16b + (size_t)r * NTOK + n0 + c4 * 4) = u;
        }
        if (tile == 0) CP_WAIT(0);
        __syncthreads();

        float acc[2][8][4];
#pragma unroll
        for (int a_ = 0; a_ < 2; a_++)
#pragma unroll
            for (int b_ = 0; b_ < 8; b_++)
#pragma unroll
                for (int c_ = 0; c_ < 4; c_++) acc[a_][b_][c_] = 0.f;

        gemm_t<8, 136>(Wt, xt, acc, rbase, cbase, l);

        float q0 = qb[rbase + lr],      q1 = qb[rbase + lr + 8];
        float q2 = qb[rbase + 16 + lr], q3 = qb[rbase + 16 + lr + 8];
#pragma unroll
        for (int ni = 0; ni < 8; ni++) {
            acc[0][ni][0] += q0; acc[0][ni][1] += q0;
            acc[0][ni][2] += q1; acc[0][ni][3] += q1;
            acc[1][ni][0] += q2; acc[1][ni][1] += q2;
            acc[1][ni][2] += q3; acc[1][ni][3] += q3;
        }

        // register LayerNorm over d=16 (ddof=1, eps on std), producing MMA fragments directly
        unsigned kf[8][2], vf[8][2];
#pragma unroll
        for (int mi = 0; mi < 2; mi++) {
#pragma unroll
            for (int ni = 0; ni < 8; ni++) {
                float* c = acc[mi][ni];
                float sa = c[0] + c[2], sb = c[1] + c[3];
                float ssa = c[0] * c[0] + c[2] * c[2];
                float ssb = c[1] * c[1] + c[3] * c[3];
#pragma unroll
                for (int m = 4; m <= 16; m <<= 1) {
                    sa += __shfl_xor_sync(0xffffffffu, sa, m);
                    sb += __shfl_xor_sync(0xffffffffu, sb, m);
                    ssa += __shfl_xor_sync(0xffffffffu, ssa, m);
                    ssb += __shfl_xor_sync(0xffffffffu, ssb, m);
                }
                float ma = sa * (1.f / 16.f);
                float va = fmaxf((ssa - 16.f * ma * ma) * (1.f / 15.f), 0.f);
                float ia = 1.f / (sqrtf(va) + LN_EPS);
                float mb = sb * (1.f / 16.f);
                float vb = fmaxf((ssb - 16.f * mb * mb) * (1.f / 15.f), 0.f);
                float ib = 1.f / (sqrtf(vb) + LN_EPS);
                float n0v = lw[mi][0] * ((c[0] - ma) * ia) + lb[mi][0];
                float n1v = lw[mi][0] * ((c[1] - mb) * ib) + lb[mi][0];
                float n2v = lw[mi][1] * ((c[2] - ma) * ia) + lb[mi][1];
                float n3v = lw[mi][1] * ((c[3] - mb) * ib) + lb[mi][1];
                unsigned lo = pk2h(n0v, n1v);   // rows d/e = lr,   cols = token pair
                unsigned hi = pk2h(n2v, n3v);   // rows d/e = lr+8
                if (mi == 0) { kf[ni][0] = lo; kf[ni][1] = hi; }
                else         { vf[ni][0] = lo; vf[ni][1] = hi; }
            }
        }

        // kv outer product entirely in registers:
        // kv[d][e] += sum_t k[d,t] * v[e,t] ; A = k fragments, B = v fragments.
#pragma unroll
        for (int tc = 0; tc < 4; tc++) {
            unsigned a[4] = {kf[2 * tc][0], kf[2 * tc][1], kf[2 * tc + 1][0], kf[2 * tc + 1][1]};
            unsigned b0[2] = {vf[2 * tc][0], vf[2 * tc + 1][0]};   // e = lr
            unsigned b1[2] = {vf[2 * tc][1], vf[2 * tc + 1][1]};   // e = lr + 8
            mma16816h(acc2[0], a, b0);
            mma16816h(acc2[1], a, b1);
        }
        // no sync needed: xt0/xt1 double-buffered, no other smem hand-off
    }

    float* base = g_kv + (size_t)(b * HEADS + mw) * 256;
#pragma unroll
    for (int eh = 0; eh < 2; eh++) {
        int e0 = eh * 8 + lc * 2;
        atomicAdd(base + lr * 16 + e0,           acc2[eh][0]);
        atomicAdd(base + lr * 16 + e0 + 1,       acc2[eh][1]);
        atomicAdd(base + (lr + 8) * 16 + e0,     acc2[eh][2]);
        atomicAdd(base + (lr + 8) * 16 + e0 + 1, acc2[eh][3]);
    }
}

// ---------------- kernel 2: compose Meff_b = Wq o kv / N ----------------
__global__ void compose_kernel(const float* __restrict__ qkv_w, const float* __restrict__ qkv_b) {
    __shared__ float kvs[256];
    __shared__ float bsum[16];
    int g = blockIdx.x, b = blockIdx.y;
    int ci = threadIdx.x;

    for (int i = ci; i < 256; i += 128)
        kvs[i] = g_kv[(b * HEADS + g) * 256 + i] * (1.f / (float)NTOK);
    if (ci < 16) {
        float s = 0.f;
#pragma unroll
        for (int d = 0; d < 16; d++) s += qkv_b[48 * g + d] * kvs[d * 16 + ci];
        bsum[ci] = s;
    }
    __syncthreads();

    float wq[16];
#pragma unroll
    for (int d = 0; d < 16; d++) wq[d] = qkv_w[(48 * g + d) * 128 + ci];

    __half* mdst = g_meff + ((size_t)b * 128 + g * 16) * 128 + ci;
#pragma unroll
    for (int e = 0; e < 16; e++) {
        float s = 0.f;
#pragma unroll
        for (int d = 0; d < 16; d++) s += wq[d] * kvs[d * 16 + e];
        mdst[e * 128] = __float2half_rn(s);
    }
    if (ci < 16) g_meffb[b * 128 + g * 16 + ci] = bsum[ci];
}

// ---------------- kernel 3: fused av + residual + o1 + gelu + o2 + residual ----------------
#define M4_LDB  264
#define M4_XT   0
#define M4_RT   (128 * M4_LDB * 2)
#define M4_WA   (2 * 128 * M4_LDB * 2)
#define M4_WB   (M4_WA + 128 * 136 * 2)
#define M4_BIAS (M4_WB + 128 * 136 * 2)
#define M4_SMEM (M4_BIAS + 3 * 128 * 4)

__global__ void __launch_bounds__(512, 1) main_kernel(const float* __restrict__ o1_b,
                                                      const float* __restrict__ o2_b,
                                                      float* __restrict__ out) {
    extern __shared__ char smem[];
    __half* xt = (__half*)(smem + M4_XT);
    __half* rt = (__half*)(smem + M4_RT);
    __half* wA = (__half*)(smem + M4_WA);
    __half* wB = (__half*)(smem + M4_WB);
    float* bias = (float*)(smem + M4_BIAS);

    int tid = threadIdx.x;
    int b = blockIdx.y;
    int n0 = blockIdx.x * 256;

    {
        unsigned wa = smem_u32(wA), xa = smem_u32(xt);
        const __half* msrc = g_meff + (size_t)b * 128 * 128;
        const __half* xsrc = g_x16 + (size_t)b * CCH * NTOK + n0;
        for (int i = tid; i < 128 * 16; i += 512) {
            int r = i >> 4, c = i & 15;
            cpasync16(wa + r * 272 + c * 16, msrc + r * 128 + c * 8);
        }
        for (int i = tid; i < 128 * 32; i += 512) {
            int r = i >> 5, c = i & 31;
            cpasync16(xa + r * (M4_LDB * 2) + c * 16, xsrc + (size_t)r * NTOK + c * 8);
        }
        CP_COMMIT();
        unsigned wb = smem_u32(wB);
        for (int i = tid; i < 128 * 16; i += 512) {
            int r = i >> 4, c = i & 15;
            cpasync16(wb + r * 272 + c * 16, g_o1h + r * 128 + c * 8);
        }
        CP_COMMIT();
    }
    if (tid < 128) {
        bias[tid] = g_meffb[b * 128 + tid];
        bias[128 + tid] = o1_b[tid];
        bias[256 + tid] = o2_b[tid];
    }
    CP_WAIT(1);
    __syncthreads();

    int w = tid >> 5, l = tid & 31;
    int lr = l >> 2, lc = l & 3;
    int mw = w >> 2, nw = w & 3;
    int rbase = mw * 32, cbase = nw * 64;

    float acc[2][8][4];
#define ZACC() { _Pragma("unroll") for (int a_=0;a_<2;a_++) _Pragma("unroll") for (int b_=0;b_<8;b_++) _Pragma("unroll") for (int c_=0;c_<4;c_++) acc[a_][b_][c_]=0.f; }

    // ---- phase 1: rt = Meff*x + meffb + x ----
    ZACC();
    gemm_t<8, M4_LDB>(wA, xt, acc, rbase, cbase, l);
    {
        float bm0 = bias[rbase + lr],      bm1 = bias[rbase + lr + 8];
        float bm2 = bias[rbase + 16 + lr], bm3 = bias[rbase + 16 + lr + 8];
#pragma unroll
        for (int mi = 0; mi < 2; mi++) {
            int row = rbase + mi * 16 + lr;
            float ba0 = mi ? bm2 : bm0, ba1 = mi ? bm3 : bm1;
#pragma unroll
            for (int ni = 0; ni < 8; ni++) {
                int col = cbase + ni * 8 + lc * 2;
                __half2 xv0 = *(const __half2*)(xt + row * M4_LDB + col);
                __half2 xv1 = *(const __half2*)(xt + (row + 8) * M4_LDB + col);
                float2 f0 = __half22float2(xv0), f1 = __half22float2(xv1);
                float r00 = acc[mi][ni][0] + ba0 + f0.x;
                float r01 = acc[mi][ni][1] + ba0 + f0.y;
                float r10 = acc[mi][ni][2] + ba1 + f1.x;
                float r11 = acc[mi][ni][3] + ba1 + f1.y;
                *(unsigned*)(rt + row * M4_LDB + col)       = pk2h(r00, r01);
                *(unsigned*)(rt + (row + 8) * M4_LDB + col) = pk2h(r10, r11);
            }
        }
    }
    __syncthreads();

    {
        unsigned wa = smem_u32(wA);
        for (int i = tid; i < 128 * 16; i += 512) {
            int r = i >> 4, c = i & 15;
            cpasync16(wa + r * 272 + c * 16, g_o2h + r * 128 + c * 8);
        }
        CP_COMMIT();
    }

    // ---- phase 2: h1 = gelu(o1 * rt + b1) ----
    ZACC();
    gemm_t<8, M4_LDB>(wB, rt, acc, rbase, cbase, l);
    {
        float b10 = bias[128 + rbase + lr],      b11 = bias[128 + rbase + lr + 8];
        float b12 = bias[128 + rbase + 16 + lr], b13 = bias[128 + rbase + 16 + lr + 8];
#pragma unroll
        for (int mi = 0; mi < 2; mi++) {
            float ba0 = mi ? b12 : b10, ba1 = mi ? b13 : b11;
#pragma unroll
            for (int ni = 0; ni < 8; ni++) {
#pragma unroll
                for (int q = 0; q < 4; q++) {
                    float h = acc[mi][ni][q] + ((q < 2) ? ba0 : ba1);
                    acc[mi][ni][q] = 0.5f * h * (1.f + fast_erf(h * 0.70710678118654752f));
                }
            }
        }
    }
    __syncthreads();
#pragma unroll
    for (int mi = 0; mi < 2; mi++) {
        int row = rbase + mi * 16 + lr;
#pragma unroll
        for (int ni = 0; ni < 8; ni++) {
            int col = cbase + ni * 8 + lc * 2;
            *(unsigned*)(rt + row * M4_LDB + col)       = pk2h(acc[mi][ni][0], acc[mi][ni][1]);
            *(unsigned*)(rt + (row + 8) * M4_LDB + col) = pk2h(acc[mi][ni][2], acc[mi][ni][3]);
        }
    }
    CP_WAIT(0);
    __syncthreads();

    // ---- phase 3: out = o2 * h1 + b2 + x ----
    ZACC();
    gemm_t<8, M4_LDB>(wA, rt, acc, rbase, cbase, l);
    {
        float b20 = bias[256 + rbase + lr],      b21 = bias[256 + rbase + lr + 8];
        float b22 = bias[256 + rbase + 16 + lr], b23 = bias[256 + rbase + 16 + lr + 8];
        float* ob = out + (size_t)b * CCH * NTOK + n0;
#pragma unroll
        for (int mi = 0; mi < 2; mi++) {
            int row = rbase + mi * 16 + lr;
            float ba0 = mi ? b22 : b20, ba1 = mi ? b23 : b21;
#pragma unroll
            for (int ni = 0; ni < 8; ni++) {
                int col = cbase + ni * 8 + lc * 2;
                __half2 xv0 = *(const __half2*)(xt + row * M4_LDB + col);
                __half2 xv1 = *(const __half2*)(xt + (row + 8) * M4_LDB + col);
                float2 f0 = __half22float2(xv0), f1 = __half22float2(xv1);
                float2 o0, o1v;
                o0.x = acc[mi][ni][0] + ba0 + f0.x;
                o0.y = acc[mi][ni][1] + ba0 + f0.y;
                o1v.x = acc[mi][ni][2] + ba1 + f1.x;
                o1v.y = acc[mi][ni][3] + ba1 + f1.y;
                *(float2*)(ob + (size_t)row * NTOK + col) = o0;
                *(float2*)(ob + (size_t)(row + 8) * NTOK + col) = o1v;
            }
        }
    }
}

// ---------------- launch ----------------
extern "C" void kernel_launch(void* const* d_in, const int* in_sizes, int n_in,
                              void* d_out, int out_size) {
    const float* x     = (const float*)d_in[0];
    const float* qkv_w = (const float*)d_in[1];
    const float* qkv_b = (const float*)d_in[2];
    const float* o1_w  = (const float*)d_in[3];
    const float* o1_b  = (const float*)d_in[4];
    const float* o2_w  = (const float*)d_in[5];
    const float* o2_b  = (const float*)d_in[6];
    const float* kln_w = (const float*)d_in[7];
    const float* kln_b = (const float*)d_in[8];
    const float* vln_w = (const float*)d_in[9];
    const float* vln_b = (const float*)d_in[10];
    float* out = (float*)d_out;

    cudaFuncSetAttribute(kv_kernel, cudaFuncAttributeMaxDynamicSharedMemorySize, KVS_SMEM);
    cudaFuncSetAttribute(main_kernel, cudaFuncAttributeMaxDynamicSharedMemorySize, M4_SMEM);

    prep_kernel<<<128, 256>>>(qkv_w, o1_w, o2_w);

    dim3 g2(NTOK / 256, BATCH);
    kv_kernel<<<g2, 512, KVS_SMEM>>>(x, qkv_b, kln_w, kln_b, vln_w, vln_b);

    dim3 gc(HEADS, BATCH);
    compose_kernel<<<gc, 128>>>(qkv_w, qkv_b);

    dim3 g4(NTOK / 256, BATCH);
    main_kernel<<<g4, 512, M4_SMEM>>>(o1_b, o2_b, out);
}

// round 9
// speedup vs baseline: 3.7033x; 1.1915x over previous
#include <cuda_runtime.h>
#include <cuda_fp16.h>

#define BATCH 8
#define CCH   128
#define NTOK  16384
#define HEADS 8
#define LN_EPS 1e-5f

// ---------------- device scratch ----------------
__device__ float  g_kv[BATCH * HEADS * 16 * 16];
__device__ __half g_wkv[256 * 128];
__device__ __half g_o1h[128 * 128];
__device__ __half g_o2h[128 * 128];
__device__ __half g_meff[BATCH * 128 * 128];
__device__ float  g_meffb[BATCH * 128];
__device__ __half g_x16[(size_t)BATCH * CCH * NTOK];

// ---------------- helpers ----------------
__device__ __forceinline__ unsigned pk2h(float a, float b) {
    __half2 h = __floats2half2_rn(a, b);
    return *reinterpret_cast<unsigned*>(&h);
}

__device__ __forceinline__ void mma16816h(float* c, const unsigned* a, const unsigned* b) {
    asm volatile(
        "mma.sync.aligned.m16n8k16.row.col.f32.f16.f16.f32 "
        "{%0,%1,%2,%3}, {%4,%5,%6,%7}, {%8,%9}, {%0,%1,%2,%3};\n"
        : "+f"(c[0]), "+f"(c[1]), "+f"(c[2]), "+f"(c[3])
        : "r"(a[0]), "r"(a[1]), "r"(a[2]), "r"(a[3]), "r"(b[0]), "r"(b[1]));
}

__device__ __forceinline__ unsigned smem_u32(const void* p) {
    return (unsigned)__cvta_generic_to_shared(p);
}

__device__ __forceinline__ void ldsm4(unsigned& r0, unsigned& r1, unsigned& r2, unsigned& r3,
                                      unsigned addr) {
    asm volatile("ldmatrix.sync.aligned.m8n8.x4.shared.b16 {%0,%1,%2,%3}, [%4];\n"
                 : "=r"(r0), "=r"(r1), "=r"(r2), "=r"(r3) : "r"(addr));
}

__device__ __forceinline__ void ldsm4t(unsigned& r0, unsigned& r1, unsigned& r2, unsigned& r3,
                                       unsigned addr) {
    asm volatile("ldmatrix.sync.aligned.m8n8.x4.trans.shared.b16 {%0,%1,%2,%3}, [%4];\n"
                 : "=r"(r0), "=r"(r1), "=r"(r2), "=r"(r3) : "r"(addr));
}

__device__ __forceinline__ void cpasync16(unsigned s, const void* g) {
    asm volatile("cp.async.cg.shared.global [%0], [%1], 16;\n" :: "r"(s), "l"(g));
}
#define CP_COMMIT() asm volatile("cp.async.commit_group;\n")
#define CP_WAIT(n)  asm volatile("cp.async.wait_group %0;\n" :: "n"(n))

__device__ __forceinline__ float rsqrt_fast(float x) {
    float r;
    asm("rsqrt.approx.f32 %0, %1;\n" : "=f"(r) : "f"(x));
    return r;
}

// fast erf: Abramowitz-Stegun 7.1.26, max abs err ~1.5e-7 (approx div adds ~2e-7)
__device__ __forceinline__ float fast_erf(float x) {
    float ax = fabsf(x);
    float t = __fdividef(1.f, fmaf(0.3275911f, ax, 1.f));
    float p = fmaf(1.061405429f, t, -1.453152027f);
    p = fmaf(p, t, 1.421413741f);
    p = fmaf(p, t, -0.284496736f);
    p = fmaf(p, t, 0.254829592f);
    p *= t;
    float r = 1.f - p * __expf(-ax * ax);
    return copysignf(r, x);
}

// Output-layout GEMM: C[c_out rows][token cols] = A[c_out][k=128] * B[k=128][t].
template <int NI8, int LDB>
__device__ __forceinline__ void gemm_t(const __half* __restrict__ A,
                                       const __half* __restrict__ B,
                                       float (&acc)[2][NI8][4], int rbase, int cbase, int lane) {
    unsigned a_addr = smem_u32(A + (rbase + (lane & 15)) * 136 + ((lane >> 4) << 3));
    unsigned b_addr = smem_u32(B + (lane & 15) * LDB + cbase + ((lane >> 4) << 3));
#pragma unroll
    for (int kc = 0; kc < 128; kc += 16) {
        unsigned a[2][4];
        ldsm4(a[0][0], a[0][1], a[0][2], a[0][3], a_addr);
        ldsm4(a[1][0], a[1][1], a[1][2], a[1][3], a_addr + 16 * 136 * 2);
#pragma unroll
        for (int g = 0; g < NI8 / 2; g++) {
            unsigned b0, b1, b2, b3;
            ldsm4t(b0, b1, b2, b3, b_addr + g * 32);
            unsigned bl[2] = {b0, b1}, bh[2] = {b2, b3};
            mma16816h(acc[0][2 * g],     a[0], bl);
            mma16816h(acc[1][2 * g],     a[1], bl);
            mma16816h(acc[0][2 * g + 1], a[0], bh);
            mma16816h(acc[1][2 * g + 1], a[1], bh);
        }
        a_addr += 32;
        b_addr += 16 * LDB * 2;
    }
}

// ---------------- kernel 0: weight prep ----------------
__global__ void prep_kernel(const float* __restrict__ qkv_w,
                            const float* __restrict__ o1_w,
                            const float* __restrict__ o2_w) {
    int idx = blockIdx.x * blockDim.x + threadIdx.x;
    int nthr = gridDim.x * blockDim.x;
    for (int i = idx; i < BATCH * HEADS * 16 * 16; i += nthr) g_kv[i] = 0.f;
    for (int i = idx; i < 256 * 128; i += nthr) {
        int r = i >> 7, c = i & 127;
        int h = r >> 5, j = r & 31;
        int src = (j < 16) ? (48 * h + 16 + j) : (48 * h + 32 + (j - 16));
        g_wkv[i] = __float2half_rn(qkv_w[src * 128 + c]);
    }
    for (int i = idx; i < 128 * 128; i += nthr) {
        g_o1h[i] = __float2half_rn(o1_w[i]);
        g_o2h[i] = __float2half_rn(o2_w[i]);
    }
}

// ---------------- kernel 1: x->fp16 + k,v projection + register-LN + register-kv MMA ----------------
#define KVS_WT   0
#define KVS_XT0  (256 * 136 * 2)
#define KVS_XT1  (KVS_XT0 + 128 * 136 * 2)
#define KVS_QB   (KVS_XT1 + 128 * 136 * 2)
#define KVS_SMEM (KVS_QB + 256 * 4)

__global__ void __launch_bounds__(512, 1) kv_kernel(const float* __restrict__ x,
                                                    const float* __restrict__ qkv_b,
                                                    const float* __restrict__ kln_w,
                                                    const float* __restrict__ kln_b,
                                                    const float* __restrict__ vln_w,
                                                    const float* __restrict__ vln_b) {
    extern __shared__ char smem[];
    __half* Wt = (__half*)(smem + KVS_WT);
    __half* xt0 = (__half*)(smem + KVS_XT0);
    __half* xt1 = (__half*)(smem + KVS_XT1);
    float* qb = (float*)(smem + KVS_QB);

    int tid = threadIdx.x;
    int b = blockIdx.y;
    const float* xb = x + (size_t)b * CCH * NTOK;
    __half* x16b = g_x16 + (size_t)b * CCH * NTOK;

    // weights via cp.async (group 0)
    {
        unsigned wt = smem_u32(Wt);
        for (int i = tid; i < 256 * 16; i += 512) {
            int r = i >> 4, c = i & 15;
            cpasync16(wt + r * 272 + c * 16, g_wkv + r * 128 + c * 8);
        }
        CP_COMMIT();
    }
    if (tid < 256) {
        int h = tid >> 5, j = tid & 31;
        int src_r = (j < 16) ? (48 * h + 16 + j) : (48 * h + 32 + (j - 16));
        qb[tid] = qkv_b[src_r];
    }

    int w = tid >> 5, l = tid & 31;
    int lr = l >> 2, lc = l & 3;
    int mw = w >> 1;      // head
    int nw = w & 1;       // token half
    int rbase = mw * 32, cbase = nw * 64;

    float lw[2][2], lb[2][2];
    lw[0][0] = kln_w[mw * 16 + lr];     lw[0][1] = kln_w[mw * 16 + lr + 8];
    lb[0][0] = kln_b[mw * 16 + lr];     lb[0][1] = kln_b[mw * 16 + lr + 8];
    lw[1][0] = vln_w[mw * 16 + lr];     lw[1][1] = vln_w[mw * 16 + lr + 8];
    lb[1][0] = vln_b[mw * 16 + lr];     lb[1][1] = vln_b[mw * 16 + lr + 8];

    float acc2[2][4];
#pragma unroll
    for (int e = 0; e < 2; e++)
#pragma unroll
        for (int q = 0; q < 4; q++) acc2[e][q] = 0.f;

#pragma unroll
    for (int tile = 0; tile < 2; tile++) {
        int n0 = blockIdx.x * 256 + tile * 128;
        __half* xt = tile ? xt1 : xt0;

        // load fp32 x tile, convert, store to smem + g_x16
#pragma unroll
        for (int k = 0; k < 8; k++) {
            int i = tid + k * 512;
            int r = i >> 5, c4 = i & 31;
            float4 v = *(const float4*)(xb + (size_t)r * NTOK + n0 + c4 * 4);
            __half2 h0 = __floats2half2_rn(v.x, v.y);
            __half2 h1 = __floats2half2_rn(v.z, v.w);
            uint2 u;
            u.x = *reinterpret_cast<unsigned*>(&h0);
            u.y = *reinterpret_cast<unsigned*>(&h1);
            *(uint2*)(xt + r * 136 + c4 * 4) = u;
            *(uint2*)(x16b + (size_t)r * NTOK + n0 + c4 * 4) = u;
        }
        if (tile == 0) CP_WAIT(0);
        __syncthreads();

        float acc[2][8][4];
#pragma unroll
        for (int a_ = 0; a_ < 2; a_++)
#pragma unroll
            for (int b_ = 0; b_ < 8; b_++)
#pragma unroll
                for (int c_ = 0; c_ < 4; c_++) acc[a_][b_][c_] = 0.f;

        gemm_t<8, 136>(Wt, xt, acc, rbase, cbase, l);

        float q0 = qb[rbase + lr],      q1 = qb[rbase + lr + 8];
        float q2 = qb[rbase + 16 + lr], q3 = qb[rbase + 16 + lr + 8];
#pragma unroll
        for (int ni = 0; ni < 8; ni++) {
            acc[0][ni][0] += q0; acc[0][ni][1] += q0;
            acc[0][ni][2] += q1; acc[0][ni][3] += q1;
            acc[1][ni][0] += q2; acc[1][ni][1] += q2;
            acc[1][ni][2] += q3; acc[1][ni][3] += q3;
        }

        // register LayerNorm over d=16 (ddof=1, eps on std), half2-packed butterflies
        unsigned kf[8][2], vf[8][2];
#pragma unroll
        for (int mi = 0; mi < 2; mi++) {
#pragma unroll
            for (int ni = 0; ni < 8; ni++) {
                float* c = acc[mi][ni];
                // packed partial sums: x-lane = token col, y-lane = token col+1
                __half2 s2 = __floats2half2_rn(c[0] + c[2], c[1] + c[3]);
                __half2 q2h = __floats2half2_rn(fmaf(c[0], c[0], c[2] * c[2]),
                                                fmaf(c[1], c[1], c[3] * c[3]));
                unsigned su = *reinterpret_cast<unsigned*>(&s2);
                unsigned qu = *reinterpret_cast<unsigned*>(&q2h);
#pragma unroll
                for (int m = 4; m <= 16; m <<= 1) {
                    unsigned so = __shfl_xor_sync(0xffffffffu, su, m);
                    unsigned qo = __shfl_xor_sync(0xffffffffu, qu, m);
                    __half2 rs2 = __hadd2(*reinterpret_cast<__half2*>(&su),
                                          *reinterpret_cast<__half2*>(&so));
                    __half2 rq2 = __hadd2(*reinterpret_cast<__half2*>(&qu),
                                          *reinterpret_cast<__half2*>(&qo));
                    su = *reinterpret_cast<unsigned*>(&rs2);
                    qu = *reinterpret_cast<unsigned*>(&rq2);
                }
                float2 s = __half22float2(*reinterpret_cast<__half2*>(&su));
                float2 q = __half22float2(*reinterpret_cast<__half2*>(&qu));
                float ma = s.x * (1.f / 16.f);
                float va = fmaxf((q.x - 16.f * ma * ma) * (1.f / 15.f), 1e-12f);
                float rsa = rsqrt_fast(va);
                float ia = fmaf(-LN_EPS * rsa, rsa, rsa);   // 1/(sqrt(va)+eps), 1st order
                float mb = s.y * (1.f / 16.f);
                float vb = fmaxf((q.y - 16.f * mb * mb) * (1.f / 15.f), 1e-12f);
                float rsb = rsqrt_fast(vb);
                float ib = fmaf(-LN_EPS * rsb, rsb, rsb);
                float n0v = lw[mi][0] * ((c[0] - ma) * ia) + lb[mi][0];
                float n1v = lw[mi][0] * ((c[1] - mb) * ib) + lb[mi][0];
                float n2v = lw[mi][1] * ((c[2] - ma) * ia) + lb[mi][1];
                float n3v = lw[mi][1] * ((c[3] - mb) * ib) + lb[mi][1];
                unsigned lo = pk2h(n0v, n1v);
                unsigned hi = pk2h(n2v, n3v);
                if (mi == 0) { kf[ni][0] = lo; kf[ni][1] = hi; }
                else         { vf[ni][0] = lo; vf[ni][1] = hi; }
            }
        }

        // kv outer product entirely in registers
#pragma unroll
        for (int tc = 0; tc < 4; tc++) {
            unsigned a[4] = {kf[2 * tc][0], kf[2 * tc][1], kf[2 * tc + 1][0], kf[2 * tc + 1][1]};
            unsigned b0[2] = {vf[2 * tc][0], vf[2 * tc + 1][0]};
            unsigned b1[2] = {vf[2 * tc][1], vf[2 * tc + 1][1]};
            mma16816h(acc2[0], a, b0);
            mma16816h(acc2[1], a, b1);
        }
    }

    float* base = g_kv + (size_t)(b * HEADS + mw) * 256;
#pragma unroll
    for (int eh = 0; eh < 2; eh++) {
        int e0 = eh * 8 + lc * 2;
        atomicAdd(base + lr * 16 + e0,           acc2[eh][0]);
        atomicAdd(base + lr * 16 + e0 + 1,       acc2[eh][1]);
        atomicAdd(base + (lr + 8) * 16 + e0,     acc2[eh][2]);
        atomicAdd(base + (lr + 8) * 16 + e0 + 1, acc2[eh][3]);
    }
}

// ---------------- kernel 2: compose Meff_b = Wq o kv / N ----------------
__global__ void compose_kernel(const float* __restrict__ qkv_w, const float* __restrict__ qkv_b) {
    __shared__ float kvs[256];
    __shared__ float bsum[16];
    int g = blockIdx.x, b = blockIdx.y;
    int ci = threadIdx.x;

    for (int i = ci; i < 256; i += 128)
        kvs[i] = g_kv[(b * HEADS + g) * 256 + i] * (1.f / (float)NTOK);
    if (ci < 16) {
        float s = 0.f;
#pragma unroll
        for (int d = 0; d < 16; d++) s += qkv_b[48 * g + d] * kvs[d * 16 + ci];
        bsum[ci] = s;
    }
    __syncthreads();

    float wq[16];
#pragma unroll
    for (int d = 0; d < 16; d++) wq[d] = qkv_w[(48 * g + d) * 128 + ci];

    __half* mdst = g_meff + ((size_t)b * 128 + g * 16) * 128 + ci;
#pragma unroll
    for (int e = 0; e < 16; e++) {
        float s = 0.f;
#pragma unroll
        for (int d = 0; d < 16; d++) s += wq[d] * kvs[d * 16 + e];
        mdst[e * 128] = __float2half_rn(s);
    }
    if (ci < 16) g_meffb[b * 128 + g * 16 + ci] = bsum[ci];
}

// ---------------- kernel 3: fused av + residual + o1 + gelu + o2 + residual ----------------
#define M4_LDB  264
#define M4_XT   0
#define M4_RT   (128 * M4_LDB * 2)
#define M4_WA   (2 * 128 * M4_LDB * 2)
#define M4_WB   (M4_WA + 128 * 136 * 2)
#define M4_BIAS (M4_WB + 128 * 136 * 2)
#define M4_SMEM (M4_BIAS + 3 * 128 * 4)

__global__ void __launch_bounds__(512, 1) main_kernel(const float* __restrict__ o1_b,
                                                      const float* __restrict__ o2_b,
                                                      float* __restrict__ out) {
    extern __shared__ char smem[];
    __half* xt = (__half*)(smem + M4_XT);
    __half* rt = (__half*)(smem + M4_RT);
    __half* wA = (__half*)(smem + M4_WA);
    __half* wB = (__half*)(smem + M4_WB);
    float* bias = (float*)(smem + M4_BIAS);

    int tid = threadIdx.x;
    int b = blockIdx.y;
    int n0 = blockIdx.x * 256;

    {
        unsigned wa = smem_u32(wA), xa = smem_u32(xt);
        const __half* msrc = g_meff + (size_t)b * 128 * 128;
        const __half* xsrc = g_x16 + (size_t)b * CCH * NTOK + n0;
        for (int i = tid; i < 128 * 16; i += 512) {
            int r = i >> 4, c = i & 15;
            cpasync16(wa + r * 272 + c * 16, msrc + r * 128 + c * 8);
        }
        for (int i = tid; i < 128 * 32; i += 512) {
            int r = i >> 5, c = i & 31;
            cpasync16(xa + r * (M4_LDB * 2) + c * 16, xsrc + (size_t)r * NTOK + c * 8);
        }
        CP_COMMIT();
        unsigned wb = smem_u32(wB);
        for (int i = tid; i < 128 * 16; i += 512) {
            int r = i >> 4, c = i & 15;
            cpasync16(wb + r * 272 + c * 16, g_o1h + r * 128 + c * 8);
        }
        CP_COMMIT();
    }
    if (tid < 128) {
        bias[tid] = g_meffb[b * 128 + tid];
        bias[128 + tid] = o1_b[tid];
        bias[256 + tid] = o2_b[tid];
    }
    CP_WAIT(1);
    __syncthreads();

    int w = tid >> 5, l = tid & 31;
    int lr = l >> 2, lc = l & 3;
    int mw = w >> 2, nw = w & 3;
    int rbase = mw * 32, cbase = nw * 64;

    float acc[2][8][4];
#define ZACC() { _Pragma("unroll") for (int a_=0;a_<2;a_++) _Pragma("unroll") for (int b_=0;b_<8;b_++) _Pragma("unroll") for (int c_=0;c_<4;c_++) acc[a_][b_][c_]=0.f; }

    // ---- phase 1: rt = Meff*x + meffb + x ----
    ZACC();
    gemm_t<8, M4_LDB>(wA, xt, acc, rbase, cbase, l);
    {
        float bm0 = bias[rbase + lr],      bm1 = bias[rbase + lr + 8];
        float bm2 = bias[rbase + 16 + lr], bm3 = bias[rbase + 16 + lr + 8];
#pragma unroll
        for (int mi = 0; mi < 2; mi++) {
            int row = rbase + mi * 16 + lr;
            float ba0 = mi ? bm2 : bm0, ba1 = mi ? bm3 : bm1;
#pragma unroll
            for (int ni = 0; ni < 8; ni++) {
                int col = cbase + ni * 8 + lc * 2;
                __half2 xv0 = *(const __half2*)(xt + row * M4_LDB + col);
                __half2 xv1 = *(const __half2*)(xt + (row + 8) * M4_LDB + col);
                float2 f0 = __half22float2(xv0), f1 = __half22float2(xv1);
                float r00 = acc[mi][ni][0] + ba0 + f0.x;
                float r01 = acc[mi][ni][1] + ba0 + f0.y;
                float r10 = acc[mi][ni][2] + ba1 + f1.x;
                float r11 = acc[mi][ni][3] + ba1 + f1.y;
                *(unsigned*)(rt + row * M4_LDB + col)       = pk2h(r00, r01);
                *(unsigned*)(rt + (row + 8) * M4_LDB + col) = pk2h(r10, r11);
            }
        }
    }
    __syncthreads();

    {
        unsigned wa = smem_u32(wA);
        for (int i = tid; i < 128 * 16; i += 512) {
            int r = i >> 4, c = i & 15;
            cpasync16(wa + r * 272 + c * 16, g_o2h + r * 128 + c * 8);
        }
        CP_COMMIT();
    }

    // ---- phase 2: h1 = gelu(o1 * rt + b1) ----
    ZACC();
    gemm_t<8, M4_LDB>(wB, rt, acc, rbase, cbase, l);
    {
        float b10 = bias[128 + rbase + lr],      b11 = bias[128 + rbase + lr + 8];
        float b12 = bias[128 + rbase + 16 + lr], b13 = bias[128 + rbase + 16 + lr + 8];
#pragma unroll
        for (int mi = 0; mi < 2; mi++) {
            float ba0 = mi ? b12 : b10, ba1 = mi ? b13 : b11;
#pragma unroll
            for (int ni = 0; ni < 8; ni++) {
#pragma unroll
                for (int q = 0; q < 4; q++) {
                    float h = acc[mi][ni][q] + ((q < 2) ? ba0 : ba1);
                    acc[mi][ni][q] = 0.5f * h * (1.f + fast_erf(h * 0.70710678118654752f));
                }
            }
        }
    }
    __syncthreads();
#pragma unroll
    for (int mi = 0; mi < 2; mi++) {
        int row = rbase + mi * 16 + lr;
#pragma unroll
        for (int ni = 0; ni < 8; ni++) {
            int col = cbase + ni * 8 + lc * 2;
            *(unsigned*)(rt + row * M4_LDB + col)       = pk2h(acc[mi][ni][0], acc[mi][ni][1]);
            *(unsigned*)(rt + (row + 8) * M4_LDB + col) = pk2h(acc[mi][ni][2], acc[mi][ni][3]);
        }
    }
    CP_WAIT(0);
    __syncthreads();

    // ---- phase 3: out = o2 * h1 + b2 + x ----
    ZACC();
    gemm_t<8, M4_LDB>(wA, rt, acc, rbase, cbase, l);
    {
        float b20 = bias[256 + rbase + lr],      b21 = bias[256 + rbase + lr + 8];
        float b22 = bias[256 + rbase + 16 + lr], b23 = bias[256 + rbase + 16 + lr + 8];
        float* ob = out + (size_t)b * CCH * NTOK + n0;
#pragma unroll
        for (int mi = 0; mi < 2; mi++) {
            int row = rbase + mi * 16 + lr;
            float ba0 = mi ? b22 : b20, ba1 = mi ? b23 : b21;
#pragma unroll
            for (int ni = 0; ni < 8; ni++) {
                int col = cbase + ni * 8 + lc * 2;
                __half2 xv0 = *(const __half2*)(xt + row * M4_LDB + col);
                __half2 xv1 = *(const __half2*)(xt + (row + 8) * M4_LDB + col);
                float2 f0 = __half22float2(xv0), f1 = __half22float2(xv1);
                float2 o0, o1v;
                o0.x = acc[mi][ni][0] + ba0 + f0.x;
                o0.y = acc[mi][ni][1] + ba0 + f0.y;
                o1v.x = acc[mi][ni][2] + ba1 + f1.x;
                o1v.y = acc[mi][ni][3] + ba1 + f1.y;
                *(float2*)(ob + (size_t)row * NTOK + col) = o0;
                *(float2*)(ob + (size_t)(row + 8) * NTOK + col) = o1v;
            }
        }
    }
}

// ---------------- launch ----------------
extern "C" void kernel_launch(void* const* d_in, const int* in_sizes, int n_in,
                              void* d_out, int out_size) {
    const float* x     = (const float*)d_in[0];
    const float* qkv_w = (const float*)d_in[1];
    const float* qkv_b = (const float*)d_in[2];
    const float* o1_w  = (const float*)d_in[3];
    const float* o1_b  = (const float*)d_in[4];
    const float* o2_w  = (const float*)d_in[5];
    const float* o2_b  = (const float*)d_in[6];
    const float* kln_w = (const float*)d_in[7];
    const float* kln_b = (const float*)d_in[8];
    const float* vln_w = (const float*)d_in[9];
    const float* vln_b = (const float*)d_in[10];
    float* out = (float*)d_out;

    cudaFuncSetAttribute(kv_kernel, cudaFuncAttributeMaxDynamicSharedMemorySize, KVS_SMEM);
    cudaFuncSetAttribute(main_kernel, cudaFuncAttributeMaxDynamicSharedMemorySize, M4_SMEM);

    prep_kernel<<<128, 256>>>(qkv_w, o1_w, o2_w);

    dim3 g2(NTOK / 256, BATCH);
    kv_kernel<<<g2, 512, KVS_SMEM>>>(x, qkv_b, kln_w, kln_b, vln_w, vln_b);

    dim3 gc(HEADS, BATCH);
    compose_kernel<<<gc, 128>>>(qkv_w, qkv_b);

    dim3 g4(NTOK / 256, BATCH);
    main_kernel<<<g4, 512, M4_SMEM>>>(o1_b, o2_b, out);
}